// round 4
// baseline (speedup 1.0000x reference)
#include <cuda_runtime.h>
#include <cuda_bf16.h>
#include <cuda_fp16.h>
#include <math.h>
#include <float.h>
#include <stdint.h>

#define SEQ    2048
#define HID    2048
#define DHEAD  64
#define NQH    32
#define NKVH   4
#define QKV_COLS 2560   // (32 + 4 + 4) * 64

// ---------------- scratch (no cudaMalloc allowed) ----------------
__device__ float g_qkv [SEQ * QKV_COLS];

__device__ __nv_bfloat16 g_hid_hi[SEQ * HID];
__device__ __nv_bfloat16 g_hid_lo[SEQ * HID];
__device__ __nv_bfloat16 g_wq_hi [QKV_COLS * HID];
__device__ __nv_bfloat16 g_wq_lo [QKV_COLS * HID];
__device__ __nv_bfloat16 g_wo_hi [HID * HID];
__device__ __nv_bfloat16 g_wo_lo [HID * HID];
__device__ __nv_bfloat16 g_at_hi [SEQ * HID];
__device__ __nv_bfloat16 g_at_lo [SEQ * HID];

__device__ __half g_q_hi[NQH  * SEQ * DHEAD];
__device__ __half g_q_lo[NQH  * SEQ * DHEAD];
__device__ __half g_k_hi[NKVH * SEQ * DHEAD];
__device__ __half g_k_lo[NKVH * SEQ * DHEAD];
__device__ __half g_v_hi[NKVH * SEQ * DHEAD];
__device__ __half g_v_lo[NKVH * SEQ * DHEAD];

// ---------------------------------------------------------------------------
// helpers
// ---------------------------------------------------------------------------
__device__ __forceinline__ void cp16(uint32_t s, const void* g) {
    asm volatile("cp.async.cg.shared.global [%0], [%1], 16;\n" :: "r"(s), "l"(g));
}
__device__ __forceinline__ void cp_commit() {
    asm volatile("cp.async.commit_group;\n");
}
template<int N>
__device__ __forceinline__ void cp_wait() {
    asm volatile("cp.async.wait_group %0;\n" :: "n"(N));
}
__device__ __forceinline__ void mma_bf16(float* d, const uint32_t* a,
                                         uint32_t b0, uint32_t b1) {
    asm volatile(
        "mma.sync.aligned.m16n8k16.row.col.f32.bf16.bf16.f32 "
        "{%0,%1,%2,%3}, {%4,%5,%6,%7}, {%8,%9}, {%0,%1,%2,%3};\n"
        : "+f"(d[0]), "+f"(d[1]), "+f"(d[2]), "+f"(d[3])
        : "r"(a[0]), "r"(a[1]), "r"(a[2]), "r"(a[3]), "r"(b0), "r"(b1));
}
__device__ __forceinline__ void mma_f16(float* d, const uint32_t* a,
                                        const uint32_t* b) {
    asm volatile(
        "mma.sync.aligned.m16n8k16.row.col.f32.f16.f16.f32 "
        "{%0,%1,%2,%3}, {%4,%5,%6,%7}, {%8,%9}, {%0,%1,%2,%3};\n"
        : "+f"(d[0]), "+f"(d[1]), "+f"(d[2]), "+f"(d[3])
        : "r"(a[0]), "r"(a[1]), "r"(a[2]), "r"(a[3]), "r"(b[0]), "r"(b[1]));
}
__device__ __forceinline__ void ldsm_x4(uint32_t* r, uint32_t addr) {
    asm volatile("ldmatrix.sync.aligned.m8n8.x4.shared.b16 {%0,%1,%2,%3}, [%4];\n"
        : "=r"(r[0]), "=r"(r[1]), "=r"(r[2]), "=r"(r[3]) : "r"(addr));
}
__device__ __forceinline__ void ldsm_x4_t(uint32_t* r, uint32_t addr) {
    asm volatile("ldmatrix.sync.aligned.m8n8.x4.trans.shared.b16 {%0,%1,%2,%3}, [%4];\n"
        : "=r"(r[0]), "=r"(r[1]), "=r"(r[2]), "=r"(r[3]) : "r"(addr));
}
__device__ __forceinline__ uint32_t smem_u32_of(const void* p) {
    uint32_t a;
    asm("{ .reg .u64 t; cvta.to.shared.u64 t, %1; cvt.u32.u64 %0, t; }"
        : "=r"(a) : "l"(p));
    return a;
}

// ---------------------------------------------------------------------------
// fp32 -> (bf16 hi, bf16 lo) split
// ---------------------------------------------------------------------------
__global__ void split_bf16(const float* __restrict__ in,
                           __nv_bfloat16* __restrict__ hi,
                           __nv_bfloat16* __restrict__ lo, int n) {
    int i = blockIdx.x * blockDim.x + threadIdx.x;
    if (i >= n) return;
    float x = in[i];
    __nv_bfloat16 h = __float2bfloat16(x);
    float r = x - __bfloat162float(h);
    hi[i] = h;
    lo[i] = __float2bfloat16(r);
}

// ---------------------------------------------------------------------------
// bf16x3 tensor-core GEMM v3: 512 threads (16 warps, 4x4), warp tile 32x32,
// ldmatrix fragment loads, 3-stage cp.async pipeline.
// C[M,N] = A[M,K] @ B[N,K]^T, fp32 accumulate
// ---------------------------------------------------------------------------
#define BM 128
#define BN 128
#define BK 32
#define SROW 40                       // halfs per smem row (80 B)
#define BUF_ELEMS (128 * SROW)
#define BUFB (BUF_ELEMS * 2)          // bytes per buffer
#define STAGE_ELEMS (4 * BUF_ELEMS)
#define GEMM_SMEM (3 * STAGE_ELEMS * 2)   // 122880 bytes

__global__ void __launch_bounds__(512, 1)
gemm_bf16x3(const __nv_bfloat16* __restrict__ Ahi,
            const __nv_bfloat16* __restrict__ Alo,
            const __nv_bfloat16* __restrict__ Bhi,
            const __nv_bfloat16* __restrict__ Blo,
            float* __restrict__ C, int M, int N, int K) {
    extern __shared__ __nv_bfloat16 smem[];
    const int tid  = threadIdx.x;
    const int warp = tid >> 5;
    const int lane = tid & 31;
    const int wm   = warp >> 2;        // 0..3
    const int wn   = warp & 3;         // 0..3
    const int row0 = blockIdx.y * BM;
    const int col0 = blockIdx.x * BN;

    uint32_t smem_b = smem_u32_of(smem);

    float acc[2][4][4];
#pragma unroll
    for (int i = 0; i < 2; i++)
#pragma unroll
        for (int j = 0; j < 4; j++)
#pragma unroll
            for (int k = 0; k < 4; k++) acc[i][j][k] = 0.f;

    const int NIT = K / BK;

    // one 16B chunk per thread per buffer per stage
    const int lrow = tid >> 2;         // 0..127
    const int lcc  = tid & 3;          // 0..3
    auto load_stage = [&](int stage, int k0) {
        uint32_t so = smem_b + stage * (STAGE_ELEMS * 2)
                    + lrow * (SROW * 2) + lcc * 16;
        size_t ga = (size_t)(row0 + lrow) * K + k0 + lcc * 8;
        size_t gb = (size_t)(col0 + lrow) * K + k0 + lcc * 8;
        cp16(so,            Ahi + ga);
        cp16(so + 1 * BUFB, Alo + ga);
        cp16(so + 2 * BUFB, Bhi + gb);
        cp16(so + 3 * BUFB, Blo + gb);
    };

    load_stage(0, 0);
    cp_commit();
    load_stage(1, BK);
    cp_commit();

    // per-lane ldmatrix addressing: row = base + (lane&15), col half-offset
    const int lr16  = lane & 15;
    const int lhalf = (lane >> 4) << 4;   // 0 or 16 bytes (8 halfs)

    for (int it = 0; it < NIT; it++) {
        if (it + 2 < NIT) { cp_wait<1>(); } else { cp_wait<0>(); }
        __syncthreads();
        if (it + 2 < NIT) {
            load_stage((it + 2) % 3, (it + 2) * BK);
            cp_commit();
        }

        uint32_t sA = smem_b + (it % 3) * (STAGE_ELEMS * 2);
        uint32_t sB = sA + 2 * BUFB;

#pragma unroll
        for (int ks = 0; ks < 2; ks++) {
            uint32_t ah[2][4], al[2][4], bh[2][4], bl[2][4];
#pragma unroll
            for (int mt = 0; mt < 2; mt++) {
                uint32_t addr = sA + (wm * 32 + mt * 16 + lr16) * (SROW * 2)
                              + ks * 32 + lhalf;
                ldsm_x4(ah[mt], addr);
                ldsm_x4(al[mt], addr + BUFB);
            }
#pragma unroll
            for (int np = 0; np < 2; np++) {
                uint32_t addr = sB + (wn * 32 + np * 16 + lr16) * (SROW * 2)
                              + ks * 32 + lhalf;
                ldsm_x4(bh[np], addr);
                ldsm_x4(bl[np], addr + BUFB);
            }
#pragma unroll
            for (int mt = 0; mt < 2; mt++)
#pragma unroll
                for (int np = 0; np < 2; np++) {
                    // nt = 2*np   -> b regs {r0, r2}
                    mma_bf16(acc[mt][2 * np], ah[mt], bh[np][0], bh[np][2]);
                    mma_bf16(acc[mt][2 * np], ah[mt], bl[np][0], bl[np][2]);
                    mma_bf16(acc[mt][2 * np], al[mt], bh[np][0], bh[np][2]);
                    // nt = 2*np+1 -> b regs {r1, r3}
                    mma_bf16(acc[mt][2 * np + 1], ah[mt], bh[np][1], bh[np][3]);
                    mma_bf16(acc[mt][2 * np + 1], ah[mt], bl[np][1], bl[np][3]);
                    mma_bf16(acc[mt][2 * np + 1], al[mt], bh[np][1], bh[np][3]);
                }
        }
        __syncthreads();
    }

#pragma unroll
    for (int mt = 0; mt < 2; mt++) {
        int r = row0 + wm * 32 + mt * 16 + (lane >> 2);
#pragma unroll
        for (int nt = 0; nt < 4; nt++) {
            int c = col0 + wn * 32 + nt * 8 + 2 * (lane & 3);
            float2 v0 = make_float2(acc[mt][nt][0], acc[mt][nt][1]);
            float2 v1 = make_float2(acc[mt][nt][2], acc[mt][nt][3]);
            *(float2*)&C[(size_t)r * N + c]       = v0;
            *(float2*)&C[(size_t)(r + 8) * N + c] = v1;
        }
    }
}

// ---------------------------------------------------------------------------
// RoPE + fp16 hi/lo split: g_qkv -> head-major q/k/v arrays
// ---------------------------------------------------------------------------
__global__ void rope_split() {
    int idx = blockIdx.x * blockDim.x + threadIdx.x;
    const int total = SEQ * 40 * 32;
    if (idx >= total) return;
    int pair = idx & 31;
    int head = (idx >> 5) % 40;
    int s    = idx / (40 * 32);

    const float* base = g_qkv + (size_t)s * QKV_COLS + head * DHEAD;
    float x1 = base[pair];
    float x2 = base[pair + 32];
    float y1, y2;
    if (head < 36) {
        float inv_freq = __expf(-(float)pair * (9.210340371976184f / 32.0f));
        float ang = (float)s * inv_freq;
        float sn, cs;
        sincosf(ang, &sn, &cs);
        y1 = x1 * cs - x2 * sn;
        y2 = x2 * cs + x1 * sn;
    } else {
        y1 = x1; y2 = x2;
    }

    __half *dh, *dl;
    size_t off;
    if (head < 32) {
        y1 *= 0.125f; y2 *= 0.125f;
        off = ((size_t)head * SEQ + s) * DHEAD;
        dh = g_q_hi; dl = g_q_lo;
    } else if (head < 36) {
        off = ((size_t)(head - 32) * SEQ + s) * DHEAD;
        dh = g_k_hi; dl = g_k_lo;
    } else {
        off = ((size_t)(head - 36) * SEQ + s) * DHEAD;
        dh = g_v_hi; dl = g_v_lo;
    }
    __half h1 = __float2half_rn(y1);
    __half h2 = __float2half_rn(y2);
    dh[off + pair]      = h1;
    dh[off + pair + 32] = h2;
    dl[off + pair]      = __float2half_rn(y1 - __half2float(h1));
    dl[off + pair + 32] = __float2half_rn(y2 - __half2float(h2));
}

// ---------------------------------------------------------------------------
// Tensor-core flash attention (fp16x3), causal, GQA. (unchanged from R2)
// ---------------------------------------------------------------------------
#define FSTRIDE 72
#define FTILE (64 * FSTRIDE)
#define FA_SMEM (6 * FTILE * 2)

__global__ void __launch_bounds__(128)
flash_attn_tc() {
    extern __shared__ __half fsm[];
    uint32_t sbase = smem_u32_of(fsm);

    const int head = blockIdx.x;
    const int qb   = gridDim.y - 1 - blockIdx.y;
    const int tid  = threadIdx.x;
    const int w    = tid >> 5;
    const int lane = tid & 31;
    const int kvh  = head >> 3;
    const int r8   = lane & 7;
    const int sub  = lane >> 3;

    {
        const __half* gqh = g_q_hi + ((size_t)head * SEQ + qb * 64) * DHEAD;
        const __half* gql = g_q_lo + ((size_t)head * SEQ + qb * 64) * DHEAD;
#pragma unroll
        for (int i = 0; i < 8; i++) {
            int c   = tid + i * 128;
            int arr = c >> 9;
            int rem = c & 511;
            int row = rem >> 3;
            int ch  = rem & 7;
            uint32_t dst = sbase + arr * (FTILE * 2) + row * 144 + ch * 16;
            const __half* src = (arr ? gql : gqh) + row * DHEAD + ch * 8;
            cp16(dst, src);
        }
        cp_commit(); cp_wait<0>();
        __syncthreads();
    }

    uint32_t qh[4][4], ql[4][4];
#pragma unroll
    for (int kk = 0; kk < 4; kk++) {
        uint32_t addr = sbase
            + (w * 16 + r8 + ((sub & 1) << 3)) * 144
            + kk * 32 + ((sub & 2) << 3);
        ldsm_x4(qh[kk], addr);
        ldsm_x4(ql[kk], addr + FTILE * 2);
    }

    float of[8][4];
#pragma unroll
    for (int f = 0; f < 8; f++)
#pragma unroll
        for (int j = 0; j < 4; j++) of[f][j] = 0.f;
    float m0 = -1e30f, m1 = -1e30f, l0 = 0.f, l1 = 0.f;

    const uint32_t sK = sbase + 2 * (FTILE * 2);
    const uint32_t sV = sbase + 4 * (FTILE * 2);

    for (int kb = 0; kb <= qb; kb++) {
        __syncthreads();
        {
            const size_t go = ((size_t)kvh * SEQ + kb * 64) * DHEAD;
#pragma unroll
            for (int i = 0; i < 16; i++) {
                int c   = tid + i * 128;
                int arr = c >> 9;
                int rem = c & 511;
                int row = rem >> 3;
                int ch  = rem & 7;
                uint32_t dst = sbase + (2 + arr) * (FTILE * 2) + row * 144 + ch * 16;
                const __half* src;
                if      (arr == 0) src = g_k_hi + go;
                else if (arr == 1) src = g_k_lo + go;
                else if (arr == 2) src = g_v_hi + go;
                else               src = g_v_lo + go;
                src += row * DHEAD + ch * 8;
                cp16(dst, src);
            }
            cp_commit(); cp_wait<0>();
            __syncthreads();
        }

        float sf[8][4];
#pragma unroll
        for (int f = 0; f < 8; f++)
#pragma unroll
            for (int j = 0; j < 4; j++) sf[f][j] = 0.f;

#pragma unroll
        for (int p = 0; p < 4; p++) {
            uint32_t bh[4][4], bl[4][4];
#pragma unroll
            for (int kk = 0; kk < 4; kk++) {
                uint32_t addr = sK
                    + (p * 16 + ((sub & 2) << 2) + r8) * 144
                    + kk * 32 + ((sub & 1) << 4);
                ldsm_x4(bh[kk], addr);
                ldsm_x4(bl[kk], addr + FTILE * 2);
            }
#pragma unroll
            for (int kk = 0; kk < 4; kk++) {
                mma_f16(sf[2 * p],     qh[kk], &bh[kk][0]);
                mma_f16(sf[2 * p],     qh[kk], &bl[kk][0]);
                mma_f16(sf[2 * p],     ql[kk], &bh[kk][0]);
                mma_f16(sf[2 * p + 1], qh[kk], &bh[kk][2]);
                mma_f16(sf[2 * p + 1], qh[kk], &bl[kk][2]);
                mma_f16(sf[2 * p + 1], ql[kk], &bh[kk][2]);
            }
        }

        if (kb == qb) {
            int rt0 = w * 16 + (lane >> 2);
#pragma unroll
            for (int f = 0; f < 8; f++) {
                int ct = 8 * f + 2 * (lane & 3);
                if (ct > rt0)         sf[f][0] = -1e30f;
                if (ct + 1 > rt0)     sf[f][1] = -1e30f;
                if (ct > rt0 + 8)     sf[f][2] = -1e30f;
                if (ct + 1 > rt0 + 8) sf[f][3] = -1e30f;
            }
        }

        float c0 = -1e30f, c1 = -1e30f;
#pragma unroll
        for (int f = 0; f < 8; f++) {
            c0 = fmaxf(c0, fmaxf(sf[f][0], sf[f][1]));
            c1 = fmaxf(c1, fmaxf(sf[f][2], sf[f][3]));
        }
        c0 = fmaxf(c0, __shfl_xor_sync(0xffffffffu, c0, 1));
        c0 = fmaxf(c0, __shfl_xor_sync(0xffffffffu, c0, 2));
        c1 = fmaxf(c1, __shfl_xor_sync(0xffffffffu, c1, 1));
        c1 = fmaxf(c1, __shfl_xor_sync(0xffffffffu, c1, 2));

        float mn0 = fmaxf(m0, c0), mn1 = fmaxf(m1, c1);
        float a0 = __expf(m0 - mn0), a1 = __expf(m1 - mn1);
        m0 = mn0; m1 = mn1;

        float s0 = 0.f, s1 = 0.f;
#pragma unroll
        for (int f = 0; f < 8; f++) {
            sf[f][0] = __expf(sf[f][0] - mn0);
            sf[f][1] = __expf(sf[f][1] - mn0);
            sf[f][2] = __expf(sf[f][2] - mn1);
            sf[f][3] = __expf(sf[f][3] - mn1);
            s0 += sf[f][0] + sf[f][1];
            s1 += sf[f][2] + sf[f][3];
        }
        s0 += __shfl_xor_sync(0xffffffffu, s0, 1);
        s0 += __shfl_xor_sync(0xffffffffu, s0, 2);
        s1 += __shfl_xor_sync(0xffffffffu, s1, 1);
        s1 += __shfl_xor_sync(0xffffffffu, s1, 2);
        l0 = l0 * a0 + s0;
        l1 = l1 * a1 + s1;

#pragma unroll
        for (int f = 0; f < 8; f++) {
            of[f][0] *= a0; of[f][1] *= a0;
            of[f][2] *= a1; of[f][3] *= a1;
        }

        uint32_t ph[4][4], pl[4][4];
#pragma unroll
        for (int kk = 0; kk < 4; kk++) {
#pragma unroll
            for (int half4 = 0; half4 < 4; half4++) {
                int f = 2 * kk + (half4 >> 1);
                int j = (half4 & 1) * 2;
                float v0 = sf[f][j], v1 = sf[f][j + 1];
                __half h0 = __float2half_rn(v0);
                __half h1 = __float2half_rn(v1);
                __half2 hp = __halves2half2(h0, h1);
                __half2 lp = __halves2half2(
                    __float2half_rn(v0 - __half2float(h0)),
                    __float2half_rn(v1 - __half2float(h1)));
                int slot = (half4 >> 1) * 2 + (half4 & 1);
                ph[kk][slot] = *(uint32_t*)&hp;
                pl[kk][slot] = *(uint32_t*)&lp;
            }
        }

#pragma unroll
        for (int p = 0; p < 4; p++) {
            uint32_t vh[4][4], vl[4][4];
#pragma unroll
            for (int kk = 0; kk < 4; kk++) {
                uint32_t addr = sV
                    + (kk * 16 + ((sub & 1) << 3) + r8) * 144
                    + p * 32 + ((sub & 2) << 3);
                ldsm_x4_t(vh[kk], addr);
                ldsm_x4_t(vl[kk], addr + FTILE * 2);
            }
#pragma unroll
            for (int kk = 0; kk < 4; kk++) {
                mma_f16(of[2 * p],     ph[kk], &vh[kk][0]);
                mma_f16(of[2 * p],     ph[kk], &vl[kk][0]);
                mma_f16(of[2 * p],     pl[kk], &vh[kk][0]);
                mma_f16(of[2 * p + 1], ph[kk], &vh[kk][2]);
                mma_f16(of[2 * p + 1], ph[kk], &vl[kk][2]);
                mma_f16(of[2 * p + 1], pl[kk], &vh[kk][2]);
            }
        }
    }

    float inv0 = 1.0f / l0, inv1 = 1.0f / l1;
    int rq = qb * 64 + w * 16 + (lane >> 2);
    int cb = head * DHEAD + 2 * (lane & 3);
#pragma unroll
    for (int f = 0; f < 8; f++) {
        int col = cb + 8 * f;
        float v00 = of[f][0] * inv0, v01 = of[f][1] * inv0;
        float v10 = of[f][2] * inv1, v11 = of[f][3] * inv1;
        __nv_bfloat16 h00 = __float2bfloat16(v00);
        __nv_bfloat16 h01 = __float2bfloat16(v01);
        __nv_bfloat16 h10 = __float2bfloat16(v10);
        __nv_bfloat16 h11 = __float2bfloat16(v11);
        __nv_bfloat162 hp0 = {h00, h01};
        __nv_bfloat162 hp1 = {h10, h11};
        __nv_bfloat162 lp0 = {__float2bfloat16(v00 - __bfloat162float(h00)),
                              __float2bfloat16(v01 - __bfloat162float(h01))};
        __nv_bfloat162 lp1 = {__float2bfloat16(v10 - __bfloat162float(h10)),
                              __float2bfloat16(v11 - __bfloat162float(h11))};
        *(uint32_t*)&g_at_hi[(size_t)rq * HID + col]       = *(uint32_t*)&hp0;
        *(uint32_t*)&g_at_hi[(size_t)(rq + 8) * HID + col] = *(uint32_t*)&hp1;
        *(uint32_t*)&g_at_lo[(size_t)rq * HID + col]       = *(uint32_t*)&lp0;
        *(uint32_t*)&g_at_lo[(size_t)(rq + 8) * HID + col] = *(uint32_t*)&lp1;
    }
}

// ---------------------------------------------------------------------------
extern "C" void kernel_launch(void* const* d_in, const int* in_sizes, int n_in,
                              void* d_out, int out_size) {
    const float* hidden = (const float*)d_in[0];
    const float* w_qkv  = (const float*)d_in[1];
    const float* w_o    = (const float*)d_in[2];
    float*       out    = (float*)d_out;

    float* qkv_ptr = nullptr;
    cudaGetSymbolAddress((void**)&qkv_ptr, g_qkv);
    __nv_bfloat16 *hid_hi, *hid_lo, *wq_hi, *wq_lo, *wo_hi, *wo_lo, *at_hi, *at_lo;
    cudaGetSymbolAddress((void**)&hid_hi, g_hid_hi);
    cudaGetSymbolAddress((void**)&hid_lo, g_hid_lo);
    cudaGetSymbolAddress((void**)&wq_hi,  g_wq_hi);
    cudaGetSymbolAddress((void**)&wq_lo,  g_wq_lo);
    cudaGetSymbolAddress((void**)&wo_hi,  g_wo_hi);
    cudaGetSymbolAddress((void**)&wo_lo,  g_wo_lo);
    cudaGetSymbolAddress((void**)&at_hi,  g_at_hi);
    cudaGetSymbolAddress((void**)&at_lo,  g_at_lo);

    cudaFuncSetAttribute(gemm_bf16x3,
                         cudaFuncAttributeMaxDynamicSharedMemorySize, GEMM_SMEM);
    cudaFuncSetAttribute(flash_attn_tc,
                         cudaFuncAttributeMaxDynamicSharedMemorySize, FA_SMEM);

    split_bf16<<<(SEQ * HID + 255) / 256, 256>>>(hidden, hid_hi, hid_lo, SEQ * HID);
    split_bf16<<<(QKV_COLS * HID + 255) / 256, 256>>>(w_qkv, wq_hi, wq_lo,
                                                      QKV_COLS * HID);
    split_bf16<<<(HID * HID + 255) / 256, 256>>>(w_o, wo_hi, wo_lo, HID * HID);

    gemm_bf16x3<<<dim3(QKV_COLS / BN, SEQ / BM), 512, GEMM_SMEM>>>(
        hid_hi, hid_lo, wq_hi, wq_lo, qkv_ptr, SEQ, QKV_COLS, HID);

    {
        int total = SEQ * 40 * 32;
        rope_split<<<(total + 255) / 256, 256>>>();
    }

    flash_attn_tc<<<dim3(NQH, SEQ / 64), 128, FA_SMEM>>>();

    gemm_bf16x3<<<dim3(HID / BN, SEQ / BM), 512, GEMM_SMEM>>>(
        at_hi, at_lo, wo_hi, wo_lo, out, SEQ, HID, HID);
}

// round 6
// speedup vs baseline: 1.0982x; 1.0982x over previous
#include <cuda_runtime.h>
#include <cuda_bf16.h>
#include <cuda_fp16.h>
#include <math.h>
#include <float.h>
#include <stdint.h>

#define SEQ    2048
#define HID    2048
#define DHEAD  64
#define NQH    32
#define NKVH   4
#define QKV_COLS 2560   // (32 + 4 + 4) * 64

// ---------------- scratch (no cudaMalloc allowed) ----------------
__device__ float g_qkv [SEQ * QKV_COLS];

__device__ __nv_bfloat16 g_hid_hi[SEQ * HID];
__device__ __nv_bfloat16 g_hid_lo[SEQ * HID];
__device__ __nv_bfloat16 g_wq_hi [QKV_COLS * HID];
__device__ __nv_bfloat16 g_wq_lo [QKV_COLS * HID];
__device__ __nv_bfloat16 g_wo_hi [HID * HID];
__device__ __nv_bfloat16 g_wo_lo [HID * HID];
__device__ __nv_bfloat16 g_at_hi [SEQ * HID];
__device__ __nv_bfloat16 g_at_lo [SEQ * HID];

__device__ __half g_q_hi[NQH  * SEQ * DHEAD];
__device__ __half g_q_lo[NQH  * SEQ * DHEAD];
__device__ __half g_k_hi[NKVH * SEQ * DHEAD];
__device__ __half g_k_lo[NKVH * SEQ * DHEAD];
__device__ __half g_v_hi[NKVH * SEQ * DHEAD];
__device__ __half g_v_lo[NKVH * SEQ * DHEAD];

// ---------------------------------------------------------------------------
// helpers
// ---------------------------------------------------------------------------
__device__ __forceinline__ void cp16(uint32_t s, const void* g) {
    asm volatile("cp.async.cg.shared.global [%0], [%1], 16;\n" :: "r"(s), "l"(g));
}
__device__ __forceinline__ void cp_commit() {
    asm volatile("cp.async.commit_group;\n");
}
template<int N>
__device__ __forceinline__ void cp_wait() {
    asm volatile("cp.async.wait_group %0;\n" :: "n"(N));
}
__device__ __forceinline__ void mma16816(float* d, const uint32_t* a,
                                         const uint32_t* b) {
    asm volatile(
        "mma.sync.aligned.m16n8k16.row.col.f32.bf16.bf16.f32 "
        "{%0,%1,%2,%3}, {%4,%5,%6,%7}, {%8,%9}, {%0,%1,%2,%3};\n"
        : "+f"(d[0]), "+f"(d[1]), "+f"(d[2]), "+f"(d[3])
        : "r"(a[0]), "r"(a[1]), "r"(a[2]), "r"(a[3]), "r"(b[0]), "r"(b[1]));
}
__device__ __forceinline__ void mma_f16(float* d, const uint32_t* a,
                                        const uint32_t* b) {
    asm volatile(
        "mma.sync.aligned.m16n8k16.row.col.f32.f16.f16.f32 "
        "{%0,%1,%2,%3}, {%4,%5,%6,%7}, {%8,%9}, {%0,%1,%2,%3};\n"
        : "+f"(d[0]), "+f"(d[1]), "+f"(d[2]), "+f"(d[3])
        : "r"(a[0]), "r"(a[1]), "r"(a[2]), "r"(a[3]), "r"(b[0]), "r"(b[1]));
}
__device__ __forceinline__ void ldsm_x4(uint32_t* r, uint32_t addr) {
    asm volatile("ldmatrix.sync.aligned.m8n8.x4.shared.b16 {%0,%1,%2,%3}, [%4];\n"
        : "=r"(r[0]), "=r"(r[1]), "=r"(r[2]), "=r"(r[3]) : "r"(addr));
}
__device__ __forceinline__ void ldsm_x4_t(uint32_t* r, uint32_t addr) {
    asm volatile("ldmatrix.sync.aligned.m8n8.x4.trans.shared.b16 {%0,%1,%2,%3}, [%4];\n"
        : "=r"(r[0]), "=r"(r[1]), "=r"(r[2]), "=r"(r[3]) : "r"(addr));
}
__device__ __forceinline__ uint32_t smem_u32_of(const void* p) {
    uint32_t a;
    asm("{ .reg .u64 t; cvta.to.shared.u64 t, %1; cvt.u32.u64 %0, t; }"
        : "=r"(a) : "l"(p));
    return a;
}

// ---------------------------------------------------------------------------
// fp32 -> (bf16 hi, bf16 lo) split, float4 vectorized (n % 4 == 0)
// ---------------------------------------------------------------------------
__global__ void split_bf16_v4(const float4* __restrict__ in,
                              uint2* __restrict__ hi,
                              uint2* __restrict__ lo, int n4) {
    int i = blockIdx.x * blockDim.x + threadIdx.x;
    if (i >= n4) return;
    float4 x = in[i];
    __nv_bfloat16 h0 = __float2bfloat16(x.x);
    __nv_bfloat16 h1 = __float2bfloat16(x.y);
    __nv_bfloat16 h2 = __float2bfloat16(x.z);
    __nv_bfloat16 h3 = __float2bfloat16(x.w);
    __nv_bfloat162 hp0 = {h0, h1}, hp1 = {h2, h3};
    __nv_bfloat162 lp0 = {__float2bfloat16(x.x - __bfloat162float(h0)),
                          __float2bfloat16(x.y - __bfloat162float(h1))};
    __nv_bfloat162 lp1 = {__float2bfloat16(x.z - __bfloat162float(h2)),
                          __float2bfloat16(x.w - __bfloat162float(h3))};
    hi[i] = make_uint2(*(uint32_t*)&hp0, *(uint32_t*)&hp1);
    lo[i] = make_uint2(*(uint32_t*)&lp0, *(uint32_t*)&lp1);
}

// ---------------------------------------------------------------------------
// bf16x3 tensor-core GEMM, 256 threads (8 warps 2x4), warp tile 64x32,
// 3-stage cp.async pipeline, TERM-MAJOR MMA ordering (same-acc distance 16).
// C[M,N] = A[M,K] @ B[N,K]^T, fp32 accumulate
// ---------------------------------------------------------------------------
#define BM 128
#define BN 128
#define BK 32
#define SROW 40
#define BUF_ELEMS (128 * SROW)
#define STAGE_ELEMS (4 * BUF_ELEMS)
#define GEMM_SMEM (3 * STAGE_ELEMS * 2)   // 122880 bytes

__global__ void __launch_bounds__(256, 1)
gemm_bf16x3(const __nv_bfloat16* __restrict__ Ahi,
            const __nv_bfloat16* __restrict__ Alo,
            const __nv_bfloat16* __restrict__ Bhi,
            const __nv_bfloat16* __restrict__ Blo,
            float* __restrict__ C, int M, int N, int K) {
    extern __shared__ __nv_bfloat16 smem[];
    const int tid  = threadIdx.x;
    const int warp = tid >> 5;
    const int lane = tid & 31;
    const int wm   = warp >> 2;
    const int wn   = warp & 3;
    const int g    = lane >> 2;
    const int t    = lane & 3;
    const int row0 = blockIdx.y * BM;
    const int col0 = blockIdx.x * BN;

    uint32_t smem_b = smem_u32_of(smem);

    float acc[4][4][4];
#pragma unroll
    for (int i = 0; i < 4; i++)
#pragma unroll
        for (int j = 0; j < 4; j++)
#pragma unroll
            for (int k = 0; k < 4; k++) acc[i][j][k] = 0.f;

    const int NIT = K / BK;

    auto load_stage = [&](int stage, int k0) {
        uint32_t sb = smem_b + stage * (STAGE_ELEMS * 2);
#pragma unroll
        for (int c = tid; c < 512; c += 256) {
            int row = c >> 2;
            int cc  = c & 3;
            uint32_t so = sb + row * (SROW * 2) + cc * 16;
            size_t ga = (size_t)(row0 + row) * K + k0 + cc * 8;
            size_t gb = (size_t)(col0 + row) * K + k0 + cc * 8;
            cp16(so,                          Ahi + ga);
            cp16(so + 1 * BUF_ELEMS * 2,      Alo + ga);
            cp16(so + 2 * BUF_ELEMS * 2,      Bhi + gb);
            cp16(so + 3 * BUF_ELEMS * 2,      Blo + gb);
        }
    };

    load_stage(0, 0);
    cp_commit();
    load_stage(1, BK);
    cp_commit();

    for (int it = 0; it < NIT; it++) {
        if (it + 2 < NIT) { cp_wait<1>(); } else { cp_wait<0>(); }
        __syncthreads();
        if (it + 2 < NIT) {
            load_stage((it + 2) % 3, (it + 2) * BK);
            cp_commit();
        }

        const __nv_bfloat16* As = smem + (it % 3) * STAGE_ELEMS;
        const __nv_bfloat16* Al = As + BUF_ELEMS;
        const __nv_bfloat16* Bs = As + 2 * BUF_ELEMS;
        const __nv_bfloat16* Bl = As + 3 * BUF_ELEMS;

#pragma unroll
        for (int ks = 0; ks < 2; ks++) {
            uint32_t ahi[4][4], alo[4][4], bhi[4][2], blo[4][2];
#pragma unroll
            for (int mt = 0; mt < 4; mt++) {
                int rb = wm * 64 + mt * 16;
                const __nv_bfloat16* pa = As + (rb + g) * SROW + ks * 16 + 2 * t;
                const __nv_bfloat16* pl = Al + (rb + g) * SROW + ks * 16 + 2 * t;
                ahi[mt][0] = *(const uint32_t*)(pa);
                ahi[mt][1] = *(const uint32_t*)(pa + 8 * SROW);
                ahi[mt][2] = *(const uint32_t*)(pa + 8);
                ahi[mt][3] = *(const uint32_t*)(pa + 8 * SROW + 8);
                alo[mt][0] = *(const uint32_t*)(pl);
                alo[mt][1] = *(const uint32_t*)(pl + 8 * SROW);
                alo[mt][2] = *(const uint32_t*)(pl + 8);
                alo[mt][3] = *(const uint32_t*)(pl + 8 * SROW + 8);
            }
#pragma unroll
            for (int nt = 0; nt < 4; nt++) {
                int cb = wn * 32 + nt * 8;
                const __nv_bfloat16* pb = Bs + (cb + g) * SROW + ks * 16 + 2 * t;
                const __nv_bfloat16* pq = Bl + (cb + g) * SROW + ks * 16 + 2 * t;
                bhi[nt][0] = *(const uint32_t*)(pb);
                bhi[nt][1] = *(const uint32_t*)(pb + 8);
                blo[nt][0] = *(const uint32_t*)(pq);
                blo[nt][1] = *(const uint32_t*)(pq + 8);
            }
            // term-major ordering: same-accumulator reuse distance = 16 MMAs
#pragma unroll
            for (int mt = 0; mt < 4; mt++)
#pragma unroll
                for (int nt = 0; nt < 4; nt++)
                    mma16816(acc[mt][nt], ahi[mt], bhi[nt]);
#pragma unroll
            for (int mt = 0; mt < 4; mt++)
#pragma unroll
                for (int nt = 0; nt < 4; nt++)
                    mma16816(acc[mt][nt], ahi[mt], blo[nt]);
#pragma unroll
            for (int mt = 0; mt < 4; mt++)
#pragma unroll
                for (int nt = 0; nt < 4; nt++)
                    mma16816(acc[mt][nt], alo[mt], bhi[nt]);
        }
        // no trailing sync: 3-stage ring + head sync make reuse safe
    }

#pragma unroll
    for (int mt = 0; mt < 4; mt++) {
        int r = row0 + wm * 64 + mt * 16 + g;
#pragma unroll
        for (int nt = 0; nt < 4; nt++) {
            int c = col0 + wn * 32 + nt * 8 + 2 * t;
            float2 v0 = make_float2(acc[mt][nt][0], acc[mt][nt][1]);
            float2 v1 = make_float2(acc[mt][nt][2], acc[mt][nt][3]);
            *(float2*)&C[(size_t)r * N + c]       = v0;
            *(float2*)&C[(size_t)(r + 8) * N + c] = v1;
        }
    }
}

// ---------------------------------------------------------------------------
// RoPE + fp16 hi/lo split: g_qkv -> head-major q/k/v arrays
// ---------------------------------------------------------------------------
__global__ void rope_split() {
    int idx = blockIdx.x * blockDim.x + threadIdx.x;
    const int total = SEQ * 40 * 32;
    if (idx >= total) return;
    int pair = idx & 31;
    int head = (idx >> 5) % 40;
    int s    = idx / (40 * 32);

    const float* base = g_qkv + (size_t)s * QKV_COLS + head * DHEAD;
    float x1 = base[pair];
    float x2 = base[pair + 32];
    float y1, y2;
    if (head < 36) {
        float inv_freq = __expf(-(float)pair * (9.210340371976184f / 32.0f));
        float ang = (float)s * inv_freq;
        float sn, cs;
        sincosf(ang, &sn, &cs);
        y1 = x1 * cs - x2 * sn;
        y2 = x2 * cs + x1 * sn;
    } else {
        y1 = x1; y2 = x2;
    }

    __half *dh, *dl;
    size_t off;
    if (head < 32) {
        y1 *= 0.125f; y2 *= 0.125f;
        off = ((size_t)head * SEQ + s) * DHEAD;
        dh = g_q_hi; dl = g_q_lo;
    } else if (head < 36) {
        off = ((size_t)(head - 32) * SEQ + s) * DHEAD;
        dh = g_k_hi; dl = g_k_lo;
    } else {
        off = ((size_t)(head - 36) * SEQ + s) * DHEAD;
        dh = g_v_hi; dl = g_v_lo;
    }
    __half h1 = __float2half_rn(y1);
    __half h2 = __float2half_rn(y2);
    dh[off + pair]      = h1;
    dh[off + pair + 32] = h2;
    dl[off + pair]      = __float2half_rn(y1 - __half2float(h1));
    dl[off + pair + 32] = __float2half_rn(y2 - __half2float(h2));
}

// ---------------------------------------------------------------------------
// Tensor-core flash attention (fp16x3), causal, GQA.
// kk-outer MMA ordering: same-accumulator reuse distance = 8.
// ---------------------------------------------------------------------------
#define FSTRIDE 72
#define FTILE (64 * FSTRIDE)
#define FA_SMEM (6 * FTILE * 2)

__global__ void __launch_bounds__(128)
flash_attn_tc() {
    extern __shared__ __half fsm[];
    uint32_t sbase = smem_u32_of(fsm);

    const int head = blockIdx.x;
    const int qb   = gridDim.y - 1 - blockIdx.y;
    const int tid  = threadIdx.x;
    const int w    = tid >> 5;
    const int lane = tid & 31;
    const int kvh  = head >> 3;
    const int r8   = lane & 7;
    const int sub  = lane >> 3;

    {
        const __half* gqh = g_q_hi + ((size_t)head * SEQ + qb * 64) * DHEAD;
        const __half* gql = g_q_lo + ((size_t)head * SEQ + qb * 64) * DHEAD;
#pragma unroll
        for (int i = 0; i < 8; i++) {
            int c   = tid + i * 128;
            int arr = c >> 9;
            int rem = c & 511;
            int row = rem >> 3;
            int ch  = rem & 7;
            uint32_t dst = sbase + arr * (FTILE * 2) + row * 144 + ch * 16;
            const __half* src = (arr ? gql : gqh) + row * DHEAD + ch * 8;
            cp16(dst, src);
        }
        cp_commit(); cp_wait<0>();
        __syncthreads();
    }

    uint32_t qh[4][4], ql[4][4];
#pragma unroll
    for (int kk = 0; kk < 4; kk++) {
        uint32_t addr = sbase
            + (w * 16 + r8 + ((sub & 1) << 3)) * 144
            + kk * 32 + ((sub & 2) << 3);
        ldsm_x4(qh[kk], addr);
        ldsm_x4(ql[kk], addr + FTILE * 2);
    }

    float of[8][4];
#pragma unroll
    for (int f = 0; f < 8; f++)
#pragma unroll
        for (int j = 0; j < 4; j++) of[f][j] = 0.f;
    float m0 = -1e30f, m1 = -1e30f, l0 = 0.f, l1 = 0.f;

    const uint32_t sK = sbase + 2 * (FTILE * 2);
    const uint32_t sV = sbase + 4 * (FTILE * 2);

    for (int kb = 0; kb <= qb; kb++) {
        __syncthreads();
        {
            const size_t go = ((size_t)kvh * SEQ + kb * 64) * DHEAD;
#pragma unroll
            for (int i = 0; i < 16; i++) {
                int c   = tid + i * 128;
                int arr = c >> 9;
                int rem = c & 511;
                int row = rem >> 3;
                int ch  = rem & 7;
                uint32_t dst = sbase + (2 + arr) * (FTILE * 2) + row * 144 + ch * 16;
                const __half* src;
                if      (arr == 0) src = g_k_hi + go;
                else if (arr == 1) src = g_k_lo + go;
                else if (arr == 2) src = g_v_hi + go;
                else               src = g_v_lo + go;
                src += row * DHEAD + ch * 8;
                cp16(dst, src);
            }
            cp_commit(); cp_wait<0>();
            __syncthreads();
        }

        // ---- S = Q K^T (fp16x3), kk-outer ----
        float sf[8][4];
#pragma unroll
        for (int f = 0; f < 8; f++)
#pragma unroll
            for (int j = 0; j < 4; j++) sf[f][j] = 0.f;

#pragma unroll
        for (int kk = 0; kk < 4; kk++) {
            uint32_t bh[4][4], bl[4][4];
#pragma unroll
            for (int p = 0; p < 4; p++) {
                uint32_t addr = sK
                    + (p * 16 + ((sub & 2) << 2) + r8) * 144
                    + kk * 32 + ((sub & 1) << 4);
                ldsm_x4(bh[p], addr);
                ldsm_x4(bl[p], addr + FTILE * 2);
            }
            // term 1: qh * kh  (8 distinct accumulators)
#pragma unroll
            for (int p = 0; p < 4; p++) {
                mma_f16(sf[2 * p],     qh[kk], &bh[p][0]);
                mma_f16(sf[2 * p + 1], qh[kk], &bh[p][2]);
            }
            // term 2: qh * kl
#pragma unroll
            for (int p = 0; p < 4; p++) {
                mma_f16(sf[2 * p],     qh[kk], &bl[p][0]);
                mma_f16(sf[2 * p + 1], qh[kk], &bl[p][2]);
            }
            // term 3: ql * kh
#pragma unroll
            for (int p = 0; p < 4; p++) {
                mma_f16(sf[2 * p],     ql[kk], &bh[p][0]);
                mma_f16(sf[2 * p + 1], ql[kk], &bh[p][2]);
            }
        }

        if (kb == qb) {
            int rt0 = w * 16 + (lane >> 2);
#pragma unroll
            for (int f = 0; f < 8; f++) {
                int ct = 8 * f + 2 * (lane & 3);
                if (ct > rt0)         sf[f][0] = -1e30f;
                if (ct + 1 > rt0)     sf[f][1] = -1e30f;
                if (ct > rt0 + 8)     sf[f][2] = -1e30f;
                if (ct + 1 > rt0 + 8) sf[f][3] = -1e30f;
            }
        }

        float c0 = -1e30f, c1 = -1e30f;
#pragma unroll
        for (int f = 0; f < 8; f++) {
            c0 = fmaxf(c0, fmaxf(sf[f][0], sf[f][1]));
            c1 = fmaxf(c1, fmaxf(sf[f][2], sf[f][3]));
        }
        c0 = fmaxf(c0, __shfl_xor_sync(0xffffffffu, c0, 1));
        c0 = fmaxf(c0, __shfl_xor_sync(0xffffffffu, c0, 2));
        c1 = fmaxf(c1, __shfl_xor_sync(0xffffffffu, c1, 1));
        c1 = fmaxf(c1, __shfl_xor_sync(0xffffffffu, c1, 2));

        float mn0 = fmaxf(m0, c0), mn1 = fmaxf(m1, c1);
        float a0 = __expf(m0 - mn0), a1 = __expf(m1 - mn1);
        m0 = mn0; m1 = mn1;

        float s0 = 0.f, s1 = 0.f;
#pragma unroll
        for (int f = 0; f < 8; f++) {
            sf[f][0] = __expf(sf[f][0] - mn0);
            sf[f][1] = __expf(sf[f][1] - mn0);
            sf[f][2] = __expf(sf[f][2] - mn1);
            sf[f][3] = __expf(sf[f][3] - mn1);
            s0 += sf[f][0] + sf[f][1];
            s1 += sf[f][2] + sf[f][3];
        }
        s0 += __shfl_xor_sync(0xffffffffu, s0, 1);
        s0 += __shfl_xor_sync(0xffffffffu, s0, 2);
        s1 += __shfl_xor_sync(0xffffffffu, s1, 1);
        s1 += __shfl_xor_sync(0xffffffffu, s1, 2);
        l0 = l0 * a0 + s0;
        l1 = l1 * a1 + s1;

#pragma unroll
        for (int f = 0; f < 8; f++) {
            of[f][0] *= a0; of[f][1] *= a0;
            of[f][2] *= a1; of[f][3] *= a1;
        }

        uint32_t ph[4][4], pl[4][4];
#pragma unroll
        for (int kk = 0; kk < 4; kk++) {
#pragma unroll
            for (int half4 = 0; half4 < 4; half4++) {
                int f = 2 * kk + (half4 >> 1);
                int j = (half4 & 1) * 2;
                float v0 = sf[f][j], v1 = sf[f][j + 1];
                __half h0 = __float2half_rn(v0);
                __half h1 = __float2half_rn(v1);
                __half2 hp = __halves2half2(h0, h1);
                __half2 lp = __halves2half2(
                    __float2half_rn(v0 - __half2float(h0)),
                    __float2half_rn(v1 - __half2float(h1)));
                int slot = (half4 >> 1) * 2 + (half4 & 1);
                ph[kk][slot] = *(uint32_t*)&hp;
                pl[kk][slot] = *(uint32_t*)&lp;
            }
        }

        // ---- O += P V (fp16x3), kk-outer ----
#pragma unroll
        for (int kk = 0; kk < 4; kk++) {
            uint32_t vh[4][4], vl[4][4];
#pragma unroll
            for (int p = 0; p < 4; p++) {
                uint32_t addr = sV
                    + (kk * 16 + ((sub & 1) << 3) + r8) * 144
                    + p * 32 + ((sub & 2) << 3);
                ldsm_x4_t(vh[p], addr);
                ldsm_x4_t(vl[p], addr + FTILE * 2);
            }
#pragma unroll
            for (int p = 0; p < 4; p++) {
                mma_f16(of[2 * p],     ph[kk], &vh[p][0]);
                mma_f16(of[2 * p + 1], ph[kk], &vh[p][2]);
            }
#pragma unroll
            for (int p = 0; p < 4; p++) {
                mma_f16(of[2 * p],     ph[kk], &vl[p][0]);
                mma_f16(of[2 * p + 1], ph[kk], &vl[p][2]);
            }
#pragma unroll
            for (int p = 0; p < 4; p++) {
                mma_f16(of[2 * p],     pl[kk], &vh[p][0]);
                mma_f16(of[2 * p + 1], pl[kk], &vh[p][2]);
            }
        }
    }

    float inv0 = 1.0f / l0, inv1 = 1.0f / l1;
    int rq = qb * 64 + w * 16 + (lane >> 2);
    int cb = head * DHEAD + 2 * (lane & 3);
#pragma unroll
    for (int f = 0; f < 8; f++) {
        int col = cb + 8 * f;
        float v00 = of[f][0] * inv0, v01 = of[f][1] * inv0;
        float v10 = of[f][2] * inv1, v11 = of[f][3] * inv1;
        __nv_bfloat16 h00 = __float2bfloat16(v00);
        __nv_bfloat16 h01 = __float2bfloat16(v01);
        __nv_bfloat16 h10 = __float2bfloat16(v10);
        __nv_bfloat16 h11 = __float2bfloat16(v11);
        __nv_bfloat162 hp0 = {h00, h01};
        __nv_bfloat162 hp1 = {h10, h11};
        __nv_bfloat162 lp0 = {__float2bfloat16(v00 - __bfloat162float(h00)),
                              __float2bfloat16(v01 - __bfloat162float(h01))};
        __nv_bfloat162 lp1 = {__float2bfloat16(v10 - __bfloat162float(h10)),
                              __float2bfloat16(v11 - __bfloat162float(h11))};
        *(uint32_t*)&g_at_hi[(size_t)rq * HID + col]       = *(uint32_t*)&hp0;
        *(uint32_t*)&g_at_hi[(size_t)(rq + 8) * HID + col] = *(uint32_t*)&hp1;
        *(uint32_t*)&g_at_lo[(size_t)rq * HID + col]       = *(uint32_t*)&lp0;
        *(uint32_t*)&g_at_lo[(size_t)(rq + 8) * HID + col] = *(uint32_t*)&lp1;
    }
}

// ---------------------------------------------------------------------------
extern "C" void kernel_launch(void* const* d_in, const int* in_sizes, int n_in,
                              void* d_out, int out_size) {
    const float* hidden = (const float*)d_in[0];
    const float* w_qkv  = (const float*)d_in[1];
    const float* w_o    = (const float*)d_in[2];
    float*       out    = (float*)d_out;

    float* qkv_ptr = nullptr;
    cudaGetSymbolAddress((void**)&qkv_ptr, g_qkv);
    __nv_bfloat16 *hid_hi, *hid_lo, *wq_hi, *wq_lo, *wo_hi, *wo_lo, *at_hi, *at_lo;
    cudaGetSymbolAddress((void**)&hid_hi, g_hid_hi);
    cudaGetSymbolAddress((void**)&hid_lo, g_hid_lo);
    cudaGetSymbolAddress((void**)&wq_hi,  g_wq_hi);
    cudaGetSymbolAddress((void**)&wq_lo,  g_wq_lo);
    cudaGetSymbolAddress((void**)&wo_hi,  g_wo_hi);
    cudaGetSymbolAddress((void**)&wo_lo,  g_wo_lo);
    cudaGetSymbolAddress((void**)&at_hi,  g_at_hi);
    cudaGetSymbolAddress((void**)&at_lo,  g_at_lo);

    cudaFuncSetAttribute(gemm_bf16x3,
                         cudaFuncAttributeMaxDynamicSharedMemorySize, GEMM_SMEM);
    cudaFuncSetAttribute(flash_attn_tc,
                         cudaFuncAttributeMaxDynamicSharedMemorySize, FA_SMEM);

    split_bf16_v4<<<(SEQ * HID / 4 + 255) / 256, 256>>>(
        (const float4*)hidden, (uint2*)hid_hi, (uint2*)hid_lo, SEQ * HID / 4);
    split_bf16_v4<<<(QKV_COLS * HID / 4 + 255) / 256, 256>>>(
        (const float4*)w_qkv, (uint2*)wq_hi, (uint2*)wq_lo, QKV_COLS * HID / 4);
    split_bf16_v4<<<(HID * HID / 4 + 255) / 256, 256>>>(
        (const float4*)w_o, (uint2*)wo_hi, (uint2*)wo_lo, HID * HID / 4);

    gemm_bf16x3<<<dim3(QKV_COLS / BN, SEQ / BM), 256, GEMM_SMEM>>>(
        hid_hi, hid_lo, wq_hi, wq_lo, qkv_ptr, SEQ, QKV_COLS, HID);

    {
        int total = SEQ * 40 * 32;
        rope_split<<<(total + 255) / 256, 256>>>();
    }

    flash_attn_tc<<<dim3(NQH, SEQ / 64), 128, FA_SMEM>>>();

    gemm_bf16x3<<<dim3(HID / BN, SEQ / BM), 256, GEMM_SMEM>>>(
        at_hi, at_lo, wo_hi, wo_lo, out, SEQ, HID, HID);
}

// round 7
// speedup vs baseline: 1.1225x; 1.0221x over previous
#include <cuda_runtime.h>
#include <cuda_bf16.h>
#include <cuda_fp16.h>
#include <math.h>
#include <float.h>
#include <stdint.h>

#define SEQ    2048
#define HID    2048
#define DHEAD  64
#define NQH    32
#define NKVH   4
#define QKV_COLS 2560   // (32 + 4 + 4) * 64

// ---------------- scratch (no cudaMalloc allowed) ----------------
__device__ float g_qkv [SEQ * QKV_COLS];

__device__ __nv_bfloat16 g_hid_hi[SEQ * HID];
__device__ __nv_bfloat16 g_hid_lo[SEQ * HID];
__device__ __nv_bfloat16 g_wq_hi [QKV_COLS * HID];
__device__ __nv_bfloat16 g_wq_lo [QKV_COLS * HID];
__device__ __nv_bfloat16 g_wo_hi [HID * HID];
__device__ __nv_bfloat16 g_wo_lo [HID * HID];
__device__ __nv_bfloat16 g_at_hi [SEQ * HID];
__device__ __nv_bfloat16 g_at_lo [SEQ * HID];

__device__ __half g_q_hi[NQH  * SEQ * DHEAD];
__device__ __half g_q_lo[NQH  * SEQ * DHEAD];
__device__ __half g_k_hi[NKVH * SEQ * DHEAD];
__device__ __half g_k_lo[NKVH * SEQ * DHEAD];
__device__ __half g_v_hi[NKVH * SEQ * DHEAD];
__device__ __half g_v_lo[NKVH * SEQ * DHEAD];

// ---------------------------------------------------------------------------
// helpers
// ---------------------------------------------------------------------------
__device__ __forceinline__ void cp16(uint32_t s, const void* g) {
    asm volatile("cp.async.cg.shared.global [%0], [%1], 16;\n" :: "r"(s), "l"(g));
}
__device__ __forceinline__ void cp_commit() {
    asm volatile("cp.async.commit_group;\n");
}
template<int N>
__device__ __forceinline__ void cp_wait() {
    asm volatile("cp.async.wait_group %0;\n" :: "n"(N));
}
__device__ __forceinline__ void mma16816(float* d, const uint32_t* a,
                                         const uint32_t* b) {
    asm volatile(
        "mma.sync.aligned.m16n8k16.row.col.f32.bf16.bf16.f32 "
        "{%0,%1,%2,%3}, {%4,%5,%6,%7}, {%8,%9}, {%0,%1,%2,%3};\n"
        : "+f"(d[0]), "+f"(d[1]), "+f"(d[2]), "+f"(d[3])
        : "r"(a[0]), "r"(a[1]), "r"(a[2]), "r"(a[3]), "r"(b[0]), "r"(b[1]));
}
__device__ __forceinline__ void mma_f16(float* d, const uint32_t* a,
                                        const uint32_t* b) {
    asm volatile(
        "mma.sync.aligned.m16n8k16.row.col.f32.f16.f16.f32 "
        "{%0,%1,%2,%3}, {%4,%5,%6,%7}, {%8,%9}, {%0,%1,%2,%3};\n"
        : "+f"(d[0]), "+f"(d[1]), "+f"(d[2]), "+f"(d[3])
        : "r"(a[0]), "r"(a[1]), "r"(a[2]), "r"(a[3]), "r"(b[0]), "r"(b[1]));
}
__device__ __forceinline__ void ldsm_x4(uint32_t* r, uint32_t addr) {
    asm volatile("ldmatrix.sync.aligned.m8n8.x4.shared.b16 {%0,%1,%2,%3}, [%4];\n"
        : "=r"(r[0]), "=r"(r[1]), "=r"(r[2]), "=r"(r[3]) : "r"(addr));
}
__device__ __forceinline__ void ldsm_x4_t(uint32_t* r, uint32_t addr) {
    asm volatile("ldmatrix.sync.aligned.m8n8.x4.trans.shared.b16 {%0,%1,%2,%3}, [%4];\n"
        : "=r"(r[0]), "=r"(r[1]), "=r"(r[2]), "=r"(r[3]) : "r"(addr));
}
__device__ __forceinline__ uint32_t smem_u32_of(const void* p) {
    uint32_t a;
    asm("{ .reg .u64 t; cvta.to.shared.u64 t, %1; cvt.u32.u64 %0, t; }"
        : "=r"(a) : "l"(p));
    return a;
}

// ---------------------------------------------------------------------------
// fp32 -> (bf16 hi, bf16 lo) split, float4 vectorized (n % 4 == 0)
// ---------------------------------------------------------------------------
__global__ void split_bf16_v4(const float4* __restrict__ in,
                              uint2* __restrict__ hi,
                              uint2* __restrict__ lo, int n4) {
    int i = blockIdx.x * blockDim.x + threadIdx.x;
    if (i >= n4) return;
    float4 x = in[i];
    __nv_bfloat16 h0 = __float2bfloat16(x.x);
    __nv_bfloat16 h1 = __float2bfloat16(x.y);
    __nv_bfloat16 h2 = __float2bfloat16(x.z);
    __nv_bfloat16 h3 = __float2bfloat16(x.w);
    __nv_bfloat162 hp0 = {h0, h1}, hp1 = {h2, h3};
    __nv_bfloat162 lp0 = {__float2bfloat16(x.x - __bfloat162float(h0)),
                          __float2bfloat16(x.y - __bfloat162float(h1))};
    __nv_bfloat162 lp1 = {__float2bfloat16(x.z - __bfloat162float(h2)),
                          __float2bfloat16(x.w - __bfloat162float(h3))};
    hi[i] = make_uint2(*(uint32_t*)&hp0, *(uint32_t*)&hp1);
    lo[i] = make_uint2(*(uint32_t*)&lp0, *(uint32_t*)&lp1);
}

// ---------------------------------------------------------------------------
// bf16x3 tensor-core GEMM: BM=128 BN=64 BK=32, 8 warps (4x2), warp tile 32x32,
// 3-stage cp.async pipeline, 30KB/stage -> 90KB smem -> 2 CTAs/SM.
// C[M,N] = A[M,K] @ B[N,K]^T, fp32 accumulate
// ---------------------------------------------------------------------------
#define BM 128
#define BN 64
#define BK 32
#define SROW 40
#define A_ELE (128 * SROW)                 // elements per A buffer
#define B_ELE (64 * SROW)                  // elements per B buffer
#define STAGE_E (2 * A_ELE + 2 * B_ELE)    // 15360 elements
#define GEMM_SMEM (3 * STAGE_E * 2)        // 92160 bytes

__global__ void __launch_bounds__(256, 2)
gemm_bf16x3(const __nv_bfloat16* __restrict__ Ahi,
            const __nv_bfloat16* __restrict__ Alo,
            const __nv_bfloat16* __restrict__ Bhi,
            const __nv_bfloat16* __restrict__ Blo,
            float* __restrict__ C, int M, int N, int K) {
    extern __shared__ __nv_bfloat16 smem[];
    const int tid  = threadIdx.x;
    const int warp = tid >> 5;
    const int lane = tid & 31;
    const int wm   = warp >> 1;        // 0..3
    const int wn   = warp & 1;         // 0..1
    const int g    = lane >> 2;        // 0..7
    const int t    = lane & 3;         // 0..3
    const int row0 = blockIdx.y * BM;
    const int col0 = blockIdx.x * BN;

    uint32_t smem_b = smem_u32_of(smem);

    float acc[2][4][4];
#pragma unroll
    for (int i = 0; i < 2; i++)
#pragma unroll
        for (int j = 0; j < 4; j++)
#pragma unroll
            for (int k = 0; k < 4; k++) acc[i][j][k] = 0.f;

    const int NIT = K / BK;   // 64

    auto load_stage = [&](int stage, int k0) {
        uint32_t sb = smem_b + stage * (STAGE_E * 2);
        // A hi/lo: 512 chunks per buffer, 2 per thread
#pragma unroll
        for (int p = 0; p < 2; p++) {
            int c   = tid + p * 256;
            int row = c >> 2;
            int cc  = c & 3;
            uint32_t so = sb + row * (SROW * 2) + cc * 16;
            size_t ga = (size_t)(row0 + row) * K + k0 + cc * 8;
            cp16(so,               Ahi + ga);
            cp16(so + A_ELE * 2,   Alo + ga);
        }
        // B hi/lo: 256 chunks per buffer, 1 per thread
        {
            int row = tid >> 2;
            int cc  = tid & 3;
            uint32_t so = sb + 2 * (A_ELE * 2) + row * (SROW * 2) + cc * 16;
            size_t gb = (size_t)(col0 + row) * K + k0 + cc * 8;
            cp16(so,               Bhi + gb);
            cp16(so + B_ELE * 2,   Blo + gb);
        }
        cp_commit();
    };

    load_stage(0, 0);
    load_stage(1, BK);

    for (int it = 0; it < NIT; it++) {
        if (it + 2 < NIT) { cp_wait<1>(); } else { cp_wait<0>(); }
        __syncthreads();
        if (it + 2 < NIT) load_stage((it + 2) % 3, (it + 2) * BK);

        const __nv_bfloat16* As = smem + (it % 3) * STAGE_E;
        const __nv_bfloat16* Al = As + A_ELE;
        const __nv_bfloat16* Bs = As + 2 * A_ELE;
        const __nv_bfloat16* Bl = Bs + B_ELE;

#pragma unroll
        for (int ks = 0; ks < 2; ks++) {
            uint32_t ahi[2][4], alo[2][4], bhi[4][2], blo[4][2];
#pragma unroll
            for (int mt = 0; mt < 2; mt++) {
                int rb = wm * 32 + mt * 16;
                const __nv_bfloat16* pa = As + (rb + g) * SROW + ks * 16 + 2 * t;
                const __nv_bfloat16* pl = Al + (rb + g) * SROW + ks * 16 + 2 * t;
                ahi[mt][0] = *(const uint32_t*)(pa);
                ahi[mt][1] = *(const uint32_t*)(pa + 8 * SROW);
                ahi[mt][2] = *(const uint32_t*)(pa + 8);
                ahi[mt][3] = *(const uint32_t*)(pa + 8 * SROW + 8);
                alo[mt][0] = *(const uint32_t*)(pl);
                alo[mt][1] = *(const uint32_t*)(pl + 8 * SROW);
                alo[mt][2] = *(const uint32_t*)(pl + 8);
                alo[mt][3] = *(const uint32_t*)(pl + 8 * SROW + 8);
            }
#pragma unroll
            for (int nt = 0; nt < 4; nt++) {
                int cb = wn * 32 + nt * 8;
                const __nv_bfloat16* pb = Bs + (cb + g) * SROW + ks * 16 + 2 * t;
                const __nv_bfloat16* pq = Bl + (cb + g) * SROW + ks * 16 + 2 * t;
                bhi[nt][0] = *(const uint32_t*)(pb);
                bhi[nt][1] = *(const uint32_t*)(pb + 8);
                blo[nt][0] = *(const uint32_t*)(pq);
                blo[nt][1] = *(const uint32_t*)(pq + 8);
            }
            // term-major: same-accumulator reuse distance = 8 MMAs
#pragma unroll
            for (int mt = 0; mt < 2; mt++)
#pragma unroll
                for (int nt = 0; nt < 4; nt++)
                    mma16816(acc[mt][nt], ahi[mt], bhi[nt]);
#pragma unroll
            for (int mt = 0; mt < 2; mt++)
#pragma unroll
                for (int nt = 0; nt < 4; nt++)
                    mma16816(acc[mt][nt], ahi[mt], blo[nt]);
#pragma unroll
            for (int mt = 0; mt < 2; mt++)
#pragma unroll
                for (int nt = 0; nt < 4; nt++)
                    mma16816(acc[mt][nt], alo[mt], bhi[nt]);
        }
    }

#pragma unroll
    for (int mt = 0; mt < 2; mt++) {
        int r = row0 + wm * 32 + mt * 16 + g;
#pragma unroll
        for (int nt = 0; nt < 4; nt++) {
            int c = col0 + wn * 32 + nt * 8 + 2 * t;
            float2 v0 = make_float2(acc[mt][nt][0], acc[mt][nt][1]);
            float2 v1 = make_float2(acc[mt][nt][2], acc[mt][nt][3]);
            *(float2*)&C[(size_t)r * N + c]       = v0;
            *(float2*)&C[(size_t)(r + 8) * N + c] = v1;
        }
    }
}

// ---------------------------------------------------------------------------
// RoPE + fp16 hi/lo split: g_qkv -> head-major q/k/v arrays
// ---------------------------------------------------------------------------
__global__ void rope_split() {
    int idx = blockIdx.x * blockDim.x + threadIdx.x;
    const int total = SEQ * 40 * 32;
    if (idx >= total) return;
    int pair = idx & 31;
    int head = (idx >> 5) % 40;
    int s    = idx / (40 * 32);

    const float* base = g_qkv + (size_t)s * QKV_COLS + head * DHEAD;
    float x1 = base[pair];
    float x2 = base[pair + 32];
    float y1, y2;
    if (head < 36) {
        float inv_freq = __expf(-(float)pair * (9.210340371976184f / 32.0f));
        float ang = (float)s * inv_freq;
        float sn, cs;
        sincosf(ang, &sn, &cs);
        y1 = x1 * cs - x2 * sn;
        y2 = x2 * cs + x1 * sn;
    } else {
        y1 = x1; y2 = x2;
    }

    __half *dh, *dl;
    size_t off;
    if (head < 32) {
        y1 *= 0.125f; y2 *= 0.125f;
        off = ((size_t)head * SEQ + s) * DHEAD;
        dh = g_q_hi; dl = g_q_lo;
    } else if (head < 36) {
        off = ((size_t)(head - 32) * SEQ + s) * DHEAD;
        dh = g_k_hi; dl = g_k_lo;
    } else {
        off = ((size_t)(head - 36) * SEQ + s) * DHEAD;
        dh = g_v_hi; dl = g_v_lo;
    }
    __half h1 = __float2half_rn(y1);
    __half h2 = __float2half_rn(y2);
    dh[off + pair]      = h1;
    dh[off + pair + 32] = h2;
    dl[off + pair]      = __float2half_rn(y1 - __half2float(h1));
    dl[off + pair + 32] = __float2half_rn(y2 - __half2float(h2));
}

// ---------------------------------------------------------------------------
// Tensor-core flash attention (fp16x3), causal, GQA. kk-outer ordering.
// ---------------------------------------------------------------------------
#define FSTRIDE 72
#define FTILE (64 * FSTRIDE)
#define FA_SMEM (6 * FTILE * 2)

__global__ void __launch_bounds__(128)
flash_attn_tc() {
    extern __shared__ __half fsm[];
    uint32_t sbase = smem_u32_of(fsm);

    const int head = blockIdx.x;
    const int qb   = gridDim.y - 1 - blockIdx.y;
    const int tid  = threadIdx.x;
    const int w    = tid >> 5;
    const int lane = tid & 31;
    const int kvh  = head >> 3;
    const int r8   = lane & 7;
    const int sub  = lane >> 3;

    {
        const __half* gqh = g_q_hi + ((size_t)head * SEQ + qb * 64) * DHEAD;
        const __half* gql = g_q_lo + ((size_t)head * SEQ + qb * 64) * DHEAD;
#pragma unroll
        for (int i = 0; i < 8; i++) {
            int c   = tid + i * 128;
            int arr = c >> 9;
            int rem = c & 511;
            int row = rem >> 3;
            int ch  = rem & 7;
            uint32_t dst = sbase + arr * (FTILE * 2) + row * 144 + ch * 16;
            const __half* src = (arr ? gql : gqh) + row * DHEAD + ch * 8;
            cp16(dst, src);
        }
        cp_commit(); cp_wait<0>();
        __syncthreads();
    }

    uint32_t qh[4][4], ql[4][4];
#pragma unroll
    for (int kk = 0; kk < 4; kk++) {
        uint32_t addr = sbase
            + (w * 16 + r8 + ((sub & 1) << 3)) * 144
            + kk * 32 + ((sub & 2) << 3);
        ldsm_x4(qh[kk], addr);
        ldsm_x4(ql[kk], addr + FTILE * 2);
    }

    float of[8][4];
#pragma unroll
    for (int f = 0; f < 8; f++)
#pragma unroll
        for (int j = 0; j < 4; j++) of[f][j] = 0.f;
    float m0 = -1e30f, m1 = -1e30f, l0 = 0.f, l1 = 0.f;

    const uint32_t sK = sbase + 2 * (FTILE * 2);
    const uint32_t sV = sbase + 4 * (FTILE * 2);

    for (int kb = 0; kb <= qb; kb++) {
        __syncthreads();
        {
            const size_t go = ((size_t)kvh * SEQ + kb * 64) * DHEAD;
#pragma unroll
            for (int i = 0; i < 16; i++) {
                int c   = tid + i * 128;
                int arr = c >> 9;
                int rem = c & 511;
                int row = rem >> 3;
                int ch  = rem & 7;
                uint32_t dst = sbase + (2 + arr) * (FTILE * 2) + row * 144 + ch * 16;
                const __half* src;
                if      (arr == 0) src = g_k_hi + go;
                else if (arr == 1) src = g_k_lo + go;
                else if (arr == 2) src = g_v_hi + go;
                else               src = g_v_lo + go;
                src += row * DHEAD + ch * 8;
                cp16(dst, src);
            }
            cp_commit(); cp_wait<0>();
            __syncthreads();
        }

        float sf[8][4];
#pragma unroll
        for (int f = 0; f < 8; f++)
#pragma unroll
            for (int j = 0; j < 4; j++) sf[f][j] = 0.f;

#pragma unroll
        for (int kk = 0; kk < 4; kk++) {
            uint32_t bh[4][4], bl[4][4];
#pragma unroll
            for (int p = 0; p < 4; p++) {
                uint32_t addr = sK
                    + (p * 16 + ((sub & 2) << 2) + r8) * 144
                    + kk * 32 + ((sub & 1) << 4);
                ldsm_x4(bh[p], addr);
                ldsm_x4(bl[p], addr + FTILE * 2);
            }
#pragma unroll
            for (int p = 0; p < 4; p++) {
                mma_f16(sf[2 * p],     qh[kk], &bh[p][0]);
                mma_f16(sf[2 * p + 1], qh[kk], &bh[p][2]);
            }
#pragma unroll
            for (int p = 0; p < 4; p++) {
                mma_f16(sf[2 * p],     qh[kk], &bl[p][0]);
                mma_f16(sf[2 * p + 1], qh[kk], &bl[p][2]);
            }
#pragma unroll
            for (int p = 0; p < 4; p++) {
                mma_f16(sf[2 * p],     ql[kk], &bh[p][0]);
                mma_f16(sf[2 * p + 1], ql[kk], &bh[p][2]);
            }
        }

        if (kb == qb) {
            int rt0 = w * 16 + (lane >> 2);
#pragma unroll
            for (int f = 0; f < 8; f++) {
                int ct = 8 * f + 2 * (lane & 3);
                if (ct > rt0)         sf[f][0] = -1e30f;
                if (ct + 1 > rt0)     sf[f][1] = -1e30f;
                if (ct > rt0 + 8)     sf[f][2] = -1e30f;
                if (ct + 1 > rt0 + 8) sf[f][3] = -1e30f;
            }
        }

        float c0 = -1e30f, c1 = -1e30f;
#pragma unroll
        for (int f = 0; f < 8; f++) {
            c0 = fmaxf(c0, fmaxf(sf[f][0], sf[f][1]));
            c1 = fmaxf(c1, fmaxf(sf[f][2], sf[f][3]));
        }
        c0 = fmaxf(c0, __shfl_xor_sync(0xffffffffu, c0, 1));
        c0 = fmaxf(c0, __shfl_xor_sync(0xffffffffu, c0, 2));
        c1 = fmaxf(c1, __shfl_xor_sync(0xffffffffu, c1, 1));
        c1 = fmaxf(c1, __shfl_xor_sync(0xffffffffu, c1, 2));

        float mn0 = fmaxf(m0, c0), mn1 = fmaxf(m1, c1);
        float a0 = __expf(m0 - mn0), a1 = __expf(m1 - mn1);
        m0 = mn0; m1 = mn1;

        float s0 = 0.f, s1 = 0.f;
#pragma unroll
        for (int f = 0; f < 8; f++) {
            sf[f][0] = __expf(sf[f][0] - mn0);
            sf[f][1] = __expf(sf[f][1] - mn0);
            sf[f][2] = __expf(sf[f][2] - mn1);
            sf[f][3] = __expf(sf[f][3] - mn1);
            s0 += sf[f][0] + sf[f][1];
            s1 += sf[f][2] + sf[f][3];
        }
        s0 += __shfl_xor_sync(0xffffffffu, s0, 1);
        s0 += __shfl_xor_sync(0xffffffffu, s0, 2);
        s1 += __shfl_xor_sync(0xffffffffu, s1, 1);
        s1 += __shfl_xor_sync(0xffffffffu, s1, 2);
        l0 = l0 * a0 + s0;
        l1 = l1 * a1 + s1;

#pragma unroll
        for (int f = 0; f < 8; f++) {
            of[f][0] *= a0; of[f][1] *= a0;
            of[f][2] *= a1; of[f][3] *= a1;
        }

        uint32_t ph[4][4], pl[4][4];
#pragma unroll
        for (int kk = 0; kk < 4; kk++) {
#pragma unroll
            for (int half4 = 0; half4 < 4; half4++) {
                int f = 2 * kk + (half4 >> 1);
                int j = (half4 & 1) * 2;
                float v0 = sf[f][j], v1 = sf[f][j + 1];
                __half h0 = __float2half_rn(v0);
                __half h1 = __float2half_rn(v1);
                __half2 hp = __halves2half2(h0, h1);
                __half2 lp = __halves2half2(
                    __float2half_rn(v0 - __half2float(h0)),
                    __float2half_rn(v1 - __half2float(h1)));
                int slot = (half4 >> 1) * 2 + (half4 & 1);
                ph[kk][slot] = *(uint32_t*)&hp;
                pl[kk][slot] = *(uint32_t*)&lp;
            }
        }

#pragma unroll
        for (int kk = 0; kk < 4; kk++) {
            uint32_t vh[4][4], vl[4][4];
#pragma unroll
            for (int p = 0; p < 4; p++) {
                uint32_t addr = sV
                    + (kk * 16 + ((sub & 1) << 3) + r8) * 144
                    + p * 32 + ((sub & 2) << 3);
                ldsm_x4_t(vh[p], addr);
                ldsm_x4_t(vl[p], addr + FTILE * 2);
            }
#pragma unroll
            for (int p = 0; p < 4; p++) {
                mma_f16(of[2 * p],     ph[kk], &vh[p][0]);
                mma_f16(of[2 * p + 1], ph[kk], &vh[p][2]);
            }
#pragma unroll
            for (int p = 0; p < 4; p++) {
                mma_f16(of[2 * p],     ph[kk], &vl[p][0]);
                mma_f16(of[2 * p + 1], ph[kk], &vl[p][2]);
            }
#pragma unroll
            for (int p = 0; p < 4; p++) {
                mma_f16(of[2 * p],     pl[kk], &vh[p][0]);
                mma_f16(of[2 * p + 1], pl[kk], &vh[p][2]);
            }
        }
    }

    float inv0 = 1.0f / l0, inv1 = 1.0f / l1;
    int rq = qb * 64 + w * 16 + (lane >> 2);
    int cb = head * DHEAD + 2 * (lane & 3);
#pragma unroll
    for (int f = 0; f < 8; f++) {
        int col = cb + 8 * f;
        float v00 = of[f][0] * inv0, v01 = of[f][1] * inv0;
        float v10 = of[f][2] * inv1, v11 = of[f][3] * inv1;
        __nv_bfloat16 h00 = __float2bfloat16(v00);
        __nv_bfloat16 h01 = __float2bfloat16(v01);
        __nv_bfloat16 h10 = __float2bfloat16(v10);
        __nv_bfloat16 h11 = __float2bfloat16(v11);
        __nv_bfloat162 hp0 = {h00, h01};
        __nv_bfloat162 hp1 = {h10, h11};
        __nv_bfloat162 lp0 = {__float2bfloat16(v00 - __bfloat162float(h00)),
                              __float2bfloat16(v01 - __bfloat162float(h01))};
        __nv_bfloat162 lp1 = {__float2bfloat16(v10 - __bfloat162float(h10)),
                              __float2bfloat16(v11 - __bfloat162float(h11))};
        *(uint32_t*)&g_at_hi[(size_t)rq * HID + col]       = *(uint32_t*)&hp0;
        *(uint32_t*)&g_at_hi[(size_t)(rq + 8) * HID + col] = *(uint32_t*)&hp1;
        *(uint32_t*)&g_at_lo[(size_t)rq * HID + col]       = *(uint32_t*)&lp0;
        *(uint32_t*)&g_at_lo[(size_t)(rq + 8) * HID + col] = *(uint32_t*)&lp1;
    }
}

// ---------------------------------------------------------------------------
extern "C" void kernel_launch(void* const* d_in, const int* in_sizes, int n_in,
                              void* d_out, int out_size) {
    const float* hidden = (const float*)d_in[0];
    const float* w_qkv  = (const float*)d_in[1];
    const float* w_o    = (const float*)d_in[2];
    float*       out    = (float*)d_out;

    float* qkv_ptr = nullptr;
    cudaGetSymbolAddress((void**)&qkv_ptr, g_qkv);
    __nv_bfloat16 *hid_hi, *hid_lo, *wq_hi, *wq_lo, *wo_hi, *wo_lo, *at_hi, *at_lo;
    cudaGetSymbolAddress((void**)&hid_hi, g_hid_hi);
    cudaGetSymbolAddress((void**)&hid_lo, g_hid_lo);
    cudaGetSymbolAddress((void**)&wq_hi,  g_wq_hi);
    cudaGetSymbolAddress((void**)&wq_lo,  g_wq_lo);
    cudaGetSymbolAddress((void**)&wo_hi,  g_wo_hi);
    cudaGetSymbolAddress((void**)&wo_lo,  g_wo_lo);
    cudaGetSymbolAddress((void**)&at_hi,  g_at_hi);
    cudaGetSymbolAddress((void**)&at_lo,  g_at_lo);

    cudaFuncSetAttribute(gemm_bf16x3,
                         cudaFuncAttributeMaxDynamicSharedMemorySize, GEMM_SMEM);
    cudaFuncSetAttribute(flash_attn_tc,
                         cudaFuncAttributeMaxDynamicSharedMemorySize, FA_SMEM);

    split_bf16_v4<<<(SEQ * HID / 4 + 255) / 256, 256>>>(
        (const float4*)hidden, (uint2*)hid_hi, (uint2*)hid_lo, SEQ * HID / 4);
    split_bf16_v4<<<(QKV_COLS * HID / 4 + 255) / 256, 256>>>(
        (const float4*)w_qkv, (uint2*)wq_hi, (uint2*)wq_lo, QKV_COLS * HID / 4);
    split_bf16_v4<<<(HID * HID / 4 + 255) / 256, 256>>>(
        (const float4*)w_o, (uint2*)wo_hi, (uint2*)wo_lo, HID * HID / 4);

    gemm_bf16x3<<<dim3(QKV_COLS / BN, SEQ / BM), 256, GEMM_SMEM>>>(
        hid_hi, hid_lo, wq_hi, wq_lo, qkv_ptr, SEQ, QKV_COLS, HID);

    {
        int total = SEQ * 40 * 32;
        rope_split<<<(total + 255) / 256, 256>>>();
    }

    flash_attn_tc<<<dim3(NQH, SEQ / 64), 128, FA_SMEM>>>();

    gemm_bf16x3<<<dim3(HID / BN, SEQ / BM), 256, GEMM_SMEM>>>(
        at_hi, at_lo, wo_hi, wo_lo, out, SEQ, HID, HID);
}

// round 8
// speedup vs baseline: 1.5414x; 1.3732x over previous
#include <cuda_runtime.h>
#include <cuda_fp16.h>
#include <math.h>
#include <float.h>
#include <stdint.h>

#define SEQ    2048
#define HID    2048
#define DHEAD  64
#define NQH    32
#define NKVH   4
#define QKV_COLS 2560   // (32 + 4 + 4) * 64

// ---------------- scratch (no cudaMalloc allowed) ----------------
__device__ float g_qkv [SEQ * QKV_COLS];

__device__ __half g_hid_h[SEQ * HID];
__device__ __half g_wq_h [QKV_COLS * HID];
__device__ __half g_wq_l [QKV_COLS * HID];
__device__ __half g_wo_h [HID * HID];
__device__ __half g_wo_l [HID * HID];
__device__ __half g_at_h [SEQ * HID];

__device__ __half g_q_h[NQH  * SEQ * DHEAD];
__device__ __half g_k_h[NKVH * SEQ * DHEAD];
__device__ __half g_k_l[NKVH * SEQ * DHEAD];
__device__ __half g_v_h[NKVH * SEQ * DHEAD];
__device__ __half g_v_l[NKVH * SEQ * DHEAD];

// ---------------------------------------------------------------------------
// helpers
// ---------------------------------------------------------------------------
__device__ __forceinline__ void cp16(uint32_t s, const void* g) {
    asm volatile("cp.async.cg.shared.global [%0], [%1], 16;\n" :: "r"(s), "l"(g));
}
__device__ __forceinline__ void cp_commit() {
    asm volatile("cp.async.commit_group;\n");
}
template<int N>
__device__ __forceinline__ void cp_wait() {
    asm volatile("cp.async.wait_group %0;\n" :: "n"(N));
}
__device__ __forceinline__ void mma_f16(float* d, const uint32_t* a,
                                        const uint32_t* b) {
    asm volatile(
        "mma.sync.aligned.m16n8k16.row.col.f32.f16.f16.f32 "
        "{%0,%1,%2,%3}, {%4,%5,%6,%7}, {%8,%9}, {%0,%1,%2,%3};\n"
        : "+f"(d[0]), "+f"(d[1]), "+f"(d[2]), "+f"(d[3])
        : "r"(a[0]), "r"(a[1]), "r"(a[2]), "r"(a[3]), "r"(b[0]), "r"(b[1]));
}
__device__ __forceinline__ void mma_f16b(float* d, const uint32_t* a,
                                         uint32_t b0, uint32_t b1) {
    asm volatile(
        "mma.sync.aligned.m16n8k16.row.col.f32.f16.f16.f32 "
        "{%0,%1,%2,%3}, {%4,%5,%6,%7}, {%8,%9}, {%0,%1,%2,%3};\n"
        : "+f"(d[0]), "+f"(d[1]), "+f"(d[2]), "+f"(d[3])
        : "r"(a[0]), "r"(a[1]), "r"(a[2]), "r"(a[3]), "r"(b0), "r"(b1));
}
__device__ __forceinline__ void ldsm_x4(uint32_t* r, uint32_t addr) {
    asm volatile("ldmatrix.sync.aligned.m8n8.x4.shared.b16 {%0,%1,%2,%3}, [%4];\n"
        : "=r"(r[0]), "=r"(r[1]), "=r"(r[2]), "=r"(r[3]) : "r"(addr));
}
__device__ __forceinline__ void ldsm_x4_t(uint32_t* r, uint32_t addr) {
    asm volatile("ldmatrix.sync.aligned.m8n8.x4.trans.shared.b16 {%0,%1,%2,%3}, [%4];\n"
        : "=r"(r[0]), "=r"(r[1]), "=r"(r[2]), "=r"(r[3]) : "r"(addr));
}
__device__ __forceinline__ uint32_t smem_u32_of(const void* p) {
    uint32_t a;
    asm("{ .reg .u64 t; cvta.to.shared.u64 t, %1; cvt.u32.u64 %0, t; }"
        : "=r"(a) : "l"(p));
    return a;
}

// ---------------------------------------------------------------------------
// fp32 -> fp16 hi (+ optional lo residual) splits, float4 vectorized
// ---------------------------------------------------------------------------
__global__ void split_f16_v4(const float4* __restrict__ in,
                             uint2* __restrict__ hi,
                             uint2* __restrict__ lo, int n4) {
    int i = blockIdx.x * blockDim.x + threadIdx.x;
    if (i >= n4) return;
    float4 x = in[i];
    __half h0 = __float2half_rn(x.x);
    __half h1 = __float2half_rn(x.y);
    __half h2 = __float2half_rn(x.z);
    __half h3 = __float2half_rn(x.w);
    __half2 hp0 = __halves2half2(h0, h1);
    __half2 hp1 = __halves2half2(h2, h3);
    __half2 lp0 = __halves2half2(__float2half_rn(x.x - __half2float(h0)),
                                 __float2half_rn(x.y - __half2float(h1)));
    __half2 lp1 = __halves2half2(__float2half_rn(x.z - __half2float(h2)),
                                 __float2half_rn(x.w - __half2float(h3)));
    hi[i] = make_uint2(*(uint32_t*)&hp0, *(uint32_t*)&hp1);
    lo[i] = make_uint2(*(uint32_t*)&lp0, *(uint32_t*)&lp1);
}
__global__ void tof16_v4(const float4* __restrict__ in,
                         uint2* __restrict__ hi, int n4) {
    int i = blockIdx.x * blockDim.x + threadIdx.x;
    if (i >= n4) return;
    float4 x = in[i];
    __half2 hp0 = __halves2half2(__float2half_rn(x.x), __float2half_rn(x.y));
    __half2 hp1 = __halves2half2(__float2half_rn(x.z), __float2half_rn(x.w));
    hi[i] = make_uint2(*(uint32_t*)&hp0, *(uint32_t*)&hp1);
}

// ---------------------------------------------------------------------------
// fp16x2 tensor-core GEMM: C = A_h @ (B_h + B_l)^T, fp32 accumulate.
// BM=128 BN=64 BK=32, 8 warps (4x2), warp tile 32x32, 3-stage cp.async,
// 20.5KB/stage -> 61.5KB smem -> 3 CTAs/SM.
// ---------------------------------------------------------------------------
#define BM 128
#define BN 64
#define BK 32
#define SROW 40
#define A_ELE (128 * SROW)                 // halfs per A buffer
#define B_ELE (64 * SROW)                  // halfs per B buffer
#define STAGE_E (A_ELE + 2 * B_ELE)        // 10240 halfs
#define GEMM_SMEM (3 * STAGE_E * 2)        // 61440 bytes

__global__ void __launch_bounds__(256, 3)
gemm_f16x2(const __half* __restrict__ Ah,
           const __half* __restrict__ Bh,
           const __half* __restrict__ Bl,
           float* __restrict__ C, int M, int N, int K) {
    extern __shared__ __half smem[];
    const int tid  = threadIdx.x;
    const int warp = tid >> 5;
    const int lane = tid & 31;
    const int wm   = warp >> 1;        // 0..3
    const int wn   = warp & 1;         // 0..1
    const int g    = lane >> 2;        // 0..7
    const int t    = lane & 3;         // 0..3
    const int row0 = blockIdx.y * BM;
    const int col0 = blockIdx.x * BN;

    uint32_t smem_b = smem_u32_of(smem);

    float acc[2][4][4];
#pragma unroll
    for (int i = 0; i < 2; i++)
#pragma unroll
        for (int j = 0; j < 4; j++)
#pragma unroll
            for (int k = 0; k < 4; k++) acc[i][j][k] = 0.f;

    const int NIT = K / BK;   // 64

    auto load_stage = [&](int stage, int k0) {
        uint32_t sb = smem_b + stage * (STAGE_E * 2);
        // A_h: 512 chunks, 2 per thread
#pragma unroll
        for (int p = 0; p < 2; p++) {
            int c   = tid + p * 256;
            int row = c >> 2;
            int cc  = c & 3;
            uint32_t so = sb + row * (SROW * 2) + cc * 16;
            cp16(so, Ah + (size_t)(row0 + row) * K + k0 + cc * 8);
        }
        // B_h/B_l: 256 chunks each, 1 per thread
        {
            int row = tid >> 2;
            int cc  = tid & 3;
            uint32_t so = sb + A_ELE * 2 + row * (SROW * 2) + cc * 16;
            size_t gb = (size_t)(col0 + row) * K + k0 + cc * 8;
            cp16(so,             Bh + gb);
            cp16(so + B_ELE * 2, Bl + gb);
        }
        cp_commit();
    };

    load_stage(0, 0);
    load_stage(1, BK);

    for (int it = 0; it < NIT; it++) {
        if (it + 2 < NIT) { cp_wait<1>(); } else { cp_wait<0>(); }
        __syncthreads();
        if (it + 2 < NIT) load_stage((it + 2) % 3, (it + 2) * BK);

        const __half* As = smem + (it % 3) * STAGE_E;
        const __half* Bs = As + A_ELE;
        const __half* Bq = Bs + B_ELE;

#pragma unroll
        for (int ks = 0; ks < 2; ks++) {
            uint32_t ah[2][4], bh[4][2], bl[4][2];
#pragma unroll
            for (int mt = 0; mt < 2; mt++) {
                int rb = wm * 32 + mt * 16;
                const __half* pa = As + (rb + g) * SROW + ks * 16 + 2 * t;
                ah[mt][0] = *(const uint32_t*)(pa);
                ah[mt][1] = *(const uint32_t*)(pa + 8 * SROW);
                ah[mt][2] = *(const uint32_t*)(pa + 8);
                ah[mt][3] = *(const uint32_t*)(pa + 8 * SROW + 8);
            }
#pragma unroll
            for (int nt = 0; nt < 4; nt++) {
                int cb = wn * 32 + nt * 8;
                const __half* pb = Bs + (cb + g) * SROW + ks * 16 + 2 * t;
                const __half* pq = Bq + (cb + g) * SROW + ks * 16 + 2 * t;
                bh[nt][0] = *(const uint32_t*)(pb);
                bh[nt][1] = *(const uint32_t*)(pb + 8);
                bl[nt][0] = *(const uint32_t*)(pq);
                bl[nt][1] = *(const uint32_t*)(pq + 8);
            }
            // term-major: same-accumulator reuse distance = 8 MMAs
#pragma unroll
            for (int mt = 0; mt < 2; mt++)
#pragma unroll
                for (int nt = 0; nt < 4; nt++)
                    mma_f16b(acc[mt][nt], ah[mt], bh[nt][0], bh[nt][1]);
#pragma unroll
            for (int mt = 0; mt < 2; mt++)
#pragma unroll
                for (int nt = 0; nt < 4; nt++)
                    mma_f16b(acc[mt][nt], ah[mt], bl[nt][0], bl[nt][1]);
        }
    }

#pragma unroll
    for (int mt = 0; mt < 2; mt++) {
        int r = row0 + wm * 32 + mt * 16 + g;
#pragma unroll
        for (int nt = 0; nt < 4; nt++) {
            int c = col0 + wn * 32 + nt * 8 + 2 * t;
            float2 v0 = make_float2(acc[mt][nt][0], acc[mt][nt][1]);
            float2 v1 = make_float2(acc[mt][nt][2], acc[mt][nt][3]);
            *(float2*)&C[(size_t)r * N + c]       = v0;
            *(float2*)&C[(size_t)(r + 8) * N + c] = v1;
        }
    }
}

// ---------------------------------------------------------------------------
// RoPE + fp16 split: g_qkv -> head-major q (hi only) / k,v (hi+lo)
// ---------------------------------------------------------------------------
__global__ void rope_split() {
    int idx = blockIdx.x * blockDim.x + threadIdx.x;
    const int total = SEQ * 40 * 32;
    if (idx >= total) return;
    int pair = idx & 31;
    int head = (idx >> 5) % 40;
    int s    = idx / (40 * 32);

    const float* base = g_qkv + (size_t)s * QKV_COLS + head * DHEAD;
    float x1 = base[pair];
    float x2 = base[pair + 32];
    float y1, y2;
    if (head < 36) {
        float inv_freq = __expf(-(float)pair * (9.210340371976184f / 32.0f));
        float ang = (float)s * inv_freq;
        float sn, cs;
        sincosf(ang, &sn, &cs);
        y1 = x1 * cs - x2 * sn;
        y2 = x2 * cs + x1 * sn;
    } else {
        y1 = x1; y2 = x2;
    }

    if (head < 32) {
        y1 *= 0.125f; y2 *= 0.125f;
        size_t off = ((size_t)head * SEQ + s) * DHEAD;
        g_q_h[off + pair]      = __float2half_rn(y1);
        g_q_h[off + pair + 32] = __float2half_rn(y2);
    } else {
        __half *dh, *dl;
        size_t off;
        if (head < 36) {
            off = ((size_t)(head - 32) * SEQ + s) * DHEAD;
            dh = g_k_h; dl = g_k_l;
        } else {
            off = ((size_t)(head - 36) * SEQ + s) * DHEAD;
            dh = g_v_h; dl = g_v_l;
        }
        __half h1 = __float2half_rn(y1);
        __half h2 = __float2half_rn(y2);
        dh[off + pair]      = h1;
        dh[off + pair + 32] = h2;
        dl[off + pair]      = __float2half_rn(y1 - __half2float(h1));
        dl[off + pair + 32] = __float2half_rn(y2 - __half2float(h2));
    }
}

// ---------------------------------------------------------------------------
// Tensor-core flash attention (fp16x2), causal, GQA. kk-outer ordering.
// smem arrays: 0:Qh 1:Kh 2:Kl 3:Vh 4:Vl
// ---------------------------------------------------------------------------
#define FSTRIDE 72
#define FTILE (64 * FSTRIDE)
#define FA_SMEM (5 * FTILE * 2)    // 46080 bytes

__global__ void __launch_bounds__(128)
flash_attn_tc() {
    extern __shared__ __half fsm[];
    uint32_t sbase = smem_u32_of(fsm);

    const int head = blockIdx.x;
    const int qb   = gridDim.y - 1 - blockIdx.y;
    const int tid  = threadIdx.x;
    const int w    = tid >> 5;
    const int lane = tid & 31;
    const int kvh  = head >> 3;
    const int r8   = lane & 7;
    const int sub  = lane >> 3;

    // ---- load Q tile (hi only): 512 chunks, 4 per thread ----
    {
        const __half* gq = g_q_h + ((size_t)head * SEQ + qb * 64) * DHEAD;
#pragma unroll
        for (int i = 0; i < 4; i++) {
            int c   = tid + i * 128;
            int row = c >> 3;
            int ch  = c & 7;
            cp16(sbase + row * 144 + ch * 16, gq + row * DHEAD + ch * 8);
        }
        cp_commit(); cp_wait<0>();
        __syncthreads();
    }

    uint32_t qh[4][4];
#pragma unroll
    for (int kk = 0; kk < 4; kk++) {
        uint32_t addr = sbase
            + (w * 16 + r8 + ((sub & 1) << 3)) * 144
            + kk * 32 + ((sub & 2) << 3);
        ldsm_x4(qh[kk], addr);
    }

    float of[8][4];
#pragma unroll
    for (int f = 0; f < 8; f++)
#pragma unroll
        for (int j = 0; j < 4; j++) of[f][j] = 0.f;
    float m0 = -1e30f, m1 = -1e30f, l0 = 0.f, l1 = 0.f;

    const uint32_t sK = sbase + 1 * (FTILE * 2);
    const uint32_t sV = sbase + 3 * (FTILE * 2);

    for (int kb = 0; kb <= qb; kb++) {
        __syncthreads();
        {
            const size_t go = ((size_t)kvh * SEQ + kb * 64) * DHEAD;
#pragma unroll
            for (int i = 0; i < 16; i++) {
                int c   = tid + i * 128;   // 2048 chunks
                int arr = c >> 9;          // 0:Kh 1:Kl 2:Vh 3:Vl
                int rem = c & 511;
                int row = rem >> 3;
                int ch  = rem & 7;
                uint32_t dst = sbase + (1 + arr) * (FTILE * 2) + row * 144 + ch * 16;
                const __half* src;
                if      (arr == 0) src = g_k_h + go;
                else if (arr == 1) src = g_k_l + go;
                else if (arr == 2) src = g_v_h + go;
                else               src = g_v_l + go;
                src += row * DHEAD + ch * 8;
                cp16(dst, src);
            }
            cp_commit(); cp_wait<0>();
            __syncthreads();
        }

        // ---- S = Q K^T (fp16x2), kk-outer ----
        float sf[8][4];
#pragma unroll
        for (int f = 0; f < 8; f++)
#pragma unroll
            for (int j = 0; j < 4; j++) sf[f][j] = 0.f;

#pragma unroll
        for (int kk = 0; kk < 4; kk++) {
            uint32_t bh[4][4], bl[4][4];
#pragma unroll
            for (int p = 0; p < 4; p++) {
                uint32_t addr = sK
                    + (p * 16 + ((sub & 2) << 2) + r8) * 144
                    + kk * 32 + ((sub & 1) << 4);
                ldsm_x4(bh[p], addr);
                ldsm_x4(bl[p], addr + FTILE * 2);
            }
#pragma unroll
            for (int p = 0; p < 4; p++) {
                mma_f16(sf[2 * p],     qh[kk], &bh[p][0]);
                mma_f16(sf[2 * p + 1], qh[kk], &bh[p][2]);
            }
#pragma unroll
            for (int p = 0; p < 4; p++) {
                mma_f16(sf[2 * p],     qh[kk], &bl[p][0]);
                mma_f16(sf[2 * p + 1], qh[kk], &bl[p][2]);
            }
        }

        if (kb == qb) {
            int rt0 = w * 16 + (lane >> 2);
#pragma unroll
            for (int f = 0; f < 8; f++) {
                int ct = 8 * f + 2 * (lane & 3);
                if (ct > rt0)         sf[f][0] = -1e30f;
                if (ct + 1 > rt0)     sf[f][1] = -1e30f;
                if (ct > rt0 + 8)     sf[f][2] = -1e30f;
                if (ct + 1 > rt0 + 8) sf[f][3] = -1e30f;
            }
        }

        float c0 = -1e30f, c1 = -1e30f;
#pragma unroll
        for (int f = 0; f < 8; f++) {
            c0 = fmaxf(c0, fmaxf(sf[f][0], sf[f][1]));
            c1 = fmaxf(c1, fmaxf(sf[f][2], sf[f][3]));
        }
        c0 = fmaxf(c0, __shfl_xor_sync(0xffffffffu, c0, 1));
        c0 = fmaxf(c0, __shfl_xor_sync(0xffffffffu, c0, 2));
        c1 = fmaxf(c1, __shfl_xor_sync(0xffffffffu, c1, 1));
        c1 = fmaxf(c1, __shfl_xor_sync(0xffffffffu, c1, 2));

        float mn0 = fmaxf(m0, c0), mn1 = fmaxf(m1, c1);
        float a0 = __expf(m0 - mn0), a1 = __expf(m1 - mn1);
        m0 = mn0; m1 = mn1;

        float s0 = 0.f, s1 = 0.f;
#pragma unroll
        for (int f = 0; f < 8; f++) {
            sf[f][0] = __expf(sf[f][0] - mn0);
            sf[f][1] = __expf(sf[f][1] - mn0);
            sf[f][2] = __expf(sf[f][2] - mn1);
            sf[f][3] = __expf(sf[f][3] - mn1);
            s0 += sf[f][0] + sf[f][1];
            s1 += sf[f][2] + sf[f][3];
        }
        s0 += __shfl_xor_sync(0xffffffffu, s0, 1);
        s0 += __shfl_xor_sync(0xffffffffu, s0, 2);
        s1 += __shfl_xor_sync(0xffffffffu, s1, 1);
        s1 += __shfl_xor_sync(0xffffffffu, s1, 2);
        l0 = l0 * a0 + s0;
        l1 = l1 * a1 + s1;

#pragma unroll
        for (int f = 0; f < 8; f++) {
            of[f][0] *= a0; of[f][1] *= a0;
            of[f][2] *= a1; of[f][3] *= a1;
        }

        // ---- P -> fp16 A fragments (hi only) ----
        uint32_t ph[4][4];
#pragma unroll
        for (int kk = 0; kk < 4; kk++) {
#pragma unroll
            for (int half4 = 0; half4 < 4; half4++) {
                int f = 2 * kk + (half4 >> 1);
                int j = (half4 & 1) * 2;
                __half2 hp = __halves2half2(__float2half_rn(sf[f][j]),
                                            __float2half_rn(sf[f][j + 1]));
                int slot = (half4 >> 1) * 2 + (half4 & 1);
                ph[kk][slot] = *(uint32_t*)&hp;
            }
        }

        // ---- O += P (V_h + V_l), kk-outer ----
#pragma unroll
        for (int kk = 0; kk < 4; kk++) {
            uint32_t vh[4][4], vl[4][4];
#pragma unroll
            for (int p = 0; p < 4; p++) {
                uint32_t addr = sV
                    + (kk * 16 + ((sub & 1) << 3) + r8) * 144
                    + p * 32 + ((sub & 2) << 3);
                ldsm_x4_t(vh[p], addr);
                ldsm_x4_t(vl[p], addr + FTILE * 2);
            }
#pragma unroll
            for (int p = 0; p < 4; p++) {
                mma_f16(of[2 * p],     ph[kk], &vh[p][0]);
                mma_f16(of[2 * p + 1], ph[kk], &vh[p][2]);
            }
#pragma unroll
            for (int p = 0; p < 4; p++) {
                mma_f16(of[2 * p],     ph[kk], &vl[p][0]);
                mma_f16(of[2 * p + 1], ph[kk], &vl[p][2]);
            }
        }
    }

    // ---- normalize + write fp16 hi ----
    float inv0 = 1.0f / l0, inv1 = 1.0f / l1;
    int rq = qb * 64 + w * 16 + (lane >> 2);
    int cb = head * DHEAD + 2 * (lane & 3);
#pragma unroll
    for (int f = 0; f < 8; f++) {
        int col = cb + 8 * f;
        __half2 hp0 = __halves2half2(__float2half_rn(of[f][0] * inv0),
                                     __float2half_rn(of[f][1] * inv0));
        __half2 hp1 = __halves2half2(__float2half_rn(of[f][2] * inv1),
                                     __float2half_rn(of[f][3] * inv1));
        *(uint32_t*)&g_at_h[(size_t)rq * HID + col]       = *(uint32_t*)&hp0;
        *(uint32_t*)&g_at_h[(size_t)(rq + 8) * HID + col] = *(uint32_t*)&hp1;
    }
}

// ---------------------------------------------------------------------------
extern "C" void kernel_launch(void* const* d_in, const int* in_sizes, int n_in,
                              void* d_out, int out_size) {
    const float* hidden = (const float*)d_in[0];
    const float* w_qkv  = (const float*)d_in[1];
    const float* w_o    = (const float*)d_in[2];
    float*       out    = (float*)d_out;

    float* qkv_ptr = nullptr;
    cudaGetSymbolAddress((void**)&qkv_ptr, g_qkv);
    __half *hid_h, *wq_h, *wq_l, *wo_h, *wo_l, *at_h;
    cudaGetSymbolAddress((void**)&hid_h, g_hid_h);
    cudaGetSymbolAddress((void**)&wq_h,  g_wq_h);
    cudaGetSymbolAddress((void**)&wq_l,  g_wq_l);
    cudaGetSymbolAddress((void**)&wo_h,  g_wo_h);
    cudaGetSymbolAddress((void**)&wo_l,  g_wo_l);
    cudaGetSymbolAddress((void**)&at_h,  g_at_h);

    cudaFuncSetAttribute(gemm_f16x2,
                         cudaFuncAttributeMaxDynamicSharedMemorySize, GEMM_SMEM);
    cudaFuncSetAttribute(flash_attn_tc,
                         cudaFuncAttributeMaxDynamicSharedMemorySize, FA_SMEM);

    tof16_v4<<<(SEQ * HID / 4 + 255) / 256, 256>>>(
        (const float4*)hidden, (uint2*)hid_h, SEQ * HID / 4);
    split_f16_v4<<<(QKV_COLS * HID / 4 + 255) / 256, 256>>>(
        (const float4*)w_qkv, (uint2*)wq_h, (uint2*)wq_l, QKV_COLS * HID / 4);
    split_f16_v4<<<(HID * HID / 4 + 255) / 256, 256>>>(
        (const float4*)w_o, (uint2*)wo_h, (uint2*)wo_l, HID * HID / 4);

    // 1) QKV projection
    gemm_f16x2<<<dim3(QKV_COLS / BN, SEQ / BM), 256, GEMM_SMEM>>>(
        hid_h, wq_h, wq_l, qkv_ptr, SEQ, QKV_COLS, HID);

    // 2) RoPE + fp16 split into head-major q/k/v
    {
        int total = SEQ * 40 * 32;
        rope_split<<<(total + 255) / 256, 256>>>();
    }

    // 3) tensor-core causal GQA flash attention
    flash_attn_tc<<<dim3(NQH, SEQ / 64), 128, FA_SMEM>>>();

    // 4) output projection
    gemm_f16x2<<<dim3(HID / BN, SEQ / BM), 256, GEMM_SMEM>>>(
        at_h, wo_h, wo_l, out, SEQ, HID, HID);
}

// round 9
// speedup vs baseline: 1.6117x; 1.0456x over previous
#include <cuda_runtime.h>
#include <cuda_fp16.h>
#include <math.h>
#include <float.h>
#include <stdint.h>

#define SEQ    2048
#define HID    2048
#define DHEAD  64
#define NQH    32
#define NKVH   4
#define QKV_COLS 2560   // (32 + 4 + 4) * 64

// ---------------- scratch (no cudaMalloc allowed) ----------------
__device__ float g_qkv [SEQ * QKV_COLS];

__device__ __half g_hid_h[SEQ * HID];
__device__ __half g_wq_h [QKV_COLS * HID];
__device__ __half g_wq_l [QKV_COLS * HID];
__device__ __half g_wo_h [HID * HID];
__device__ __half g_wo_l [HID * HID];
__device__ __half g_at_h [SEQ * HID];

__device__ __half g_q_h[NQH  * SEQ * DHEAD];
__device__ __half g_k_h[NKVH * SEQ * DHEAD];
__device__ __half g_k_l[NKVH * SEQ * DHEAD];
__device__ __half g_v_h[NKVH * SEQ * DHEAD];
__device__ __half g_v_l[NKVH * SEQ * DHEAD];

// ---------------------------------------------------------------------------
// helpers
// ---------------------------------------------------------------------------
__device__ __forceinline__ void cp16(uint32_t s, const void* g) {
    asm volatile("cp.async.cg.shared.global [%0], [%1], 16;\n" :: "r"(s), "l"(g));
}
__device__ __forceinline__ void cp_commit() {
    asm volatile("cp.async.commit_group;\n");
}
template<int N>
__device__ __forceinline__ void cp_wait() {
    asm volatile("cp.async.wait_group %0;\n" :: "n"(N));
}
__device__ __forceinline__ void mma_f16(float* d, const uint32_t* a,
                                        const uint32_t* b) {
    asm volatile(
        "mma.sync.aligned.m16n8k16.row.col.f32.f16.f16.f32 "
        "{%0,%1,%2,%3}, {%4,%5,%6,%7}, {%8,%9}, {%0,%1,%2,%3};\n"
        : "+f"(d[0]), "+f"(d[1]), "+f"(d[2]), "+f"(d[3])
        : "r"(a[0]), "r"(a[1]), "r"(a[2]), "r"(a[3]), "r"(b[0]), "r"(b[1]));
}
__device__ __forceinline__ void mma_f16b(float* d, const uint32_t* a,
                                         uint32_t b0, uint32_t b1) {
    asm volatile(
        "mma.sync.aligned.m16n8k16.row.col.f32.f16.f16.f32 "
        "{%0,%1,%2,%3}, {%4,%5,%6,%7}, {%8,%9}, {%0,%1,%2,%3};\n"
        : "+f"(d[0]), "+f"(d[1]), "+f"(d[2]), "+f"(d[3])
        : "r"(a[0]), "r"(a[1]), "r"(a[2]), "r"(a[3]), "r"(b0), "r"(b1));
}
__device__ __forceinline__ void ldsm_x4(uint32_t* r, uint32_t addr) {
    asm volatile("ldmatrix.sync.aligned.m8n8.x4.shared.b16 {%0,%1,%2,%3}, [%4];\n"
        : "=r"(r[0]), "=r"(r[1]), "=r"(r[2]), "=r"(r[3]) : "r"(addr));
}
__device__ __forceinline__ void ldsm_x4_t(uint32_t* r, uint32_t addr) {
    asm volatile("ldmatrix.sync.aligned.m8n8.x4.trans.shared.b16 {%0,%1,%2,%3}, [%4];\n"
        : "=r"(r[0]), "=r"(r[1]), "=r"(r[2]), "=r"(r[3]) : "r"(addr));
}
__device__ __forceinline__ uint32_t smem_u32_of(const void* p) {
    uint32_t a;
    asm("{ .reg .u64 t; cvta.to.shared.u64 t, %1; cvt.u32.u64 %0, t; }"
        : "=r"(a) : "l"(p));
    return a;
}

// ---------------------------------------------------------------------------
// fp32 -> fp16 hi (+ optional lo residual) splits, float4 vectorized
// ---------------------------------------------------------------------------
__global__ void split_f16_v4(const float4* __restrict__ in,
                             uint2* __restrict__ hi,
                             uint2* __restrict__ lo, int n4) {
    int i = blockIdx.x * blockDim.x + threadIdx.x;
    if (i >= n4) return;
    float4 x = in[i];
    __half h0 = __float2half_rn(x.x);
    __half h1 = __float2half_rn(x.y);
    __half h2 = __float2half_rn(x.z);
    __half h3 = __float2half_rn(x.w);
    __half2 hp0 = __halves2half2(h0, h1);
    __half2 hp1 = __halves2half2(h2, h3);
    __half2 lp0 = __halves2half2(__float2half_rn(x.x - __half2float(h0)),
                                 __float2half_rn(x.y - __half2float(h1)));
    __half2 lp1 = __halves2half2(__float2half_rn(x.z - __half2float(h2)),
                                 __float2half_rn(x.w - __half2float(h3)));
    hi[i] = make_uint2(*(uint32_t*)&hp0, *(uint32_t*)&hp1);
    lo[i] = make_uint2(*(uint32_t*)&lp0, *(uint32_t*)&lp1);
}
__global__ void tof16_v4(const float4* __restrict__ in,
                         uint2* __restrict__ hi, int n4) {
    int i = blockIdx.x * blockDim.x + threadIdx.x;
    if (i >= n4) return;
    float4 x = in[i];
    __half2 hp0 = __halves2half2(__float2half_rn(x.x), __float2half_rn(x.y));
    __half2 hp1 = __halves2half2(__float2half_rn(x.z), __float2half_rn(x.w));
    hi[i] = make_uint2(*(uint32_t*)&hp0, *(uint32_t*)&hp1);
}

// ---------------------------------------------------------------------------
// fp16 tensor-core GEMM with per-CTA term count:
// columns >= n2start use 2 terms (B_h + B_l); columns < n2start use 1 term.
// BM=128 BN=64 BK=32, 8 warps (4x2), warp tile 32x32, 3-stage cp.async.
// ---------------------------------------------------------------------------
#define BM 128
#define BN 64
#define BK 32
#define SROW 40
#define A_ELE (128 * SROW)
#define B_ELE (64 * SROW)
#define STAGE_E (A_ELE + 2 * B_ELE)        // 10240 halfs
#define GEMM_SMEM (3 * STAGE_E * 2)        // 61440 bytes

__global__ void __launch_bounds__(256, 3)
gemm_f16x2(const __half* __restrict__ Ah,
           const __half* __restrict__ Bh,
           const __half* __restrict__ Bl,
           float* __restrict__ C, int M, int N, int K, int n2start) {
    extern __shared__ __half smem[];
    const int tid  = threadIdx.x;
    const int warp = tid >> 5;
    const int lane = tid & 31;
    const int wm   = warp >> 1;
    const int wn   = warp & 1;
    const int g    = lane >> 2;
    const int t    = lane & 3;
    const int row0 = blockIdx.y * BM;
    const int col0 = blockIdx.x * BN;
    const bool use2 = (col0 >= n2start);   // uniform per CTA

    uint32_t smem_b = smem_u32_of(smem);

    float acc[2][4][4];
#pragma unroll
    for (int i = 0; i < 2; i++)
#pragma unroll
        for (int j = 0; j < 4; j++)
#pragma unroll
            for (int k = 0; k < 4; k++) acc[i][j][k] = 0.f;

    const int NIT = K / BK;   // 64

    auto load_stage = [&](int stage, int k0) {
        uint32_t sb = smem_b + stage * (STAGE_E * 2);
#pragma unroll
        for (int p = 0; p < 2; p++) {
            int c   = tid + p * 256;
            int row = c >> 2;
            int cc  = c & 3;
            uint32_t so = sb + row * (SROW * 2) + cc * 16;
            cp16(so, Ah + (size_t)(row0 + row) * K + k0 + cc * 8);
        }
        {
            int row = tid >> 2;
            int cc  = tid & 3;
            uint32_t so = sb + A_ELE * 2 + row * (SROW * 2) + cc * 16;
            size_t gb = (size_t)(col0 + row) * K + k0 + cc * 8;
            cp16(so, Bh + gb);
            if (use2) cp16(so + B_ELE * 2, Bl + gb);
        }
        cp_commit();
    };

    load_stage(0, 0);
    load_stage(1, BK);

    for (int it = 0; it < NIT; it++) {
        if (it + 2 < NIT) { cp_wait<1>(); } else { cp_wait<0>(); }
        __syncthreads();
        if (it + 2 < NIT) load_stage((it + 2) % 3, (it + 2) * BK);

        const __half* As = smem + (it % 3) * STAGE_E;
        const __half* Bs = As + A_ELE;
        const __half* Bq = Bs + B_ELE;

#pragma unroll
        for (int ks = 0; ks < 2; ks++) {
            uint32_t ah[2][4], bh[4][2], bl[4][2];
#pragma unroll
            for (int mt = 0; mt < 2; mt++) {
                int rb = wm * 32 + mt * 16;
                const __half* pa = As + (rb + g) * SROW + ks * 16 + 2 * t;
                ah[mt][0] = *(const uint32_t*)(pa);
                ah[mt][1] = *(const uint32_t*)(pa + 8 * SROW);
                ah[mt][2] = *(const uint32_t*)(pa + 8);
                ah[mt][3] = *(const uint32_t*)(pa + 8 * SROW + 8);
            }
#pragma unroll
            for (int nt = 0; nt < 4; nt++) {
                int cb = wn * 32 + nt * 8;
                const __half* pb = Bs + (cb + g) * SROW + ks * 16 + 2 * t;
                bh[nt][0] = *(const uint32_t*)(pb);
                bh[nt][1] = *(const uint32_t*)(pb + 8);
            }
            if (use2) {
#pragma unroll
                for (int nt = 0; nt < 4; nt++) {
                    int cb = wn * 32 + nt * 8;
                    const __half* pq = Bq + (cb + g) * SROW + ks * 16 + 2 * t;
                    bl[nt][0] = *(const uint32_t*)(pq);
                    bl[nt][1] = *(const uint32_t*)(pq + 8);
                }
            }
#pragma unroll
            for (int mt = 0; mt < 2; mt++)
#pragma unroll
                for (int nt = 0; nt < 4; nt++)
                    mma_f16b(acc[mt][nt], ah[mt], bh[nt][0], bh[nt][1]);
            if (use2) {
#pragma unroll
                for (int mt = 0; mt < 2; mt++)
#pragma unroll
                    for (int nt = 0; nt < 4; nt++)
                        mma_f16b(acc[mt][nt], ah[mt], bl[nt][0], bl[nt][1]);
            }
        }
    }

#pragma unroll
    for (int mt = 0; mt < 2; mt++) {
        int r = row0 + wm * 32 + mt * 16 + g;
#pragma unroll
        for (int nt = 0; nt < 4; nt++) {
            int c = col0 + wn * 32 + nt * 8 + 2 * t;
            float2 v0 = make_float2(acc[mt][nt][0], acc[mt][nt][1]);
            float2 v1 = make_float2(acc[mt][nt][2], acc[mt][nt][3]);
            *(float2*)&C[(size_t)r * N + c]       = v0;
            *(float2*)&C[(size_t)(r + 8) * N + c] = v1;
        }
    }
}

// ---------------------------------------------------------------------------
// RoPE + fp16 split: g_qkv -> head-major q (hi only) / k,v (hi+lo)
// ---------------------------------------------------------------------------
__global__ void rope_split() {
    int idx = blockIdx.x * blockDim.x + threadIdx.x;
    const int total = SEQ * 40 * 32;
    if (idx >= total) return;
    int pair = idx & 31;
    int head = (idx >> 5) % 40;
    int s    = idx / (40 * 32);

    const float* base = g_qkv + (size_t)s * QKV_COLS + head * DHEAD;
    float x1 = base[pair];
    float x2 = base[pair + 32];
    float y1, y2;
    if (head < 36) {
        float inv_freq = __expf(-(float)pair * (9.210340371976184f / 32.0f));
        float ang = (float)s * inv_freq;
        float sn, cs;
        sincosf(ang, &sn, &cs);
        y1 = x1 * cs - x2 * sn;
        y2 = x2 * cs + x1 * sn;
    } else {
        y1 = x1; y2 = x2;
    }

    if (head < 32) {
        y1 *= 0.125f; y2 *= 0.125f;
        size_t off = ((size_t)head * SEQ + s) * DHEAD;
        g_q_h[off + pair]      = __float2half_rn(y1);
        g_q_h[off + pair + 32] = __float2half_rn(y2);
    } else {
        __half *dh, *dl;
        size_t off;
        if (head < 36) {
            off = ((size_t)(head - 32) * SEQ + s) * DHEAD;
            dh = g_k_h; dl = g_k_l;
        } else {
            off = ((size_t)(head - 36) * SEQ + s) * DHEAD;
            dh = g_v_h; dl = g_v_l;
        }
        __half h1 = __float2half_rn(y1);
        __half h2 = __float2half_rn(y2);
        dh[off + pair]      = h1;
        dh[off + pair + 32] = h2;
        dl[off + pair]      = __float2half_rn(y1 - __half2float(h1));
        dl[off + pair + 32] = __float2half_rn(y2 - __half2float(h2));
    }
}

// ---------------------------------------------------------------------------
// Tensor-core flash attention (fp16x2), causal, GQA. kk-outer ordering.
// smem arrays: 0:Qh 1:Kh 2:Kl 3:Vh 4:Vl
// ---------------------------------------------------------------------------
#define FSTRIDE 72
#define FTILE (64 * FSTRIDE)
#define FA_SMEM (5 * FTILE * 2)    // 46080 bytes

__global__ void __launch_bounds__(128)
flash_attn_tc() {
    extern __shared__ __half fsm[];
    uint32_t sbase = smem_u32_of(fsm);

    const int head = blockIdx.x;
    const int qb   = gridDim.y - 1 - blockIdx.y;
    const int tid  = threadIdx.x;
    const int w    = tid >> 5;
    const int lane = tid & 31;
    const int kvh  = head >> 3;
    const int r8   = lane & 7;
    const int sub  = lane >> 3;

    {
        const __half* gq = g_q_h + ((size_t)head * SEQ + qb * 64) * DHEAD;
#pragma unroll
        for (int i = 0; i < 4; i++) {
            int c   = tid + i * 128;
            int row = c >> 3;
            int ch  = c & 7;
            cp16(sbase + row * 144 + ch * 16, gq + row * DHEAD + ch * 8);
        }
        cp_commit(); cp_wait<0>();
        __syncthreads();
    }

    uint32_t qh[4][4];
#pragma unroll
    for (int kk = 0; kk < 4; kk++) {
        uint32_t addr = sbase
            + (w * 16 + r8 + ((sub & 1) << 3)) * 144
            + kk * 32 + ((sub & 2) << 3);
        ldsm_x4(qh[kk], addr);
    }

    float of[8][4];
#pragma unroll
    for (int f = 0; f < 8; f++)
#pragma unroll
        for (int j = 0; j < 4; j++) of[f][j] = 0.f;
    float m0 = -1e30f, m1 = -1e30f, l0 = 0.f, l1 = 0.f;

    const uint32_t sK = sbase + 1 * (FTILE * 2);
    const uint32_t sV = sbase + 3 * (FTILE * 2);

    for (int kb = 0; kb <= qb; kb++) {
        __syncthreads();
        {
            const size_t go = ((size_t)kvh * SEQ + kb * 64) * DHEAD;
#pragma unroll
            for (int i = 0; i < 16; i++) {
                int c   = tid + i * 128;
                int arr = c >> 9;
                int rem = c & 511;
                int row = rem >> 3;
                int ch  = rem & 7;
                uint32_t dst = sbase + (1 + arr) * (FTILE * 2) + row * 144 + ch * 16;
                const __half* src;
                if      (arr == 0) src = g_k_h + go;
                else if (arr == 1) src = g_k_l + go;
                else if (arr == 2) src = g_v_h + go;
                else               src = g_v_l + go;
                src += row * DHEAD + ch * 8;
                cp16(dst, src);
            }
            cp_commit(); cp_wait<0>();
            __syncthreads();
        }

        float sf[8][4];
#pragma unroll
        for (int f = 0; f < 8; f++)
#pragma unroll
            for (int j = 0; j < 4; j++) sf[f][j] = 0.f;

#pragma unroll
        for (int kk = 0; kk < 4; kk++) {
            uint32_t bh[4][4], bl[4][4];
#pragma unroll
            for (int p = 0; p < 4; p++) {
                uint32_t addr = sK
                    + (p * 16 + ((sub & 2) << 2) + r8) * 144
                    + kk * 32 + ((sub & 1) << 4);
                ldsm_x4(bh[p], addr);
                ldsm_x4(bl[p], addr + FTILE * 2);
            }
#pragma unroll
            for (int p = 0; p < 4; p++) {
                mma_f16(sf[2 * p],     qh[kk], &bh[p][0]);
                mma_f16(sf[2 * p + 1], qh[kk], &bh[p][2]);
            }
#pragma unroll
            for (int p = 0; p < 4; p++) {
                mma_f16(sf[2 * p],     qh[kk], &bl[p][0]);
                mma_f16(sf[2 * p + 1], qh[kk], &bl[p][2]);
            }
        }

        if (kb == qb) {
            int rt0 = w * 16 + (lane >> 2);
#pragma unroll
            for (int f = 0; f < 8; f++) {
                int ct = 8 * f + 2 * (lane & 3);
                if (ct > rt0)         sf[f][0] = -1e30f;
                if (ct + 1 > rt0)     sf[f][1] = -1e30f;
                if (ct > rt0 + 8)     sf[f][2] = -1e30f;
                if (ct + 1 > rt0 + 8) sf[f][3] = -1e30f;
            }
        }

        float c0 = -1e30f, c1 = -1e30f;
#pragma unroll
        for (int f = 0; f < 8; f++) {
            c0 = fmaxf(c0, fmaxf(sf[f][0], sf[f][1]));
            c1 = fmaxf(c1, fmaxf(sf[f][2], sf[f][3]));
        }
        c0 = fmaxf(c0, __shfl_xor_sync(0xffffffffu, c0, 1));
        c0 = fmaxf(c0, __shfl_xor_sync(0xffffffffu, c0, 2));
        c1 = fmaxf(c1, __shfl_xor_sync(0xffffffffu, c1, 1));
        c1 = fmaxf(c1, __shfl_xor_sync(0xffffffffu, c1, 2));

        float mn0 = fmaxf(m0, c0), mn1 = fmaxf(m1, c1);
        float a0 = __expf(m0 - mn0), a1 = __expf(m1 - mn1);
        m0 = mn0; m1 = mn1;

        float s0 = 0.f, s1 = 0.f;
#pragma unroll
        for (int f = 0; f < 8; f++) {
            sf[f][0] = __expf(sf[f][0] - mn0);
            sf[f][1] = __expf(sf[f][1] - mn0);
            sf[f][2] = __expf(sf[f][2] - mn1);
            sf[f][3] = __expf(sf[f][3] - mn1);
            s0 += sf[f][0] + sf[f][1];
            s1 += sf[f][2] + sf[f][3];
        }
        s0 += __shfl_xor_sync(0xffffffffu, s0, 1);
        s0 += __shfl_xor_sync(0xffffffffu, s0, 2);
        s1 += __shfl_xor_sync(0xffffffffu, s1, 1);
        s1 += __shfl_xor_sync(0xffffffffu, s1, 2);
        l0 = l0 * a0 + s0;
        l1 = l1 * a1 + s1;

#pragma unroll
        for (int f = 0; f < 8; f++) {
            of[f][0] *= a0; of[f][1] *= a0;
            of[f][2] *= a1; of[f][3] *= a1;
        }

        uint32_t ph[4][4];
#pragma unroll
        for (int kk = 0; kk < 4; kk++) {
#pragma unroll
            for (int half4 = 0; half4 < 4; half4++) {
                int f = 2 * kk + (half4 >> 1);
                int j = (half4 & 1) * 2;
                __half2 hp = __halves2half2(__float2half_rn(sf[f][j]),
                                            __float2half_rn(sf[f][j + 1]));
                int slot = (half4 >> 1) * 2 + (half4 & 1);
                ph[kk][slot] = *(uint32_t*)&hp;
            }
        }

#pragma unroll
        for (int kk = 0; kk < 4; kk++) {
            uint32_t vh[4][4], vl[4][4];
#pragma unroll
            for (int p = 0; p < 4; p++) {
                uint32_t addr = sV
                    + (kk * 16 + ((sub & 1) << 3) + r8) * 144
                    + p * 32 + ((sub & 2) << 3);
                ldsm_x4_t(vh[p], addr);
                ldsm_x4_t(vl[p], addr + FTILE * 2);
            }
#pragma unroll
            for (int p = 0; p < 4; p++) {
                mma_f16(of[2 * p],     ph[kk], &vh[p][0]);
                mma_f16(of[2 * p + 1], ph[kk], &vh[p][2]);
            }
#pragma unroll
            for (int p = 0; p < 4; p++) {
                mma_f16(of[2 * p],     ph[kk], &vl[p][0]);
                mma_f16(of[2 * p + 1], ph[kk], &vl[p][2]);
            }
        }
    }

    float inv0 = 1.0f / l0, inv1 = 1.0f / l1;
    int rq = qb * 64 + w * 16 + (lane >> 2);
    int cb = head * DHEAD + 2 * (lane & 3);
#pragma unroll
    for (int f = 0; f < 8; f++) {
        int col = cb + 8 * f;
        __half2 hp0 = __halves2half2(__float2half_rn(of[f][0] * inv0),
                                     __float2half_rn(of[f][1] * inv0));
        __half2 hp1 = __halves2half2(__float2half_rn(of[f][2] * inv1),
                                     __float2half_rn(of[f][3] * inv1));
        *(uint32_t*)&g_at_h[(size_t)rq * HID + col]       = *(uint32_t*)&hp0;
        *(uint32_t*)&g_at_h[(size_t)(rq + 8) * HID + col] = *(uint32_t*)&hp1;
    }
}

// ---------------------------------------------------------------------------
extern "C" void kernel_launch(void* const* d_in, const int* in_sizes, int n_in,
                              void* d_out, int out_size) {
    const float* hidden = (const float*)d_in[0];
    const float* w_qkv  = (const float*)d_in[1];
    const float* w_o    = (const float*)d_in[2];
    float*       out    = (float*)d_out;

    float* qkv_ptr = nullptr;
    cudaGetSymbolAddress((void**)&qkv_ptr, g_qkv);
    __half *hid_h, *wq_h, *wq_l, *wo_h, *wo_l, *at_h;
    cudaGetSymbolAddress((void**)&hid_h, g_hid_h);
    cudaGetSymbolAddress((void**)&wq_h,  g_wq_h);
    cudaGetSymbolAddress((void**)&wq_l,  g_wq_l);
    cudaGetSymbolAddress((void**)&wo_h,  g_wo_h);
    cudaGetSymbolAddress((void**)&wo_l,  g_wo_l);
    cudaGetSymbolAddress((void**)&at_h,  g_at_h);

    cudaFuncSetAttribute(gemm_f16x2,
                         cudaFuncAttributeMaxDynamicSharedMemorySize, GEMM_SMEM);
    cudaFuncSetAttribute(flash_attn_tc,
                         cudaFuncAttributeMaxDynamicSharedMemorySize, FA_SMEM);

    tof16_v4<<<(SEQ * HID / 4 + 255) / 256, 256>>>(
        (const float4*)hidden, (uint2*)hid_h, SEQ * HID / 4);
    split_f16_v4<<<(QKV_COLS * HID / 4 + 255) / 256, 256>>>(
        (const float4*)w_qkv, (uint2*)wq_h, (uint2*)wq_l, QKV_COLS * HID / 4);
    split_f16_v4<<<(HID * HID / 4 + 255) / 256, 256>>>(
        (const float4*)w_o, (uint2*)wo_h, (uint2*)wo_l, HID * HID / 4);

    // 1) QKV projection: q columns (0..2047) 1-term, k/v columns (2048..) 2-term
    gemm_f16x2<<<dim3(QKV_COLS / BN, SEQ / BM), 256, GEMM_SMEM>>>(
        hid_h, wq_h, wq_l, qkv_ptr, SEQ, QKV_COLS, HID, NQH * DHEAD);

    // 2) RoPE + fp16 split into head-major q/k/v
    {
        int total = SEQ * 40 * 32;
        rope_split<<<(total + 255) / 256, 256>>>();
    }

    // 3) tensor-core causal GQA flash attention
    flash_attn_tc<<<dim3(NQH, SEQ / 64), 128, FA_SMEM>>>();

    // 4) output projection: all columns 2-term
    gemm_f16x2<<<dim3(HID / BN, SEQ / BM), 256, GEMM_SMEM>>>(
        at_h, wo_h, wo_l, out, SEQ, HID, HID, 0);
}

// round 10
// speedup vs baseline: 1.9797x; 1.2284x over previous
#include <cuda_runtime.h>
#include <cuda_fp16.h>
#include <math.h>
#include <float.h>
#include <stdint.h>

#define SEQ    2048
#define HID    2048
#define DHEAD  64
#define NQH    32
#define NKVH   4
#define QKV_COLS 2560   // (32 + 4 + 4) * 64

// ---------------- scratch (no cudaMalloc allowed) ----------------
__device__ float g_qkv [SEQ * QKV_COLS];

__device__ __half g_hid_h[SEQ * HID];
__device__ __half g_wq_h [QKV_COLS * HID];
__device__ __half g_wq_l [QKV_COLS * HID];
__device__ __half g_wo_h [HID * HID];
__device__ __half g_at_h [SEQ * HID];

__device__ __half g_q_h[NQH  * SEQ * DHEAD];
__device__ __half g_k_h[NKVH * SEQ * DHEAD];
__device__ __half g_k_l[NKVH * SEQ * DHEAD];
__device__ __half g_v_h[NKVH * SEQ * DHEAD];

// ---------------------------------------------------------------------------
// helpers
// ---------------------------------------------------------------------------
__device__ __forceinline__ void cp16(uint32_t s, const void* g) {
    asm volatile("cp.async.cg.shared.global [%0], [%1], 16;\n" :: "r"(s), "l"(g));
}
__device__ __forceinline__ void cp_commit() {
    asm volatile("cp.async.commit_group;\n");
}
template<int N>
__device__ __forceinline__ void cp_wait() {
    asm volatile("cp.async.wait_group %0;\n" :: "n"(N));
}
__device__ __forceinline__ void mma_f16(float* d, const uint32_t* a,
                                        const uint32_t* b) {
    asm volatile(
        "mma.sync.aligned.m16n8k16.row.col.f32.f16.f16.f32 "
        "{%0,%1,%2,%3}, {%4,%5,%6,%7}, {%8,%9}, {%0,%1,%2,%3};\n"
        : "+f"(d[0]), "+f"(d[1]), "+f"(d[2]), "+f"(d[3])
        : "r"(a[0]), "r"(a[1]), "r"(a[2]), "r"(a[3]), "r"(b[0]), "r"(b[1]));
}
__device__ __forceinline__ void mma_f16b(float* d, const uint32_t* a,
                                         uint32_t b0, uint32_t b1) {
    asm volatile(
        "mma.sync.aligned.m16n8k16.row.col.f32.f16.f16.f32 "
        "{%0,%1,%2,%3}, {%4,%5,%6,%7}, {%8,%9}, {%0,%1,%2,%3};\n"
        : "+f"(d[0]), "+f"(d[1]), "+f"(d[2]), "+f"(d[3])
        : "r"(a[0]), "r"(a[1]), "r"(a[2]), "r"(a[3]), "r"(b0), "r"(b1));
}
__device__ __forceinline__ void ldsm_x4(uint32_t* r, uint32_t addr) {
    asm volatile("ldmatrix.sync.aligned.m8n8.x4.shared.b16 {%0,%1,%2,%3}, [%4];\n"
        : "=r"(r[0]), "=r"(r[1]), "=r"(r[2]), "=r"(r[3]) : "r"(addr));
}
__device__ __forceinline__ void ldsm_x4_t(uint32_t* r, uint32_t addr) {
    asm volatile("ldmatrix.sync.aligned.m8n8.x4.trans.shared.b16 {%0,%1,%2,%3}, [%4];\n"
        : "=r"(r[0]), "=r"(r[1]), "=r"(r[2]), "=r"(r[3]) : "r"(addr));
}
__device__ __forceinline__ uint32_t smem_u32_of(const void* p) {
    uint32_t a;
    asm("{ .reg .u64 t; cvta.to.shared.u64 t, %1; cvt.u32.u64 %0, t; }"
        : "=r"(a) : "l"(p));
    return a;
}

// ---------------------------------------------------------------------------
// fp32 -> fp16 hi (+ optional lo residual) splits, float4 vectorized
// ---------------------------------------------------------------------------
__global__ void split_f16_v4(const float4* __restrict__ in,
                             uint2* __restrict__ hi,
                             uint2* __restrict__ lo, int n4) {
    int i = blockIdx.x * blockDim.x + threadIdx.x;
    if (i >= n4) return;
    float4 x = in[i];
    __half h0 = __float2half_rn(x.x);
    __half h1 = __float2half_rn(x.y);
    __half h2 = __float2half_rn(x.z);
    __half h3 = __float2half_rn(x.w);
    __half2 hp0 = __halves2half2(h0, h1);
    __half2 hp1 = __halves2half2(h2, h3);
    __half2 lp0 = __halves2half2(__float2half_rn(x.x - __half2float(h0)),
                                 __float2half_rn(x.y - __half2float(h1)));
    __half2 lp1 = __halves2half2(__float2half_rn(x.z - __half2float(h2)),
                                 __float2half_rn(x.w - __half2float(h3)));
    hi[i] = make_uint2(*(uint32_t*)&hp0, *(uint32_t*)&hp1);
    lo[i] = make_uint2(*(uint32_t*)&lp0, *(uint32_t*)&lp1);
}
__global__ void tof16_v4(const float4* __restrict__ in,
                         uint2* __restrict__ hi, int n4) {
    int i = blockIdx.x * blockDim.x + threadIdx.x;
    if (i >= n4) return;
    float4 x = in[i];
    __half2 hp0 = __halves2half2(__float2half_rn(x.x), __float2half_rn(x.y));
    __half2 hp1 = __halves2half2(__float2half_rn(x.z), __float2half_rn(x.w));
    hi[i] = make_uint2(*(uint32_t*)&hp0, *(uint32_t*)&hp1);
}

// ---------------------------------------------------------------------------
// fp16 tensor-core GEMM with per-CTA term count:
// columns in [n2start, n2end) use 2 terms (B_h + B_l); others 1 term.
// BM=128 BN=64 BK=32, 8 warps (4x2), warp tile 32x32, 3-stage cp.async.
// ---------------------------------------------------------------------------
#define BM 128
#define BN 64
#define BK 32
#define SROW 40
#define A_ELE (128 * SROW)
#define B_ELE (64 * SROW)
#define STAGE_E (A_ELE + 2 * B_ELE)        // 10240 halfs
#define GEMM_SMEM (3 * STAGE_E * 2)        // 61440 bytes

__global__ void __launch_bounds__(256, 3)
gemm_f16x2(const __half* __restrict__ Ah,
           const __half* __restrict__ Bh,
           const __half* __restrict__ Bl,
           float* __restrict__ C, int M, int N, int K,
           int n2start, int n2end) {
    extern __shared__ __half smem[];
    const int tid  = threadIdx.x;
    const int warp = tid >> 5;
    const int lane = tid & 31;
    const int wm   = warp >> 1;
    const int wn   = warp & 1;
    const int g    = lane >> 2;
    const int t    = lane & 3;
    const int row0 = blockIdx.y * BM;
    const int col0 = blockIdx.x * BN;
    const bool use2 = (col0 >= n2start) && (col0 < n2end);   // uniform per CTA

    uint32_t smem_b = smem_u32_of(smem);

    float acc[2][4][4];
#pragma unroll
    for (int i = 0; i < 2; i++)
#pragma unroll
        for (int j = 0; j < 4; j++)
#pragma unroll
            for (int k = 0; k < 4; k++) acc[i][j][k] = 0.f;

    const int NIT = K / BK;   // 64

    auto load_stage = [&](int stage, int k0) {
        uint32_t sb = smem_b + stage * (STAGE_E * 2);
#pragma unroll
        for (int p = 0; p < 2; p++) {
            int c   = tid + p * 256;
            int row = c >> 2;
            int cc  = c & 3;
            uint32_t so = sb + row * (SROW * 2) + cc * 16;
            cp16(so, Ah + (size_t)(row0 + row) * K + k0 + cc * 8);
        }
        {
            int row = tid >> 2;
            int cc  = tid & 3;
            uint32_t so = sb + A_ELE * 2 + row * (SROW * 2) + cc * 16;
            size_t gb = (size_t)(col0 + row) * K + k0 + cc * 8;
            cp16(so, Bh + gb);
            if (use2) cp16(so + B_ELE * 2, Bl + gb);
        }
        cp_commit();
    };

    load_stage(0, 0);
    load_stage(1, BK);

    for (int it = 0; it < NIT; it++) {
        if (it + 2 < NIT) { cp_wait<1>(); } else { cp_wait<0>(); }
        __syncthreads();
        if (it + 2 < NIT) load_stage((it + 2) % 3, (it + 2) * BK);

        const __half* As = smem + (it % 3) * STAGE_E;
        const __half* Bs = As + A_ELE;
        const __half* Bq = Bs + B_ELE;

#pragma unroll
        for (int ks = 0; ks < 2; ks++) {
            uint32_t ah[2][4], bh[4][2], bl[4][2];
#pragma unroll
            for (int mt = 0; mt < 2; mt++) {
                int rb = wm * 32 + mt * 16;
                const __half* pa = As + (rb + g) * SROW + ks * 16 + 2 * t;
                ah[mt][0] = *(const uint32_t*)(pa);
                ah[mt][1] = *(const uint32_t*)(pa + 8 * SROW);
                ah[mt][2] = *(const uint32_t*)(pa + 8);
                ah[mt][3] = *(const uint32_t*)(pa + 8 * SROW + 8);
            }
#pragma unroll
            for (int nt = 0; nt < 4; nt++) {
                int cb = wn * 32 + nt * 8;
                const __half* pb = Bs + (cb + g) * SROW + ks * 16 + 2 * t;
                bh[nt][0] = *(const uint32_t*)(pb);
                bh[nt][1] = *(const uint32_t*)(pb + 8);
            }
            if (use2) {
#pragma unroll
                for (int nt = 0; nt < 4; nt++) {
                    int cb = wn * 32 + nt * 8;
                    const __half* pq = Bq + (cb + g) * SROW + ks * 16 + 2 * t;
                    bl[nt][0] = *(const uint32_t*)(pq);
                    bl[nt][1] = *(const uint32_t*)(pq + 8);
                }
            }
#pragma unroll
            for (int mt = 0; mt < 2; mt++)
#pragma unroll
                for (int nt = 0; nt < 4; nt++)
                    mma_f16b(acc[mt][nt], ah[mt], bh[nt][0], bh[nt][1]);
            if (use2) {
#pragma unroll
                for (int mt = 0; mt < 2; mt++)
#pragma unroll
                    for (int nt = 0; nt < 4; nt++)
                        mma_f16b(acc[mt][nt], ah[mt], bl[nt][0], bl[nt][1]);
            }
        }
    }

#pragma unroll
    for (int mt = 0; mt < 2; mt++) {
        int r = row0 + wm * 32 + mt * 16 + g;
#pragma unroll
        for (int nt = 0; nt < 4; nt++) {
            int c = col0 + wn * 32 + nt * 8 + 2 * t;
            float2 v0 = make_float2(acc[mt][nt][0], acc[mt][nt][1]);
            float2 v1 = make_float2(acc[mt][nt][2], acc[mt][nt][3]);
            *(float2*)&C[(size_t)r * N + c]       = v0;
            *(float2*)&C[(size_t)(r + 8) * N + c] = v1;
        }
    }
}

// ---------------------------------------------------------------------------
// RoPE + fp16 split: g_qkv -> head-major q (hi) / k (hi+lo) / v (hi)
// ---------------------------------------------------------------------------
__global__ void rope_split() {
    int idx = blockIdx.x * blockDim.x + threadIdx.x;
    const int total = SEQ * 40 * 32;
    if (idx >= total) return;
    int pair = idx & 31;
    int head = (idx >> 5) % 40;
    int s    = idx / (40 * 32);

    const float* base = g_qkv + (size_t)s * QKV_COLS + head * DHEAD;
    float x1 = base[pair];
    float x2 = base[pair + 32];
    float y1, y2;
    if (head < 36) {
        float inv_freq = __expf(-(float)pair * (9.210340371976184f / 32.0f));
        float ang = (float)s * inv_freq;
        float sn, cs;
        sincosf(ang, &sn, &cs);
        y1 = x1 * cs - x2 * sn;
        y2 = x2 * cs + x1 * sn;
    } else {
        y1 = x1; y2 = x2;
    }

    if (head < 32) {
        y1 *= 0.125f; y2 *= 0.125f;
        size_t off = ((size_t)head * SEQ + s) * DHEAD;
        g_q_h[off + pair]      = __float2half_rn(y1);
        g_q_h[off + pair + 32] = __float2half_rn(y2);
    } else if (head < 36) {
        size_t off = ((size_t)(head - 32) * SEQ + s) * DHEAD;
        __half h1 = __float2half_rn(y1);
        __half h2 = __float2half_rn(y2);
        g_k_h[off + pair]      = h1;
        g_k_h[off + pair + 32] = h2;
        g_k_l[off + pair]      = __float2half_rn(y1 - __half2float(h1));
        g_k_l[off + pair + 32] = __float2half_rn(y2 - __half2float(h2));
    } else {
        size_t off = ((size_t)(head - 36) * SEQ + s) * DHEAD;
        g_v_h[off + pair]      = __float2half_rn(y1);
        g_v_h[off + pair + 32] = __float2half_rn(y2);
    }
}

// ---------------------------------------------------------------------------
// Tensor-core flash attention, causal, GQA. kk-outer ordering.
// QK^T uses K 2-term (hi+lo); PV uses V 1-term (hi).
// smem arrays: 0:Qh 1:Kh 2:Kl 3:Vh
// ---------------------------------------------------------------------------
#define FSTRIDE 72
#define FTILE (64 * FSTRIDE)
#define FA_SMEM (4 * FTILE * 2)    // 36864 bytes

__global__ void __launch_bounds__(128)
flash_attn_tc() {
    extern __shared__ __half fsm[];
    uint32_t sbase = smem_u32_of(fsm);

    const int head = blockIdx.x;
    const int qb   = gridDim.y - 1 - blockIdx.y;
    const int tid  = threadIdx.x;
    const int w    = tid >> 5;
    const int lane = tid & 31;
    const int kvh  = head >> 3;
    const int r8   = lane & 7;
    const int sub  = lane >> 3;

    {
        const __half* gq = g_q_h + ((size_t)head * SEQ + qb * 64) * DHEAD;
#pragma unroll
        for (int i = 0; i < 4; i++) {
            int c   = tid + i * 128;
            int row = c >> 3;
            int ch  = c & 7;
            cp16(sbase + row * 144 + ch * 16, gq + row * DHEAD + ch * 8);
        }
        cp_commit(); cp_wait<0>();
        __syncthreads();
    }

    uint32_t qh[4][4];
#pragma unroll
    for (int kk = 0; kk < 4; kk++) {
        uint32_t addr = sbase
            + (w * 16 + r8 + ((sub & 1) << 3)) * 144
            + kk * 32 + ((sub & 2) << 3);
        ldsm_x4(qh[kk], addr);
    }

    float of[8][4];
#pragma unroll
    for (int f = 0; f < 8; f++)
#pragma unroll
        for (int j = 0; j < 4; j++) of[f][j] = 0.f;
    float m0 = -1e30f, m1 = -1e30f, l0 = 0.f, l1 = 0.f;

    const uint32_t sK = sbase + 1 * (FTILE * 2);
    const uint32_t sV = sbase + 3 * (FTILE * 2);

    for (int kb = 0; kb <= qb; kb++) {
        __syncthreads();
        {
            const size_t go = ((size_t)kvh * SEQ + kb * 64) * DHEAD;
#pragma unroll
            for (int i = 0; i < 12; i++) {
                int c   = tid + i * 128;   // 1536 chunks: Kh, Kl, Vh
                int arr = c >> 9;
                int rem = c & 511;
                int row = rem >> 3;
                int ch  = rem & 7;
                uint32_t dst = sbase + (1 + arr) * (FTILE * 2) + row * 144 + ch * 16;
                const __half* src;
                if      (arr == 0) src = g_k_h + go;
                else if (arr == 1) src = g_k_l + go;
                else               src = g_v_h + go;
                src += row * DHEAD + ch * 8;
                cp16(dst, src);
            }
            cp_commit(); cp_wait<0>();
            __syncthreads();
        }

        // ---- S = Q K^T (K 2-term), kk-outer ----
        float sf[8][4];
#pragma unroll
        for (int f = 0; f < 8; f++)
#pragma unroll
            for (int j = 0; j < 4; j++) sf[f][j] = 0.f;

#pragma unroll
        for (int kk = 0; kk < 4; kk++) {
            uint32_t bh[4][4], bl[4][4];
#pragma unroll
            for (int p = 0; p < 4; p++) {
                uint32_t addr = sK
                    + (p * 16 + ((sub & 2) << 2) + r8) * 144
                    + kk * 32 + ((sub & 1) << 4);
                ldsm_x4(bh[p], addr);
                ldsm_x4(bl[p], addr + FTILE * 2);
            }
#pragma unroll
            for (int p = 0; p < 4; p++) {
                mma_f16(sf[2 * p],     qh[kk], &bh[p][0]);
                mma_f16(sf[2 * p + 1], qh[kk], &bh[p][2]);
            }
#pragma unroll
            for (int p = 0; p < 4; p++) {
                mma_f16(sf[2 * p],     qh[kk], &bl[p][0]);
                mma_f16(sf[2 * p + 1], qh[kk], &bl[p][2]);
            }
        }

        if (kb == qb) {
            int rt0 = w * 16 + (lane >> 2);
#pragma unroll
            for (int f = 0; f < 8; f++) {
                int ct = 8 * f + 2 * (lane & 3);
                if (ct > rt0)         sf[f][0] = -1e30f;
                if (ct + 1 > rt0)     sf[f][1] = -1e30f;
                if (ct > rt0 + 8)     sf[f][2] = -1e30f;
                if (ct + 1 > rt0 + 8) sf[f][3] = -1e30f;
            }
        }

        float c0 = -1e30f, c1 = -1e30f;
#pragma unroll
        for (int f = 0; f < 8; f++) {
            c0 = fmaxf(c0, fmaxf(sf[f][0], sf[f][1]));
            c1 = fmaxf(c1, fmaxf(sf[f][2], sf[f][3]));
        }
        c0 = fmaxf(c0, __shfl_xor_sync(0xffffffffu, c0, 1));
        c0 = fmaxf(c0, __shfl_xor_sync(0xffffffffu, c0, 2));
        c1 = fmaxf(c1, __shfl_xor_sync(0xffffffffu, c1, 1));
        c1 = fmaxf(c1, __shfl_xor_sync(0xffffffffu, c1, 2));

        float mn0 = fmaxf(m0, c0), mn1 = fmaxf(m1, c1);
        float a0 = __expf(m0 - mn0), a1 = __expf(m1 - mn1);
        m0 = mn0; m1 = mn1;

        float s0 = 0.f, s1 = 0.f;
#pragma unroll
        for (int f = 0; f < 8; f++) {
            sf[f][0] = __expf(sf[f][0] - mn0);
            sf[f][1] = __expf(sf[f][1] - mn0);
            sf[f][2] = __expf(sf[f][2] - mn1);
            sf[f][3] = __expf(sf[f][3] - mn1);
            s0 += sf[f][0] + sf[f][1];
            s1 += sf[f][2] + sf[f][3];
        }
        s0 += __shfl_xor_sync(0xffffffffu, s0, 1);
        s0 += __shfl_xor_sync(0xffffffffu, s0, 2);
        s1 += __shfl_xor_sync(0xffffffffu, s1, 1);
        s1 += __shfl_xor_sync(0xffffffffu, s1, 2);
        l0 = l0 * a0 + s0;
        l1 = l1 * a1 + s1;

#pragma unroll
        for (int f = 0; f < 8; f++) {
            of[f][0] *= a0; of[f][1] *= a0;
            of[f][2] *= a1; of[f][3] *= a1;
        }

        uint32_t ph[4][4];
#pragma unroll
        for (int kk = 0; kk < 4; kk++) {
#pragma unroll
            for (int half4 = 0; half4 < 4; half4++) {
                int f = 2 * kk + (half4 >> 1);
                int j = (half4 & 1) * 2;
                __half2 hp = __halves2half2(__float2half_rn(sf[f][j]),
                                            __float2half_rn(sf[f][j + 1]));
                int slot = (half4 >> 1) * 2 + (half4 & 1);
                ph[kk][slot] = *(uint32_t*)&hp;
            }
        }

        // ---- O += P V_h (1-term), kk-outer ----
#pragma unroll
        for (int kk = 0; kk < 4; kk++) {
            uint32_t vh[4][4];
#pragma unroll
            for (int p = 0; p < 4; p++) {
                uint32_t addr = sV
                    + (kk * 16 + ((sub & 1) << 3) + r8) * 144
                    + p * 32 + ((sub & 2) << 3);
                ldsm_x4_t(vh[p], addr);
            }
#pragma unroll
            for (int p = 0; p < 4; p++) {
                mma_f16(of[2 * p],     ph[kk], &vh[p][0]);
                mma_f16(of[2 * p + 1], ph[kk], &vh[p][2]);
            }
        }
    }

    float inv0 = 1.0f / l0, inv1 = 1.0f / l1;
    int rq = qb * 64 + w * 16 + (lane >> 2);
    int cb = head * DHEAD + 2 * (lane & 3);
#pragma unroll
    for (int f = 0; f < 8; f++) {
        int col = cb + 8 * f;
        __half2 hp0 = __halves2half2(__float2half_rn(of[f][0] * inv0),
                                     __float2half_rn(of[f][1] * inv0));
        __half2 hp1 = __halves2half2(__float2half_rn(of[f][2] * inv1),
                                     __float2half_rn(of[f][3] * inv1));
        *(uint32_t*)&g_at_h[(size_t)rq * HID + col]       = *(uint32_t*)&hp0;
        *(uint32_t*)&g_at_h[(size_t)(rq + 8) * HID + col] = *(uint32_t*)&hp1;
    }
}

// ---------------------------------------------------------------------------
extern "C" void kernel_launch(void* const* d_in, const int* in_sizes, int n_in,
                              void* d_out, int out_size) {
    const float* hidden = (const float*)d_in[0];
    const float* w_qkv  = (const float*)d_in[1];
    const float* w_o    = (const float*)d_in[2];
    float*       out    = (float*)d_out;

    float* qkv_ptr = nullptr;
    cudaGetSymbolAddress((void**)&qkv_ptr, g_qkv);
    __half *hid_h, *wq_h, *wq_l, *wo_h, *at_h;
    cudaGetSymbolAddress((void**)&hid_h, g_hid_h);
    cudaGetSymbolAddress((void**)&wq_h,  g_wq_h);
    cudaGetSymbolAddress((void**)&wq_l,  g_wq_l);
    cudaGetSymbolAddress((void**)&wo_h,  g_wo_h);
    cudaGetSymbolAddress((void**)&at_h,  g_at_h);

    cudaFuncSetAttribute(gemm_f16x2,
                         cudaFuncAttributeMaxDynamicSharedMemorySize, GEMM_SMEM);
    cudaFuncSetAttribute(flash_attn_tc,
                         cudaFuncAttributeMaxDynamicSharedMemorySize, FA_SMEM);

    tof16_v4<<<(SEQ * HID / 4 + 255) / 256, 256>>>(
        (const float4*)hidden, (uint2*)hid_h, SEQ * HID / 4);
    split_f16_v4<<<(QKV_COLS * HID / 4 + 255) / 256, 256>>>(
        (const float4*)w_qkv, (uint2*)wq_h, (uint2*)wq_l, QKV_COLS * HID / 4);
    tof16_v4<<<(HID * HID / 4 + 255) / 256, 256>>>(
        (const float4*)w_o, (uint2*)wo_h, HID * HID / 4);

    // 1) QKV projection: 2-term window = k head columns [2048, 2304) only
    gemm_f16x2<<<dim3(QKV_COLS / BN, SEQ / BM), 256, GEMM_SMEM>>>(
        hid_h, wq_h, wq_l, qkv_ptr, SEQ, QKV_COLS, HID,
        NQH * DHEAD, (NQH + NKVH) * DHEAD);

    // 2) RoPE + fp16 split into head-major q/k/v
    {
        int total = SEQ * 40 * 32;
        rope_split<<<(total + 255) / 256, 256>>>();
    }

    // 3) tensor-core causal GQA flash attention
    flash_attn_tc<<<dim3(NQH, SEQ / 64), 128, FA_SMEM>>>();

    // 4) output projection: plain 1-term fp16 GEMM (empty 2-term window)
    gemm_f16x2<<<dim3(HID / BN, SEQ / BM), 256, GEMM_SMEM>>>(
        at_h, wo_h, wo_h, out, SEQ, HID, HID, 0, 0);
}

// round 11
// speedup vs baseline: 2.1844x; 1.1034x over previous
#include <cuda_runtime.h>
#include <cuda_fp16.h>
#include <math.h>
#include <float.h>
#include <stdint.h>

#define SEQ    2048
#define HID    2048
#define DHEAD  64
#define NQH    32
#define NKVH   4
#define QKV_COLS 2560   // (32 + 4 + 4) * 64

// ---------------- scratch (no cudaMalloc allowed) ----------------
__device__ float g_qkv [SEQ * QKV_COLS];

__device__ __half g_hid_h[SEQ * HID];
__device__ __half g_wq_h [QKV_COLS * HID];
__device__ __half g_wq_l [QKV_COLS * HID];
__device__ __half g_wo_h [HID * HID];
__device__ __half g_at_h [SEQ * HID];

__device__ __half g_q_h[NQH  * SEQ * DHEAD];
__device__ __half g_k_h[NKVH * SEQ * DHEAD];
__device__ __half g_k_l[NKVH * SEQ * DHEAD];
__device__ __half g_v_h[NKVH * SEQ * DHEAD];

// ---------------------------------------------------------------------------
// helpers
// ---------------------------------------------------------------------------
__device__ __forceinline__ void cp16(uint32_t s, const void* g) {
    asm volatile("cp.async.cg.shared.global [%0], [%1], 16;\n" :: "r"(s), "l"(g));
}
__device__ __forceinline__ void cp_commit() {
    asm volatile("cp.async.commit_group;\n");
}
template<int N>
__device__ __forceinline__ void cp_wait() {
    asm volatile("cp.async.wait_group %0;\n" :: "n"(N));
}
__device__ __forceinline__ void mma_f16(float* d, const uint32_t* a,
                                        const uint32_t* b) {
    asm volatile(
        "mma.sync.aligned.m16n8k16.row.col.f32.f16.f16.f32 "
        "{%0,%1,%2,%3}, {%4,%5,%6,%7}, {%8,%9}, {%0,%1,%2,%3};\n"
        : "+f"(d[0]), "+f"(d[1]), "+f"(d[2]), "+f"(d[3])
        : "r"(a[0]), "r"(a[1]), "r"(a[2]), "r"(a[3]), "r"(b[0]), "r"(b[1]));
}
__device__ __forceinline__ void mma_f16b(float* d, const uint32_t* a,
                                         uint32_t b0, uint32_t b1) {
    asm volatile(
        "mma.sync.aligned.m16n8k16.row.col.f32.f16.f16.f32 "
        "{%0,%1,%2,%3}, {%4,%5,%6,%7}, {%8,%9}, {%0,%1,%2,%3};\n"
        : "+f"(d[0]), "+f"(d[1]), "+f"(d[2]), "+f"(d[3])
        : "r"(a[0]), "r"(a[1]), "r"(a[2]), "r"(a[3]), "r"(b0), "r"(b1));
}
__device__ __forceinline__ void ldsm_x4(uint32_t* r, uint32_t addr) {
    asm volatile("ldmatrix.sync.aligned.m8n8.x4.shared.b16 {%0,%1,%2,%3}, [%4];\n"
        : "=r"(r[0]), "=r"(r[1]), "=r"(r[2]), "=r"(r[3]) : "r"(addr));
}
__device__ __forceinline__ void ldsm_x4_t(uint32_t* r, uint32_t addr) {
    asm volatile("ldmatrix.sync.aligned.m8n8.x4.trans.shared.b16 {%0,%1,%2,%3}, [%4];\n"
        : "=r"(r[0]), "=r"(r[1]), "=r"(r[2]), "=r"(r[3]) : "r"(addr));
}
__device__ __forceinline__ uint32_t smem_u32_of(const void* p) {
    uint32_t a;
    asm("{ .reg .u64 t; cvta.to.shared.u64 t, %1; cvt.u32.u64 %0, t; }"
        : "=r"(a) : "l"(p));
    return a;
}

// ---------------------------------------------------------------------------
// fp32 -> fp16 hi (+ optional lo residual) splits, float4 vectorized
// ---------------------------------------------------------------------------
__global__ void split_f16_v4(const float4* __restrict__ in,
                             uint2* __restrict__ hi,
                             uint2* __restrict__ lo, int n4) {
    int i = blockIdx.x * blockDim.x + threadIdx.x;
    if (i >= n4) return;
    float4 x = in[i];
    __half h0 = __float2half_rn(x.x);
    __half h1 = __float2half_rn(x.y);
    __half h2 = __float2half_rn(x.z);
    __half h3 = __float2half_rn(x.w);
    __half2 hp0 = __halves2half2(h0, h1);
    __half2 hp1 = __halves2half2(h2, h3);
    __half2 lp0 = __halves2half2(__float2half_rn(x.x - __half2float(h0)),
                                 __float2half_rn(x.y - __half2float(h1)));
    __half2 lp1 = __halves2half2(__float2half_rn(x.z - __half2float(h2)),
                                 __float2half_rn(x.w - __half2float(h3)));
    hi[i] = make_uint2(*(uint32_t*)&hp0, *(uint32_t*)&hp1);
    lo[i] = make_uint2(*(uint32_t*)&lp0, *(uint32_t*)&lp1);
}
__global__ void tof16_v4(const float4* __restrict__ in,
                         uint2* __restrict__ hi, int n4) {
    int i = blockIdx.x * blockDim.x + threadIdx.x;
    if (i >= n4) return;
    float4 x = in[i];
    __half2 hp0 = __halves2half2(__float2half_rn(x.x), __float2half_rn(x.y));
    __half2 hp1 = __halves2half2(__float2half_rn(x.z), __float2half_rn(x.w));
    hi[i] = make_uint2(*(uint32_t*)&hp0, *(uint32_t*)&hp1);
}

// ---------------------------------------------------------------------------
// 1-term fp16 GEMM: BM=128 BN=128 BK=32, 8 warps (4x2), warp tile 32x64,
// 3-stage cp.async, 20KB/stage -> 60KB smem -> 2 CTAs/SM.
// C[M,N] = A_h[M,K] @ B_h[N,K]^T, fp32 accumulate
// ---------------------------------------------------------------------------
#define SROW 40
#define T1_A_ELE (128 * SROW)
#define T1_B_ELE (128 * SROW)
#define T1_STAGE (T1_A_ELE + T1_B_ELE)    // 10240 halfs
#define T1_SMEM (3 * T1_STAGE * 2)        // 61440 bytes

__global__ void __launch_bounds__(256, 2)
gemm_1t(const __half* __restrict__ Ah,
        const __half* __restrict__ Bh,
        float* __restrict__ C, int M, int N, int K) {
    extern __shared__ __half smem[];
    const int tid  = threadIdx.x;
    const int warp = tid >> 5;
    const int lane = tid & 31;
    const int wm   = warp >> 1;        // 0..3
    const int wn   = warp & 1;         // 0..1
    const int g    = lane >> 2;
    const int t    = lane & 3;
    const int row0 = blockIdx.y * 128;
    const int col0 = blockIdx.x * 128;

    uint32_t smem_b = smem_u32_of(smem);

    float acc[2][8][4];
#pragma unroll
    for (int i = 0; i < 2; i++)
#pragma unroll
        for (int j = 0; j < 8; j++)
#pragma unroll
            for (int k = 0; k < 4; k++) acc[i][j][k] = 0.f;

    const int NIT = K / 32;   // 64

    auto load_stage = [&](int stage, int k0) {
        uint32_t sb = smem_b + stage * (T1_STAGE * 2);
#pragma unroll
        for (int p = 0; p < 2; p++) {
            int c   = tid + p * 256;
            int row = c >> 2;
            int cc  = c & 3;
            uint32_t so = sb + row * (SROW * 2) + cc * 16;
            cp16(so, Ah + (size_t)(row0 + row) * K + k0 + cc * 8);
            uint32_t sb2 = so + T1_A_ELE * 2;
            cp16(sb2, Bh + (size_t)(col0 + row) * K + k0 + cc * 8);
        }
        cp_commit();
    };

    load_stage(0, 0);
    load_stage(1, 32);

    for (int it = 0; it < NIT; it++) {
        if (it + 2 < NIT) { cp_wait<1>(); } else { cp_wait<0>(); }
        __syncthreads();
        if (it + 2 < NIT) load_stage((it + 2) % 3, (it + 2) * 32);

        const __half* As = smem + (it % 3) * T1_STAGE;
        const __half* Bs = As + T1_A_ELE;

#pragma unroll
        for (int ks = 0; ks < 2; ks++) {
            uint32_t ah[2][4], bh[8][2];
#pragma unroll
            for (int mt = 0; mt < 2; mt++) {
                int rb = wm * 32 + mt * 16;
                const __half* pa = As + (rb + g) * SROW + ks * 16 + 2 * t;
                ah[mt][0] = *(const uint32_t*)(pa);
                ah[mt][1] = *(const uint32_t*)(pa + 8 * SROW);
                ah[mt][2] = *(const uint32_t*)(pa + 8);
                ah[mt][3] = *(const uint32_t*)(pa + 8 * SROW + 8);
            }
#pragma unroll
            for (int nt = 0; nt < 8; nt++) {
                int cb = wn * 64 + nt * 8;
                const __half* pb = Bs + (cb + g) * SROW + ks * 16 + 2 * t;
                bh[nt][0] = *(const uint32_t*)(pb);
                bh[nt][1] = *(const uint32_t*)(pb + 8);
            }
#pragma unroll
            for (int mt = 0; mt < 2; mt++)
#pragma unroll
                for (int nt = 0; nt < 8; nt++)
                    mma_f16b(acc[mt][nt], ah[mt], bh[nt][0], bh[nt][1]);
        }
    }

#pragma unroll
    for (int mt = 0; mt < 2; mt++) {
        int r = row0 + wm * 32 + mt * 16 + g;
#pragma unroll
        for (int nt = 0; nt < 8; nt++) {
            int c = col0 + wn * 64 + nt * 8 + 2 * t;
            float2 v0 = make_float2(acc[mt][nt][0], acc[mt][nt][1]);
            float2 v1 = make_float2(acc[mt][nt][2], acc[mt][nt][3]);
            *(float2*)&C[(size_t)r * N + c]       = v0;
            *(float2*)&C[(size_t)(r + 8) * N + c] = v1;
        }
    }
}

// ---------------------------------------------------------------------------
// Mixed-term fp16 GEMM (BN=64), used for the k/v strip.
// columns in [n2start, n2end) use 2 terms (B_h + B_l); others 1 term.
// ---------------------------------------------------------------------------
#define BM 128
#define BN 64
#define A_ELE (128 * SROW)
#define B_ELE (64 * SROW)
#define STAGE_E (A_ELE + 2 * B_ELE)        // 10240 halfs
#define GEMM_SMEM (3 * STAGE_E * 2)        // 61440 bytes

__global__ void __launch_bounds__(256, 3)
gemm_f16x2(const __half* __restrict__ Ah,
           const __half* __restrict__ Bh,
           const __half* __restrict__ Bl,
           float* __restrict__ C, int M, int N, int K,
           int n2start, int n2end) {
    extern __shared__ __half smem[];
    const int tid  = threadIdx.x;
    const int warp = tid >> 5;
    const int lane = tid & 31;
    const int wm   = warp >> 1;
    const int wn   = warp & 1;
    const int g    = lane >> 2;
    const int t    = lane & 3;
    const int row0 = blockIdx.y * BM;
    const int col0 = blockIdx.x * BN;
    const bool use2 = (col0 >= n2start) && (col0 < n2end);

    uint32_t smem_b = smem_u32_of(smem);

    float acc[2][4][4];
#pragma unroll
    for (int i = 0; i < 2; i++)
#pragma unroll
        for (int j = 0; j < 4; j++)
#pragma unroll
            for (int k = 0; k < 4; k++) acc[i][j][k] = 0.f;

    const int NIT = K / 32;

    auto load_stage = [&](int stage, int k0) {
        uint32_t sb = smem_b + stage * (STAGE_E * 2);
#pragma unroll
        for (int p = 0; p < 2; p++) {
            int c   = tid + p * 256;
            int row = c >> 2;
            int cc  = c & 3;
            uint32_t so = sb + row * (SROW * 2) + cc * 16;
            cp16(so, Ah + (size_t)(row0 + row) * K + k0 + cc * 8);
        }
        {
            int row = tid >> 2;
            int cc  = tid & 3;
            uint32_t so = sb + A_ELE * 2 + row * (SROW * 2) + cc * 16;
            size_t gb = (size_t)(col0 + row) * K + k0 + cc * 8;
            cp16(so, Bh + gb);
            if (use2) cp16(so + B_ELE * 2, Bl + gb);
        }
        cp_commit();
    };

    load_stage(0, 0);
    load_stage(1, 32);

    for (int it = 0; it < NIT; it++) {
        if (it + 2 < NIT) { cp_wait<1>(); } else { cp_wait<0>(); }
        __syncthreads();
        if (it + 2 < NIT) load_stage((it + 2) % 3, (it + 2) * 32);

        const __half* As = smem + (it % 3) * STAGE_E;
        const __half* Bs = As + A_ELE;
        const __half* Bq = Bs + B_ELE;

#pragma unroll
        for (int ks = 0; ks < 2; ks++) {
            uint32_t ah[2][4], bh[4][2], bl[4][2];
#pragma unroll
            for (int mt = 0; mt < 2; mt++) {
                int rb = wm * 32 + mt * 16;
                const __half* pa = As + (rb + g) * SROW + ks * 16 + 2 * t;
                ah[mt][0] = *(const uint32_t*)(pa);
                ah[mt][1] = *(const uint32_t*)(pa + 8 * SROW);
                ah[mt][2] = *(const uint32_t*)(pa + 8);
                ah[mt][3] = *(const uint32_t*)(pa + 8 * SROW + 8);
            }
#pragma unroll
            for (int nt = 0; nt < 4; nt++) {
                int cb = wn * 32 + nt * 8;
                const __half* pb = Bs + (cb + g) * SROW + ks * 16 + 2 * t;
                bh[nt][0] = *(const uint32_t*)(pb);
                bh[nt][1] = *(const uint32_t*)(pb + 8);
            }
            if (use2) {
#pragma unroll
                for (int nt = 0; nt < 4; nt++) {
                    int cb = wn * 32 + nt * 8;
                    const __half* pq = Bq + (cb + g) * SROW + ks * 16 + 2 * t;
                    bl[nt][0] = *(const uint32_t*)(pq);
                    bl[nt][1] = *(const uint32_t*)(pq + 8);
                }
            }
#pragma unroll
            for (int mt = 0; mt < 2; mt++)
#pragma unroll
                for (int nt = 0; nt < 4; nt++)
                    mma_f16b(acc[mt][nt], ah[mt], bh[nt][0], bh[nt][1]);
            if (use2) {
#pragma unroll
                for (int mt = 0; mt < 2; mt++)
#pragma unroll
                    for (int nt = 0; nt < 4; nt++)
                        mma_f16b(acc[mt][nt], ah[mt], bl[nt][0], bl[nt][1]);
            }
        }
    }

#pragma unroll
    for (int mt = 0; mt < 2; mt++) {
        int r = row0 + wm * 32 + mt * 16 + g;
#pragma unroll
        for (int nt = 0; nt < 4; nt++) {
            int c = col0 + wn * 32 + nt * 8 + 2 * t;
            float2 v0 = make_float2(acc[mt][nt][0], acc[mt][nt][1]);
            float2 v1 = make_float2(acc[mt][nt][2], acc[mt][nt][3]);
            *(float2*)&C[(size_t)r * N + c]       = v0;
            *(float2*)&C[(size_t)(r + 8) * N + c] = v1;
        }
    }
}

// ---------------------------------------------------------------------------
// RoPE + fp16 split: g_qkv -> head-major q (hi) / k (hi+lo) / v (hi)
// ---------------------------------------------------------------------------
__global__ void rope_split() {
    int idx = blockIdx.x * blockDim.x + threadIdx.x;
    const int total = SEQ * 40 * 32;
    if (idx >= total) return;
    int pair = idx & 31;
    int head = (idx >> 5) % 40;
    int s    = idx / (40 * 32);

    const float* base = g_qkv + (size_t)s * QKV_COLS + head * DHEAD;
    float x1 = base[pair];
    float x2 = base[pair + 32];
    float y1, y2;
    if (head < 36) {
        float inv_freq = __expf(-(float)pair * (9.210340371976184f / 32.0f));
        float ang = (float)s * inv_freq;
        float sn, cs;
        sincosf(ang, &sn, &cs);
        y1 = x1 * cs - x2 * sn;
        y2 = x2 * cs + x1 * sn;
    } else {
        y1 = x1; y2 = x2;
    }

    if (head < 32) {
        y1 *= 0.125f; y2 *= 0.125f;
        size_t off = ((size_t)head * SEQ + s) * DHEAD;
        g_q_h[off + pair]      = __float2half_rn(y1);
        g_q_h[off + pair + 32] = __float2half_rn(y2);
    } else if (head < 36) {
        size_t off = ((size_t)(head - 32) * SEQ + s) * DHEAD;
        __half h1 = __float2half_rn(y1);
        __half h2 = __float2half_rn(y2);
        g_k_h[off + pair]      = h1;
        g_k_h[off + pair + 32] = h2;
        g_k_l[off + pair]      = __float2half_rn(y1 - __half2float(h1));
        g_k_l[off + pair + 32] = __float2half_rn(y2 - __half2float(h2));
    } else {
        size_t off = ((size_t)(head - 36) * SEQ + s) * DHEAD;
        g_v_h[off + pair]      = __float2half_rn(y1);
        g_v_h[off + pair + 32] = __float2half_rn(y2);
    }
}

// ---------------------------------------------------------------------------
// Tensor-core flash attention, causal, GQA. kk-outer ordering.
// QK^T uses K 2-term (hi+lo); PV uses V 1-term (hi).
// smem arrays: 0:Qh 1:Kh 2:Kl 3:Vh
// ---------------------------------------------------------------------------
#define FSTRIDE 72
#define FTILE (64 * FSTRIDE)
#define FA_SMEM (4 * FTILE * 2)    // 36864 bytes

__global__ void __launch_bounds__(128)
flash_attn_tc() {
    extern __shared__ __half fsm[];
    uint32_t sbase = smem_u32_of(fsm);

    const int head = blockIdx.x;
    const int qb   = gridDim.y - 1 - blockIdx.y;
    const int tid  = threadIdx.x;
    const int w    = tid >> 5;
    const int lane = tid & 31;
    const int kvh  = head >> 3;
    const int r8   = lane & 7;
    const int sub  = lane >> 3;

    {
        const __half* gq = g_q_h + ((size_t)head * SEQ + qb * 64) * DHEAD;
#pragma unroll
        for (int i = 0; i < 4; i++) {
            int c   = tid + i * 128;
            int row = c >> 3;
            int ch  = c & 7;
            cp16(sbase + row * 144 + ch * 16, gq + row * DHEAD + ch * 8);
        }
        cp_commit(); cp_wait<0>();
        __syncthreads();
    }

    uint32_t qh[4][4];
#pragma unroll
    for (int kk = 0; kk < 4; kk++) {
        uint32_t addr = sbase
            + (w * 16 + r8 + ((sub & 1) << 3)) * 144
            + kk * 32 + ((sub & 2) << 3);
        ldsm_x4(qh[kk], addr);
    }

    float of[8][4];
#pragma unroll
    for (int f = 0; f < 8; f++)
#pragma unroll
        for (int j = 0; j < 4; j++) of[f][j] = 0.f;
    float m0 = -1e30f, m1 = -1e30f, l0 = 0.f, l1 = 0.f;

    const uint32_t sK = sbase + 1 * (FTILE * 2);
    const uint32_t sV = sbase + 3 * (FTILE * 2);

    for (int kb = 0; kb <= qb; kb++) {
        __syncthreads();
        {
            const size_t go = ((size_t)kvh * SEQ + kb * 64) * DHEAD;
#pragma unroll
            for (int i = 0; i < 12; i++) {
                int c   = tid + i * 128;
                int arr = c >> 9;
                int rem = c & 511;
                int row = rem >> 3;
                int ch  = rem & 7;
                uint32_t dst = sbase + (1 + arr) * (FTILE * 2) + row * 144 + ch * 16;
                const __half* src;
                if      (arr == 0) src = g_k_h + go;
                else if (arr == 1) src = g_k_l + go;
                else               src = g_v_h + go;
                src += row * DHEAD + ch * 8;
                cp16(dst, src);
            }
            cp_commit(); cp_wait<0>();
            __syncthreads();
        }

        float sf[8][4];
#pragma unroll
        for (int f = 0; f < 8; f++)
#pragma unroll
            for (int j = 0; j < 4; j++) sf[f][j] = 0.f;

#pragma unroll
        for (int kk = 0; kk < 4; kk++) {
            uint32_t bh[4][4], bl[4][4];
#pragma unroll
            for (int p = 0; p < 4; p++) {
                uint32_t addr = sK
                    + (p * 16 + ((sub & 2) << 2) + r8) * 144
                    + kk * 32 + ((sub & 1) << 4);
                ldsm_x4(bh[p], addr);
                ldsm_x4(bl[p], addr + FTILE * 2);
            }
#pragma unroll
            for (int p = 0; p < 4; p++) {
                mma_f16(sf[2 * p],     qh[kk], &bh[p][0]);
                mma_f16(sf[2 * p + 1], qh[kk], &bh[p][2]);
            }
#pragma unroll
            for (int p = 0; p < 4; p++) {
                mma_f16(sf[2 * p],     qh[kk], &bl[p][0]);
                mma_f16(sf[2 * p + 1], qh[kk], &bl[p][2]);
            }
        }

        if (kb == qb) {
            int rt0 = w * 16 + (lane >> 2);
#pragma unroll
            for (int f = 0; f < 8; f++) {
                int ct = 8 * f + 2 * (lane & 3);
                if (ct > rt0)         sf[f][0] = -1e30f;
                if (ct + 1 > rt0)     sf[f][1] = -1e30f;
                if (ct > rt0 + 8)     sf[f][2] = -1e30f;
                if (ct + 1 > rt0 + 8) sf[f][3] = -1e30f;
            }
        }

        float c0 = -1e30f, c1 = -1e30f;
#pragma unroll
        for (int f = 0; f < 8; f++) {
            c0 = fmaxf(c0, fmaxf(sf[f][0], sf[f][1]));
            c1 = fmaxf(c1, fmaxf(sf[f][2], sf[f][3]));
        }
        c0 = fmaxf(c0, __shfl_xor_sync(0xffffffffu, c0, 1));
        c0 = fmaxf(c0, __shfl_xor_sync(0xffffffffu, c0, 2));
        c1 = fmaxf(c1, __shfl_xor_sync(0xffffffffu, c1, 1));
        c1 = fmaxf(c1, __shfl_xor_sync(0xffffffffu, c1, 2));

        float mn0 = fmaxf(m0, c0), mn1 = fmaxf(m1, c1);
        float a0 = __expf(m0 - mn0), a1 = __expf(m1 - mn1);
        m0 = mn0; m1 = mn1;

        float s0 = 0.f, s1 = 0.f;
#pragma unroll
        for (int f = 0; f < 8; f++) {
            sf[f][0] = __expf(sf[f][0] - mn0);
            sf[f][1] = __expf(sf[f][1] - mn0);
            sf[f][2] = __expf(sf[f][2] - mn1);
            sf[f][3] = __expf(sf[f][3] - mn1);
            s0 += sf[f][0] + sf[f][1];
            s1 += sf[f][2] + sf[f][3];
        }
        s0 += __shfl_xor_sync(0xffffffffu, s0, 1);
        s0 += __shfl_xor_sync(0xffffffffu, s0, 2);
        s1 += __shfl_xor_sync(0xffffffffu, s1, 1);
        s1 += __shfl_xor_sync(0xffffffffu, s1, 2);
        l0 = l0 * a0 + s0;
        l1 = l1 * a1 + s1;

#pragma unroll
        for (int f = 0; f < 8; f++) {
            of[f][0] *= a0; of[f][1] *= a0;
            of[f][2] *= a1; of[f][3] *= a1;
        }

        uint32_t ph[4][4];
#pragma unroll
        for (int kk = 0; kk < 4; kk++) {
#pragma unroll
            for (int half4 = 0; half4 < 4; half4++) {
                int f = 2 * kk + (half4 >> 1);
                int j = (half4 & 1) * 2;
                __half2 hp = __halves2half2(__float2half_rn(sf[f][j]),
                                            __float2half_rn(sf[f][j + 1]));
                int slot = (half4 >> 1) * 2 + (half4 & 1);
                ph[kk][slot] = *(uint32_t*)&hp;
            }
        }

#pragma unroll
        for (int kk = 0; kk < 4; kk++) {
            uint32_t vh[4][4];
#pragma unroll
            for (int p = 0; p < 4; p++) {
                uint32_t addr = sV
                    + (kk * 16 + ((sub & 1) << 3) + r8) * 144
                    + p * 32 + ((sub & 2) << 3);
                ldsm_x4_t(vh[p], addr);
            }
#pragma unroll
            for (int p = 0; p < 4; p++) {
                mma_f16(of[2 * p],     ph[kk], &vh[p][0]);
                mma_f16(of[2 * p + 1], ph[kk], &vh[p][2]);
            }
        }
    }

    float inv0 = 1.0f / l0, inv1 = 1.0f / l1;
    int rq = qb * 64 + w * 16 + (lane >> 2);
    int cb = head * DHEAD + 2 * (lane & 3);
#pragma unroll
    for (int f = 0; f < 8; f++) {
        int col = cb + 8 * f;
        __half2 hp0 = __halves2half2(__float2half_rn(of[f][0] * inv0),
                                     __float2half_rn(of[f][1] * inv0));
        __half2 hp1 = __halves2half2(__float2half_rn(of[f][2] * inv1),
                                     __float2half_rn(of[f][3] * inv1));
        *(uint32_t*)&g_at_h[(size_t)rq * HID + col]       = *(uint32_t*)&hp0;
        *(uint32_t*)&g_at_h[(size_t)(rq + 8) * HID + col] = *(uint32_t*)&hp1;
    }
}

// ---------------------------------------------------------------------------
extern "C" void kernel_launch(void* const* d_in, const int* in_sizes, int n_in,
                              void* d_out, int out_size) {
    const float* hidden = (const float*)d_in[0];
    const float* w_qkv  = (const float*)d_in[1];
    const float* w_o    = (const float*)d_in[2];
    float*       out    = (float*)d_out;

    float* qkv_ptr = nullptr;
    cudaGetSymbolAddress((void**)&qkv_ptr, g_qkv);
    __half *hid_h, *wq_h, *wq_l, *wo_h, *at_h;
    cudaGetSymbolAddress((void**)&hid_h, g_hid_h);
    cudaGetSymbolAddress((void**)&wq_h,  g_wq_h);
    cudaGetSymbolAddress((void**)&wq_l,  g_wq_l);
    cudaGetSymbolAddress((void**)&wo_h,  g_wo_h);
    cudaGetSymbolAddress((void**)&at_h,  g_at_h);

    cudaFuncSetAttribute(gemm_1t,
                         cudaFuncAttributeMaxDynamicSharedMemorySize, T1_SMEM);
    cudaFuncSetAttribute(gemm_f16x2,
                         cudaFuncAttributeMaxDynamicSharedMemorySize, GEMM_SMEM);
    cudaFuncSetAttribute(flash_attn_tc,
                         cudaFuncAttributeMaxDynamicSharedMemorySize, FA_SMEM);

    tof16_v4<<<(SEQ * HID / 4 + 255) / 256, 256>>>(
        (const float4*)hidden, (uint2*)hid_h, SEQ * HID / 4);
    split_f16_v4<<<(QKV_COLS * HID / 4 + 255) / 256, 256>>>(
        (const float4*)w_qkv, (uint2*)wq_h, (uint2*)wq_l, QKV_COLS * HID / 4);
    tof16_v4<<<(HID * HID / 4 + 255) / 256, 256>>>(
        (const float4*)w_o, (uint2*)wo_h, HID * HID / 4);

    // 1a) QKV projection, q columns [0, 2048): 1-term BN=128 kernel
    gemm_1t<<<dim3(2048 / 128, SEQ / 128), 256, T1_SMEM>>>(
        hid_h, wq_h, qkv_ptr, SEQ, QKV_COLS, HID);

    // 1b) QKV projection, k/v strip [2048, 2560): k cols 2-term, v cols 1-term
    gemm_f16x2<<<dim3(512 / BN, SEQ / BM), 256, GEMM_SMEM>>>(
        hid_h, wq_h + (size_t)2048 * HID, wq_l + (size_t)2048 * HID,
        qkv_ptr + 2048, SEQ, QKV_COLS, HID,
        0, NKVH * DHEAD);

    // 2) RoPE + fp16 split into head-major q/k/v
    {
        int total = SEQ * 40 * 32;
        rope_split<<<(total + 255) / 256, 256>>>();
    }

    // 3) tensor-core causal GQA flash attention
    flash_attn_tc<<<dim3(NQH, SEQ / 64), 128, FA_SMEM>>>();

    // 4) output projection: 1-term BN=128 kernel
    gemm_1t<<<dim3(HID / 128, SEQ / 128), 256, T1_SMEM>>>(
        at_h, wo_h, out, SEQ, HID, HID);
}

// round 12
// speedup vs baseline: 2.1982x; 1.0063x over previous
#include <cuda_runtime.h>
#include <cuda_fp16.h>
#include <math.h>
#include <float.h>
#include <stdint.h>

#define SEQ    2048
#define HID    2048
#define DHEAD  64
#define NQH    32
#define NKVH   4
#define QKV_COLS 2560   // (32 + 4 + 4) * 64

// ---------------- scratch (no cudaMalloc allowed) ----------------
__device__ float g_qkv [SEQ * QKV_COLS];

__device__ __half g_hid_h[SEQ * HID];
__device__ __half g_wq_h [QKV_COLS * HID];
__device__ __half g_wq_l [QKV_COLS * HID];
__device__ __half g_wo_h [HID * HID];
__device__ __half g_at_h [SEQ * HID];

__device__ __half g_q_h[NQH  * SEQ * DHEAD];
__device__ __half g_k_h[NKVH * SEQ * DHEAD];
__device__ __half g_k_l[NKVH * SEQ * DHEAD];
__device__ __half g_v_h[NKVH * SEQ * DHEAD];

// ---------------------------------------------------------------------------
// helpers
// ---------------------------------------------------------------------------
__device__ __forceinline__ void cp16(uint32_t s, const void* g) {
    asm volatile("cp.async.cg.shared.global [%0], [%1], 16;\n" :: "r"(s), "l"(g));
}
__device__ __forceinline__ void cp_commit() {
    asm volatile("cp.async.commit_group;\n");
}
template<int N>
__device__ __forceinline__ void cp_wait() {
    asm volatile("cp.async.wait_group %0;\n" :: "n"(N));
}
__device__ __forceinline__ void mma_f16(float* d, const uint32_t* a,
                                        const uint32_t* b) {
    asm volatile(
        "mma.sync.aligned.m16n8k16.row.col.f32.f16.f16.f32 "
        "{%0,%1,%2,%3}, {%4,%5,%6,%7}, {%8,%9}, {%0,%1,%2,%3};\n"
        : "+f"(d[0]), "+f"(d[1]), "+f"(d[2]), "+f"(d[3])
        : "r"(a[0]), "r"(a[1]), "r"(a[2]), "r"(a[3]), "r"(b[0]), "r"(b[1]));
}
__device__ __forceinline__ void mma_f16b(float* d, const uint32_t* a,
                                         uint32_t b0, uint32_t b1) {
    asm volatile(
        "mma.sync.aligned.m16n8k16.row.col.f32.f16.f16.f32 "
        "{%0,%1,%2,%3}, {%4,%5,%6,%7}, {%8,%9}, {%0,%1,%2,%3};\n"
        : "+f"(d[0]), "+f"(d[1]), "+f"(d[2]), "+f"(d[3])
        : "r"(a[0]), "r"(a[1]), "r"(a[2]), "r"(a[3]), "r"(b0), "r"(b1));
}
__device__ __forceinline__ void ldsm_x4(uint32_t* r, uint32_t addr) {
    asm volatile("ldmatrix.sync.aligned.m8n8.x4.shared.b16 {%0,%1,%2,%3}, [%4];\n"
        : "=r"(r[0]), "=r"(r[1]), "=r"(r[2]), "=r"(r[3]) : "r"(addr));
}
__device__ __forceinline__ void ldsm_x4_t(uint32_t* r, uint32_t addr) {
    asm volatile("ldmatrix.sync.aligned.m8n8.x4.trans.shared.b16 {%0,%1,%2,%3}, [%4];\n"
        : "=r"(r[0]), "=r"(r[1]), "=r"(r[2]), "=r"(r[3]) : "r"(addr));
}
__device__ __forceinline__ uint32_t smem_u32_of(const void* p) {
    uint32_t a;
    asm("{ .reg .u64 t; cvta.to.shared.u64 t, %1; cvt.u32.u64 %0, t; }"
        : "=r"(a) : "l"(p));
    return a;
}

// ---------------------------------------------------------------------------
// fp32 -> fp16 hi (+ optional lo residual) splits, float4 vectorized
// ---------------------------------------------------------------------------
__global__ void split_f16_v4(const float4* __restrict__ in,
                             uint2* __restrict__ hi,
                             uint2* __restrict__ lo, int n4) {
    int i = blockIdx.x * blockDim.x + threadIdx.x;
    if (i >= n4) return;
    float4 x = in[i];
    __half h0 = __float2half_rn(x.x);
    __half h1 = __float2half_rn(x.y);
    __half h2 = __float2half_rn(x.z);
    __half h3 = __float2half_rn(x.w);
    __half2 hp0 = __halves2half2(h0, h1);
    __half2 hp1 = __halves2half2(h2, h3);
    __half2 lp0 = __halves2half2(__float2half_rn(x.x - __half2float(h0)),
                                 __float2half_rn(x.y - __half2float(h1)));
    __half2 lp1 = __halves2half2(__float2half_rn(x.z - __half2float(h2)),
                                 __float2half_rn(x.w - __half2float(h3)));
    hi[i] = make_uint2(*(uint32_t*)&hp0, *(uint32_t*)&hp1);
    lo[i] = make_uint2(*(uint32_t*)&lp0, *(uint32_t*)&lp1);
}
__global__ void tof16_v4(const float4* __restrict__ in,
                         uint2* __restrict__ hi, int n4) {
    int i = blockIdx.x * blockDim.x + threadIdx.x;
    if (i >= n4) return;
    float4 x = in[i];
    __half2 hp0 = __halves2half2(__float2half_rn(x.x), __float2half_rn(x.y));
    __half2 hp1 = __halves2half2(__float2half_rn(x.z), __float2half_rn(x.w));
    hi[i] = make_uint2(*(uint32_t*)&hp0, *(uint32_t*)&hp1);
}

// ---------------------------------------------------------------------------
// 1-term fp16 GEMM: BM=128 BN=128 BK=32 (unchanged from R11)
// ---------------------------------------------------------------------------
#define SROW 40
#define T1_A_ELE (128 * SROW)
#define T1_B_ELE (128 * SROW)
#define T1_STAGE (T1_A_ELE + T1_B_ELE)
#define T1_SMEM (3 * T1_STAGE * 2)

__global__ void __launch_bounds__(256, 2)
gemm_1t(const __half* __restrict__ Ah,
        const __half* __restrict__ Bh,
        float* __restrict__ C, int M, int N, int K) {
    extern __shared__ __half smem[];
    const int tid  = threadIdx.x;
    const int warp = tid >> 5;
    const int lane = tid & 31;
    const int wm   = warp >> 1;
    const int wn   = warp & 1;
    const int g    = lane >> 2;
    const int t    = lane & 3;
    const int row0 = blockIdx.y * 128;
    const int col0 = blockIdx.x * 128;

    uint32_t smem_b = smem_u32_of(smem);

    float acc[2][8][4];
#pragma unroll
    for (int i = 0; i < 2; i++)
#pragma unroll
        for (int j = 0; j < 8; j++)
#pragma unroll
            for (int k = 0; k < 4; k++) acc[i][j][k] = 0.f;

    const int NIT = K / 32;

    auto load_stage = [&](int stage, int k0) {
        uint32_t sb = smem_b + stage * (T1_STAGE * 2);
#pragma unroll
        for (int p = 0; p < 2; p++) {
            int c   = tid + p * 256;
            int row = c >> 2;
            int cc  = c & 3;
            uint32_t so = sb + row * (SROW * 2) + cc * 16;
            cp16(so, Ah + (size_t)(row0 + row) * K + k0 + cc * 8);
            cp16(so + T1_A_ELE * 2, Bh + (size_t)(col0 + row) * K + k0 + cc * 8);
        }
        cp_commit();
    };

    load_stage(0, 0);
    load_stage(1, 32);

    for (int it = 0; it < NIT; it++) {
        if (it + 2 < NIT) { cp_wait<1>(); } else { cp_wait<0>(); }
        __syncthreads();
        if (it + 2 < NIT) load_stage((it + 2) % 3, (it + 2) * 32);

        const __half* As = smem + (it % 3) * T1_STAGE;
        const __half* Bs = As + T1_A_ELE;

#pragma unroll
        for (int ks = 0; ks < 2; ks++) {
            uint32_t ah[2][4], bh[8][2];
#pragma unroll
            for (int mt = 0; mt < 2; mt++) {
                int rb = wm * 32 + mt * 16;
                const __half* pa = As + (rb + g) * SROW + ks * 16 + 2 * t;
                ah[mt][0] = *(const uint32_t*)(pa);
                ah[mt][1] = *(const uint32_t*)(pa + 8 * SROW);
                ah[mt][2] = *(const uint32_t*)(pa + 8);
                ah[mt][3] = *(const uint32_t*)(pa + 8 * SROW + 8);
            }
#pragma unroll
            for (int nt = 0; nt < 8; nt++) {
                int cb = wn * 64 + nt * 8;
                const __half* pb = Bs + (cb + g) * SROW + ks * 16 + 2 * t;
                bh[nt][0] = *(const uint32_t*)(pb);
                bh[nt][1] = *(const uint32_t*)(pb + 8);
            }
#pragma unroll
            for (int mt = 0; mt < 2; mt++)
#pragma unroll
                for (int nt = 0; nt < 8; nt++)
                    mma_f16b(acc[mt][nt], ah[mt], bh[nt][0], bh[nt][1]);
        }
    }

#pragma unroll
    for (int mt = 0; mt < 2; mt++) {
        int r = row0 + wm * 32 + mt * 16 + g;
#pragma unroll
        for (int nt = 0; nt < 8; nt++) {
            int c = col0 + wn * 64 + nt * 8 + 2 * t;
            float2 v0 = make_float2(acc[mt][nt][0], acc[mt][nt][1]);
            float2 v1 = make_float2(acc[mt][nt][2], acc[mt][nt][3]);
            *(float2*)&C[(size_t)r * N + c]       = v0;
            *(float2*)&C[(size_t)(r + 8) * N + c] = v1;
        }
    }
}

// ---------------------------------------------------------------------------
// Mixed-term fp16 GEMM (BN=64), k/v strip (unchanged from R11)
// ---------------------------------------------------------------------------
#define BM 128
#define BN 64
#define A_ELE (128 * SROW)
#define B_ELE (64 * SROW)
#define STAGE_E (A_ELE + 2 * B_ELE)
#define GEMM_SMEM (3 * STAGE_E * 2)

__global__ void __launch_bounds__(256, 3)
gemm_f16x2(const __half* __restrict__ Ah,
           const __half* __restrict__ Bh,
           const __half* __restrict__ Bl,
           float* __restrict__ C, int M, int N, int K,
           int n2start, int n2end) {
    extern __shared__ __half smem[];
    const int tid  = threadIdx.x;
    const int warp = tid >> 5;
    const int lane = tid & 31;
    const int wm   = warp >> 1;
    const int wn   = warp & 1;
    const int g    = lane >> 2;
    const int t    = lane & 3;
    const int row0 = blockIdx.y * BM;
    const int col0 = blockIdx.x * BN;
    const bool use2 = (col0 >= n2start) && (col0 < n2end);

    uint32_t smem_b = smem_u32_of(smem);

    float acc[2][4][4];
#pragma unroll
    for (int i = 0; i < 2; i++)
#pragma unroll
        for (int j = 0; j < 4; j++)
#pragma unroll
            for (int k = 0; k < 4; k++) acc[i][j][k] = 0.f;

    const int NIT = K / 32;

    auto load_stage = [&](int stage, int k0) {
        uint32_t sb = smem_b + stage * (STAGE_E * 2);
#pragma unroll
        for (int p = 0; p < 2; p++) {
            int c   = tid + p * 256;
            int row = c >> 2;
            int cc  = c & 3;
            uint32_t so = sb + row * (SROW * 2) + cc * 16;
            cp16(so, Ah + (size_t)(row0 + row) * K + k0 + cc * 8);
        }
        {
            int row = tid >> 2;
            int cc  = tid & 3;
            uint32_t so = sb + A_ELE * 2 + row * (SROW * 2) + cc * 16;
            size_t gb = (size_t)(col0 + row) * K + k0 + cc * 8;
            cp16(so, Bh + gb);
            if (use2) cp16(so + B_ELE * 2, Bl + gb);
        }
        cp_commit();
    };

    load_stage(0, 0);
    load_stage(1, 32);

    for (int it = 0; it < NIT; it++) {
        if (it + 2 < NIT) { cp_wait<1>(); } else { cp_wait<0>(); }
        __syncthreads();
        if (it + 2 < NIT) load_stage((it + 2) % 3, (it + 2) * 32);

        const __half* As = smem + (it % 3) * STAGE_E;
        const __half* Bs = As + A_ELE;
        const __half* Bq = Bs + B_ELE;

#pragma unroll
        for (int ks = 0; ks < 2; ks++) {
            uint32_t ah[2][4], bh[4][2], bl[4][2];
#pragma unroll
            for (int mt = 0; mt < 2; mt++) {
                int rb = wm * 32 + mt * 16;
                const __half* pa = As + (rb + g) * SROW + ks * 16 + 2 * t;
                ah[mt][0] = *(const uint32_t*)(pa);
                ah[mt][1] = *(const uint32_t*)(pa + 8 * SROW);
                ah[mt][2] = *(const uint32_t*)(pa + 8);
                ah[mt][3] = *(const uint32_t*)(pa + 8 * SROW + 8);
            }
#pragma unroll
            for (int nt = 0; nt < 4; nt++) {
                int cb = wn * 32 + nt * 8;
                const __half* pb = Bs + (cb + g) * SROW + ks * 16 + 2 * t;
                bh[nt][0] = *(const uint32_t*)(pb);
                bh[nt][1] = *(const uint32_t*)(pb + 8);
            }
            if (use2) {
#pragma unroll
                for (int nt = 0; nt < 4; nt++) {
                    int cb = wn * 32 + nt * 8;
                    const __half* pq = Bq + (cb + g) * SROW + ks * 16 + 2 * t;
                    bl[nt][0] = *(const uint32_t*)(pq);
                    bl[nt][1] = *(const uint32_t*)(pq + 8);
                }
            }
#pragma unroll
            for (int mt = 0; mt < 2; mt++)
#pragma unroll
                for (int nt = 0; nt < 4; nt++)
                    mma_f16b(acc[mt][nt], ah[mt], bh[nt][0], bh[nt][1]);
            if (use2) {
#pragma unroll
                for (int mt = 0; mt < 2; mt++)
#pragma unroll
                    for (int nt = 0; nt < 4; nt++)
                        mma_f16b(acc[mt][nt], ah[mt], bl[nt][0], bl[nt][1]);
            }
        }
    }

#pragma unroll
    for (int mt = 0; mt < 2; mt++) {
        int r = row0 + wm * 32 + mt * 16 + g;
#pragma unroll
        for (int nt = 0; nt < 4; nt++) {
            int c = col0 + wn * 32 + nt * 8 + 2 * t;
            float2 v0 = make_float2(acc[mt][nt][0], acc[mt][nt][1]);
            float2 v1 = make_float2(acc[mt][nt][2], acc[mt][nt][3]);
            *(float2*)&C[(size_t)r * N + c]       = v0;
            *(float2*)&C[(size_t)(r + 8) * N + c] = v1;
        }
    }
}

// ---------------------------------------------------------------------------
// RoPE + fp16 split: g_qkv -> head-major q (hi) / k (hi+lo) / v (hi)
// ---------------------------------------------------------------------------
__global__ void rope_split() {
    int idx = blockIdx.x * blockDim.x + threadIdx.x;
    const int total = SEQ * 40 * 32;
    if (idx >= total) return;
    int pair = idx & 31;
    int head = (idx >> 5) % 40;
    int s    = idx / (40 * 32);

    const float* base = g_qkv + (size_t)s * QKV_COLS + head * DHEAD;
    float x1 = base[pair];
    float x2 = base[pair + 32];
    float y1, y2;
    if (head < 36) {
        float inv_freq = __expf(-(float)pair * (9.210340371976184f / 32.0f));
        float ang = (float)s * inv_freq;
        float sn, cs;
        sincosf(ang, &sn, &cs);
        y1 = x1 * cs - x2 * sn;
        y2 = x2 * cs + x1 * sn;
    } else {
        y1 = x1; y2 = x2;
    }

    if (head < 32) {
        y1 *= 0.125f; y2 *= 0.125f;
        size_t off = ((size_t)head * SEQ + s) * DHEAD;
        g_q_h[off + pair]      = __float2half_rn(y1);
        g_q_h[off + pair + 32] = __float2half_rn(y2);
    } else if (head < 36) {
        size_t off = ((size_t)(head - 32) * SEQ + s) * DHEAD;
        __half h1 = __float2half_rn(y1);
        __half h2 = __float2half_rn(y2);
        g_k_h[off + pair]      = h1;
        g_k_h[off + pair + 32] = h2;
        g_k_l[off + pair]      = __float2half_rn(y1 - __half2float(h1));
        g_k_l[off + pair + 32] = __float2half_rn(y2 - __half2float(h2));
    } else {
        size_t off = ((size_t)(head - 36) * SEQ + s) * DHEAD;
        g_v_h[off + pair]      = __float2half_rn(y1);
        g_v_h[off + pair + 32] = __float2half_rn(y2);
    }
}

// ---------------------------------------------------------------------------
// Flash attention v2: 128-row Q tiles, 8 warps (256 thr), double-buffered KV.
// QK^T uses K 2-term (hi+lo); PV uses V 1-term (hi). kk-outer ordering.
// smem: Q (128x144B) | stage0 {Kh,Kl,Vh} | stage1 {Kh,Kl,Vh}
// ---------------------------------------------------------------------------
#define F2_QBYTES (128 * 144)        // 18432
#define F2_KVT    (64 * 144)         // 9216 per array
#define F2_STAGE  (3 * F2_KVT)       // 27648
#define FA2_SMEM  (F2_QBYTES + 2 * F2_STAGE)   // 73728

__global__ void __launch_bounds__(256)
flash_attn_tc2() {
    extern __shared__ __half fsm[];
    const uint32_t sQ = smem_u32_of(fsm);

    const int head = blockIdx.x;
    const int qb   = gridDim.y - 1 - blockIdx.y;   // heavy blocks first
    const int tid  = threadIdx.x;
    const int w    = tid >> 5;
    const int lane = tid & 31;
    const int kvh  = head >> 3;
    const int r8   = lane & 7;
    const int sub  = lane >> 3;
    const int KB   = 2 * qb + 2;

    auto load_kv = [&](int stage, int kb) {
        const size_t go = ((size_t)kvh * SEQ + kb * 64) * DHEAD;
        uint32_t sb = sQ + F2_QBYTES + stage * F2_STAGE;
#pragma unroll
        for (int i = 0; i < 6; i++) {
            int c   = tid + i * 256;     // 1536 chunks: Kh, Kl, Vh
            int arr = c >> 9;
            int rem = c & 511;
            int row = rem >> 3;
            int ch  = rem & 7;
            uint32_t dst = sb + arr * F2_KVT + row * 144 + ch * 16;
            const __half* src;
            if      (arr == 0) src = g_k_h + go;
            else if (arr == 1) src = g_k_l + go;
            else               src = g_v_h + go;
            cp16(dst, src + row * DHEAD + ch * 8);
        }
        cp_commit();
    };

    // ---- prologue: Q + first two KV stages ----
    {
        const __half* gq = g_q_h + ((size_t)head * SEQ + qb * 128) * DHEAD;
#pragma unroll
        for (int i = 0; i < 4; i++) {
            int c   = tid + i * 256;     // 1024 chunks
            int row = c >> 3;
            int ch  = c & 7;
            cp16(sQ + row * 144 + ch * 16, gq + row * DHEAD + ch * 8);
        }
        cp_commit();
    }
    load_kv(0, 0);
    load_kv(1, 1);
    cp_wait<2>();     // Q group complete
    __syncthreads();

    uint32_t qh[4][4];
#pragma unroll
    for (int kk = 0; kk < 4; kk++) {
        uint32_t addr = sQ
            + (w * 16 + r8 + ((sub & 1) << 3)) * 144
            + kk * 32 + ((sub & 2) << 3);
        ldsm_x4(qh[kk], addr);
    }

    float of[8][4];
#pragma unroll
    for (int f = 0; f < 8; f++)
#pragma unroll
        for (int j = 0; j < 4; j++) of[f][j] = 0.f;
    float m0 = -1e30f, m1 = -1e30f, l0 = 0.f, l1 = 0.f;

    for (int kb = 0; kb < KB; kb++) {
        if (kb + 1 < KB) { cp_wait<1>(); } else { cp_wait<0>(); }
        __syncthreads();

        const uint32_t sK = sQ + F2_QBYTES + (kb & 1) * F2_STAGE;
        const uint32_t sKl = sK + F2_KVT;
        const uint32_t sV = sK + 2 * F2_KVT;

        // ---- S = Q K^T (K 2-term), kk-outer ----
        float sf[8][4];
#pragma unroll
        for (int f = 0; f < 8; f++)
#pragma unroll
            for (int j = 0; j < 4; j++) sf[f][j] = 0.f;

#pragma unroll
        for (int kk = 0; kk < 4; kk++) {
            uint32_t bh[4][4], bl[4][4];
#pragma unroll
            for (int p = 0; p < 4; p++) {
                uint32_t off = (p * 16 + ((sub & 2) << 2) + r8) * 144
                             + kk * 32 + ((sub & 1) << 4);
                ldsm_x4(bh[p], sK + off);
                ldsm_x4(bl[p], sKl + off);
            }
#pragma unroll
            for (int p = 0; p < 4; p++) {
                mma_f16(sf[2 * p],     qh[kk], &bh[p][0]);
                mma_f16(sf[2 * p + 1], qh[kk], &bh[p][2]);
            }
#pragma unroll
            for (int p = 0; p < 4; p++) {
                mma_f16(sf[2 * p],     qh[kk], &bl[p][0]);
                mma_f16(sf[2 * p + 1], qh[kk], &bl[p][2]);
            }
        }

        // ---- causal mask (global indices) ----
        if (kb >= 2 * qb) {
            int rt0 = qb * 128 + w * 16 + (lane >> 2);
#pragma unroll
            for (int f = 0; f < 8; f++) {
                int ct = kb * 64 + 8 * f + 2 * (lane & 3);
                if (ct > rt0)         sf[f][0] = -1e30f;
                if (ct + 1 > rt0)     sf[f][1] = -1e30f;
                if (ct > rt0 + 8)     sf[f][2] = -1e30f;
                if (ct + 1 > rt0 + 8) sf[f][3] = -1e30f;
            }
        }

        // ---- online softmax (warp-local rows) ----
        float c0 = -1e30f, c1 = -1e30f;
#pragma unroll
        for (int f = 0; f < 8; f++) {
            c0 = fmaxf(c0, fmaxf(sf[f][0], sf[f][1]));
            c1 = fmaxf(c1, fmaxf(sf[f][2], sf[f][3]));
        }
        c0 = fmaxf(c0, __shfl_xor_sync(0xffffffffu, c0, 1));
        c0 = fmaxf(c0, __shfl_xor_sync(0xffffffffu, c0, 2));
        c1 = fmaxf(c1, __shfl_xor_sync(0xffffffffu, c1, 1));
        c1 = fmaxf(c1, __shfl_xor_sync(0xffffffffu, c1, 2));

        float mn0 = fmaxf(m0, c0), mn1 = fmaxf(m1, c1);
        float a0 = __expf(m0 - mn0), a1 = __expf(m1 - mn1);
        m0 = mn0; m1 = mn1;

        float s0 = 0.f, s1 = 0.f;
#pragma unroll
        for (int f = 0; f < 8; f++) {
            sf[f][0] = __expf(sf[f][0] - mn0);
            sf[f][1] = __expf(sf[f][1] - mn0);
            sf[f][2] = __expf(sf[f][2] - mn1);
            sf[f][3] = __expf(sf[f][3] - mn1);
            s0 += sf[f][0] + sf[f][1];
            s1 += sf[f][2] + sf[f][3];
        }
        s0 += __shfl_xor_sync(0xffffffffu, s0, 1);
        s0 += __shfl_xor_sync(0xffffffffu, s0, 2);
        s1 += __shfl_xor_sync(0xffffffffu, s1, 1);
        s1 += __shfl_xor_sync(0xffffffffu, s1, 2);
        l0 = l0 * a0 + s0;
        l1 = l1 * a1 + s1;

#pragma unroll
        for (int f = 0; f < 8; f++) {
            of[f][0] *= a0; of[f][1] *= a0;
            of[f][2] *= a1; of[f][3] *= a1;
        }

        // ---- P -> fp16 A fragments ----
        uint32_t ph[4][4];
#pragma unroll
        for (int kk = 0; kk < 4; kk++) {
#pragma unroll
            for (int half4 = 0; half4 < 4; half4++) {
                int f = 2 * kk + (half4 >> 1);
                int j = (half4 & 1) * 2;
                __half2 hp = __halves2half2(__float2half_rn(sf[f][j]),
                                            __float2half_rn(sf[f][j + 1]));
                int slot = (half4 >> 1) * 2 + (half4 & 1);
                ph[kk][slot] = *(uint32_t*)&hp;
            }
        }

        // ---- O += P V_h (1-term), kk-outer ----
#pragma unroll
        for (int kk = 0; kk < 4; kk++) {
            uint32_t vh[4][4];
#pragma unroll
            for (int p = 0; p < 4; p++) {
                uint32_t addr = sV
                    + (kk * 16 + ((sub & 1) << 3) + r8) * 144
                    + p * 32 + ((sub & 2) << 3);
                ldsm_x4_t(vh[p], addr);
            }
#pragma unroll
            for (int p = 0; p < 4; p++) {
                mma_f16(of[2 * p],     ph[kk], &vh[p][0]);
                mma_f16(of[2 * p + 1], ph[kk], &vh[p][2]);
            }
        }

        // ---- prefetch kb+2 into the buffer just consumed ----
        if (kb + 2 < KB) {
            __syncthreads();              // all warps done reading this buffer
            load_kv(kb & 1, kb + 2);
        }
    }

    // ---- normalize + write fp16 hi ----
    float inv0 = 1.0f / l0, inv1 = 1.0f / l1;
    int rq = qb * 128 + w * 16 + (lane >> 2);
    int cb = head * DHEAD + 2 * (lane & 3);
#pragma unroll
    for (int f = 0; f < 8; f++) {
        int col = cb + 8 * f;
        __half2 hp0 = __halves2half2(__float2half_rn(of[f][0] * inv0),
                                     __float2half_rn(of[f][1] * inv0));
        __half2 hp1 = __halves2half2(__float2half_rn(of[f][2] * inv1),
                                     __float2half_rn(of[f][3] * inv1));
        *(uint32_t*)&g_at_h[(size_t)rq * HID + col]       = *(uint32_t*)&hp0;
        *(uint32_t*)&g_at_h[(size_t)(rq + 8) * HID + col] = *(uint32_t*)&hp1;
    }
}

// ---------------------------------------------------------------------------
extern "C" void kernel_launch(void* const* d_in, const int* in_sizes, int n_in,
                              void* d_out, int out_size) {
    const float* hidden = (const float*)d_in[0];
    const float* w_qkv  = (const float*)d_in[1];
    const float* w_o    = (const float*)d_in[2];
    float*       out    = (float*)d_out;

    float* qkv_ptr = nullptr;
    cudaGetSymbolAddress((void**)&qkv_ptr, g_qkv);
    __half *hid_h, *wq_h, *wq_l, *wo_h, *at_h;
    cudaGetSymbolAddress((void**)&hid_h, g_hid_h);
    cudaGetSymbolAddress((void**)&wq_h,  g_wq_h);
    cudaGetSymbolAddress((void**)&wq_l,  g_wq_l);
    cudaGetSymbolAddress((void**)&wo_h,  g_wo_h);
    cudaGetSymbolAddress((void**)&at_h,  g_at_h);

    cudaFuncSetAttribute(gemm_1t,
                         cudaFuncAttributeMaxDynamicSharedMemorySize, T1_SMEM);
    cudaFuncSetAttribute(gemm_f16x2,
                         cudaFuncAttributeMaxDynamicSharedMemorySize, GEMM_SMEM);
    cudaFuncSetAttribute(flash_attn_tc2,
                         cudaFuncAttributeMaxDynamicSharedMemorySize, FA2_SMEM);

    tof16_v4<<<(SEQ * HID / 4 + 255) / 256, 256>>>(
        (const float4*)hidden, (uint2*)hid_h, SEQ * HID / 4);
    split_f16_v4<<<(QKV_COLS * HID / 4 + 255) / 256, 256>>>(
        (const float4*)w_qkv, (uint2*)wq_h, (uint2*)wq_l, QKV_COLS * HID / 4);
    tof16_v4<<<(HID * HID / 4 + 255) / 256, 256>>>(
        (const float4*)w_o, (uint2*)wo_h, HID * HID / 4);

    // 1a) QKV projection, q columns [0, 2048): 1-term BN=128 kernel
    gemm_1t<<<dim3(2048 / 128, SEQ / 128), 256, T1_SMEM>>>(
        hid_h, wq_h, qkv_ptr, SEQ, QKV_COLS, HID);

    // 1b) QKV projection, k/v strip [2048, 2560)
    gemm_f16x2<<<dim3(512 / BN, SEQ / BM), 256, GEMM_SMEM>>>(
        hid_h, wq_h + (size_t)2048 * HID, wq_l + (size_t)2048 * HID,
        qkv_ptr + 2048, SEQ, QKV_COLS, HID,
        0, NKVH * DHEAD);

    // 2) RoPE + fp16 split into head-major q/k/v
    {
        int total = SEQ * 40 * 32;
        rope_split<<<(total + 255) / 256, 256>>>();
    }

    // 3) flash attention v2: 128-row Q tiles, double-buffered KV
    flash_attn_tc2<<<dim3(NQH, SEQ / 128), 256, FA2_SMEM>>>();

    // 4) output projection: 1-term BN=128 kernel
    gemm_1t<<<dim3(HID / 128, SEQ / 128), 256, T1_SMEM>>>(
        at_h, wo_h, out, SEQ, HID, HID);
}